// round 3
// baseline (speedup 1.0000x reference)
#include <cuda_runtime.h>
#include <math.h>

#define B 2
#define NQ 4096
#define NA 2048
#define DIM 512
#define HID 512
#define NBLK 5
#define KNN 8

#define BQ    (B*NQ)        // 8192
#define ROWS8 (BQ*KNN)      // 65536
#define ROWS9 (BQ*9)        // 73728

// ---------------- static scratch (no allocations allowed) ----------------
__device__ float g_KS[B*NA*DIM];        // anchors_feats @ w_ks
__device__ float g_VS[B*NA*DIM];        // anchors_feats @ w_vs
__device__ int   g_idx[BQ*KNN];         // knn indices
__device__ float g_bufA[(size_t)ROWS9*DIM];   // H1 -> T_pre
__device__ float g_bufB[(size_t)ROWS9*DIM];   // PE (pos), rows8 used
__device__ float g_bufC[(size_t)ROWS9*DIM];   // X  -> G
__device__ float g_lat[BQ*DIM];
__device__ float g_tmp[BQ*HID];
__device__ float g_h[BQ*HID];
__device__ float g_qattn[B*DIM];
__device__ float g_kgv[B*DIM];
__device__ float g_vgv[B*DIM];

// ---------------- tiny projection of global feats ----------------
__global__ void k_global_proj(const float* __restrict__ gf,
                              const float* __restrict__ wqs,
                              const float* __restrict__ wkg,
                              const float* __restrict__ wvg) {
    int t = blockIdx.x * blockDim.x + threadIdx.x;
    if (t >= 3 * B * DIM) return;
    int which = t / (B * DIM);
    int r = t % (B * DIM);
    int b = r / DIM, n = r % DIM;
    const float* W = (which == 0) ? wqs : (which == 1) ? wkg : wvg;
    float acc = 0.f;
    for (int k = 0; k < DIM; k++)
        acc = fmaf(gf[b * DIM + k], W[(size_t)k * DIM + n], acc);
    float* out = (which == 0) ? g_qattn : (which == 1) ? g_kgv : g_vgv;
    out[b * DIM + n] = acc;
}

// ---------------- brute-force KNN (top-8 smallest d2) ----------------
__global__ void k_knn(const float* __restrict__ xyz_q,
                      const float* __restrict__ axyz) {
    __shared__ float sx[512], sy[512], sz[512], s2[512];
    int b = blockIdx.y;
    int q = blockIdx.x * 128 + threadIdx.x;
    int bq = b * NQ + q;
    float qx = xyz_q[bq * 3 + 0];
    float qy = xyz_q[bq * 3 + 1];
    float qz = xyz_q[bq * 3 + 2];
    float q2 = qx * qx + qy * qy + qz * qz;
    float bd[KNN]; int bi[KNN];
#pragma unroll
    for (int i = 0; i < KNN; i++) { bd[i] = INFINITY; bi[i] = 0; }
    for (int t0 = 0; t0 < NA; t0 += 512) {
        __syncthreads();
        for (int j = threadIdx.x; j < 512; j += 128) {
            float ax = axyz[(b * NA + t0 + j) * 3 + 0];
            float ay = axyz[(b * NA + t0 + j) * 3 + 1];
            float az = axyz[(b * NA + t0 + j) * 3 + 2];
            sx[j] = ax; sy[j] = ay; sz[j] = az;
            s2[j] = ax * ax + ay * ay + az * az;
        }
        __syncthreads();
        for (int j = 0; j < 512; j++) {
            float d2 = q2 + s2[j] - 2.f * (qx * sx[j] + qy * sy[j] + qz * sz[j]);
            if (d2 < bd[KNN - 1]) {
                bd[KNN - 1] = d2; bi[KNN - 1] = t0 + j;
#pragma unroll
                for (int s = KNN - 1; s > 0; --s) {
                    if (bd[s] < bd[s - 1]) {
                        float td = bd[s]; bd[s] = bd[s - 1]; bd[s - 1] = td;
                        int ti = bi[s]; bi[s] = bi[s - 1]; bi[s - 1] = ti;
                    }
                }
            }
        }
    }
#pragma unroll
    for (int i = 0; i < KNN; i++) g_idx[bq * KNN + i] = bi[i];
}

// ---------------- H1 = relu(d @ d1_w + d1_b)  (K=3 layer, fused) ----------------
__global__ void k_h1(const float* __restrict__ xyz_q,
                     const float* __restrict__ axyz,
                     const float* __restrict__ d1w,
                     const float* __restrict__ d1b) {
    size_t o = (size_t)blockIdx.x * blockDim.x + threadIdx.x;
    if (o >= (size_t)ROWS8 * DIM) return;
    int f = (int)(o & 511);
    size_t r = o >> 9;
    int kk = (int)(r & 7);
    int bq = (int)(r >> 3);
    int b = bq >> 12;   // NQ = 4096
    int aidx = g_idx[bq * KNN + kk];
    const float* qp = xyz_q + (size_t)bq * 3;
    const float* ap = axyz + ((size_t)b * NA + aidx) * 3;
    float dx = qp[0] - ap[0], dy = qp[1] - ap[1], dz = qp[2] - ap[2];
    float h = fmaf(dx, d1w[f], fmaf(dy, d1w[512 + f], fmaf(dz, d1w[1024 + f], d1b[f])));
    g_bufA[o] = fmaxf(h, 0.f);
}

// ---------------- build attention input X = q - k + pos ----------------
__global__ void k_buildx() {
    size_t o = (size_t)blockIdx.x * blockDim.x + threadIdx.x;
    if (o >= (size_t)ROWS9 * DIM) return;
    int f = (int)(o & 511);
    size_t r = o >> 9;
    int n = (int)(r % 9);
    int bq = (int)(r / 9);
    int b = bq >> 12;
    float v = g_qattn[b * DIM + f];
    if (n < KNN) {
        int aidx = g_idx[bq * KNN + n];
        v = v - g_KS[((size_t)b * NA + aidx) * DIM + f]
              + g_bufB[((size_t)bq * KNN + n) * DIM + f];
    } else {
        v = v - g_kgv[b * DIM + f];
    }
    g_bufC[o] = v;
}

// ---------------- per-feature softmax over 9 tokens + weighted sum ----------------
__global__ void k_attn_lat() {
    int bq = blockIdx.x;
    int f = threadIdx.x;      // 512
    int b = bq >> 12;
    __shared__ int sidx[KNN];
    if (threadIdx.x < KNN) sidx[threadIdx.x] = g_idx[bq * KNN + threadIdx.x];
    __syncthreads();
    float v[9];
#pragma unroll
    for (int n = 0; n < 9; n++)
        v[n] = g_bufC[((size_t)bq * 9 + n) * DIM + f];
    float m = v[0];
#pragma unroll
    for (int n = 1; n < 9; n++) m = fmaxf(m, v[n]);
    float s = 0.f;
#pragma unroll
    for (int n = 0; n < 9; n++) { v[n] = expf(v[n] - m); s += v[n]; }
    float inv = 1.f / s;
    float acc = 0.f;
#pragma unroll
    for (int n = 0; n < KNN; n++) {
        float val = g_VS[((size_t)b * NA + sidx[n]) * DIM + f]
                  + g_bufB[((size_t)bq * KNN + n) * DIM + f];
        acc = fmaf(v[n], val, acc);
    }
    acc = fmaf(v[8], g_vgv[b * DIM + f], acc);
    g_lat[(size_t)bq * DIM + f] = acc * inv;
}

// ---------------- NeRF positional encoding + fc_p ----------------
__global__ void k_pe_fcp(const float* __restrict__ xyz_q,
                         const float* __restrict__ fcpw,
                         const float* __restrict__ fcpb,
                         float* __restrict__ out) {
    __shared__ float pe[60];
    int bq = blockIdx.x;
    if (threadIdx.x < 60) {
        int i = threadIdx.x;
        int fr = i / 6, rem = i % 6, sc = rem / 3, c = rem % 3;
        float p = xyz_q[(size_t)bq * 3 + c];
        float a = p * ((float)(1 << fr) * 3.14159265358979f);
        pe[i] = (sc == 0) ? sinf(a) : cosf(a);
    }
    __syncthreads();
#pragma unroll
    for (int j = 0; j < 4; j++) {
        int n = j * 128 + threadIdx.x;
        float acc = fcpb[n];
#pragma unroll
        for (int i = 0; i < 60; i++)
            acc = fmaf(pe[i], fcpw[(size_t)i * 512 + n], acc);
        out[(size_t)bq * 512 + n] = acc;
    }
}

// ---------------- generic fp32 SGEMM: C = f(A)@W (+bias) (+res) ----------------
// BM=BN=128, BK=8, 256 threads, 8x8 per-thread tile. All dims divide tiles.
template<bool RELU_A, bool HAS_BIAS, bool HAS_RES>
__global__ __launch_bounds__(256, 2)
void k_sgemm(const float* __restrict__ A, const float* __restrict__ W,
             const float* __restrict__ bias, const float* __restrict__ R,
             float* __restrict__ C, int M, int N, int K) {
    __shared__ float As[8][128];
    __shared__ float Bs[8][128];
    const int tid = threadIdx.x;
    const int bn = blockIdx.x * 128;
    const int bm = blockIdx.y * 128;
    const int tx = (tid % 16) * 8;
    const int ty = (tid / 16) * 8;
    const int arow = tid >> 1;
    const int acol = (tid & 1) * 4;
    const int brow = tid >> 5;
    const int bcol = (tid & 31) * 4;

    float acc[8][8];
#pragma unroll
    for (int i = 0; i < 8; i++)
#pragma unroll
        for (int j = 0; j < 8; j++) acc[i][j] = 0.f;

    const float* Ap = A + (size_t)(bm + arow) * K + acol;
    const float* Wp = W + (size_t)brow * N + bn + bcol;

    for (int k0 = 0; k0 < K; k0 += 8) {
        float4 a4 = *(const float4*)(Ap + k0);
        if (RELU_A) {
            a4.x = fmaxf(a4.x, 0.f); a4.y = fmaxf(a4.y, 0.f);
            a4.z = fmaxf(a4.z, 0.f); a4.w = fmaxf(a4.w, 0.f);
        }
        As[acol + 0][arow] = a4.x; As[acol + 1][arow] = a4.y;
        As[acol + 2][arow] = a4.z; As[acol + 3][arow] = a4.w;
        float4 b4 = *(const float4*)(Wp + (size_t)k0 * N);
        *(float4*)(&Bs[brow][bcol]) = b4;
        __syncthreads();
#pragma unroll
        for (int kk = 0; kk < 8; kk++) {
            float ar[8], br[8];
            *(float4*)&ar[0] = *(const float4*)&As[kk][ty];
            *(float4*)&ar[4] = *(const float4*)&As[kk][ty + 4];
            *(float4*)&br[0] = *(const float4*)&Bs[kk][tx];
            *(float4*)&br[4] = *(const float4*)&Bs[kk][tx + 4];
#pragma unroll
            for (int i = 0; i < 8; i++)
#pragma unroll
                for (int j = 0; j < 8; j++)
                    acc[i][j] = fmaf(ar[i], br[j], acc[i][j]);
        }
        __syncthreads();
    }

#pragma unroll
    for (int i = 0; i < 8; i++) {
        int row = bm + ty + i;
#pragma unroll
        for (int j = 0; j < 8; j += 4) {
            int col = bn + tx + j;
            float4 v;
            v.x = acc[i][j]; v.y = acc[i][j + 1]; v.z = acc[i][j + 2]; v.w = acc[i][j + 3];
            if (HAS_BIAS) {
                v.x += bias[col]; v.y += bias[col + 1];
                v.z += bias[col + 2]; v.w += bias[col + 3];
            }
            if (HAS_RES) {
                float4 r4 = *(const float4*)(R + (size_t)row * N + col);
                v.x += r4.x; v.y += r4.y; v.z += r4.z; v.w += r4.w;
            }
            *(float4*)(C + (size_t)row * N + col) = v;
        }
    }
}

// ---------------- launch ----------------
extern "C" void kernel_launch(void* const* d_in, const int* in_sizes, int n_in,
                              void* d_out, int out_size) {
    const float* xyz_q        = (const float*)d_in[0];
    const float* global_feats = (const float*)d_in[1];
    const float* anchors_xyz  = (const float*)d_in[2];
    const float* anchors_feats= (const float*)d_in[3];
    const float* w_qs = (const float*)d_in[4];
    const float* w_ks = (const float*)d_in[5];
    const float* w_vs = (const float*)d_in[6];
    const float* w_kg = (const float*)d_in[7];
    const float* w_vg = (const float*)d_in[8];
    const float* d1_w = (const float*)d_in[9];
    const float* d1_b = (const float*)d_in[10];
    const float* d2_w = (const float*)d_in[11];
    const float* d2_b = (const float*)d_in[12];
    const float* g1_w = (const float*)d_in[13];
    const float* g1_b = (const float*)d_in[14];
    const float* g2_w = (const float*)d_in[15];
    const float* g2_b = (const float*)d_in[16];
    const float* fc_p_w = (const float*)d_in[17];
    const float* fc_p_b = (const float*)d_in[18];
    const float* fc_c_w = (const float*)d_in[19];
    const float* fc_c_b = (const float*)d_in[20];
    const float* blk0_w = (const float*)d_in[21];
    const float* blk0_b = (const float*)d_in[22];
    const float* blk1_w = (const float*)d_in[23];
    const float* blk1_b = (const float*)d_in[24];
    float* out = (float*)d_out;

    float *pKS, *pVS, *pA, *pB, *pC, *pLat, *pTmp, *pH;
    cudaGetSymbolAddress((void**)&pKS,  g_KS);
    cudaGetSymbolAddress((void**)&pVS,  g_VS);
    cudaGetSymbolAddress((void**)&pA,   g_bufA);
    cudaGetSymbolAddress((void**)&pB,   g_bufB);
    cudaGetSymbolAddress((void**)&pC,   g_bufC);
    cudaGetSymbolAddress((void**)&pLat, g_lat);
    cudaGetSymbolAddress((void**)&pTmp, g_tmp);
    cudaGetSymbolAddress((void**)&pH,   g_h);

    // global projections + KNN
    k_global_proj<<<(3 * B * DIM + 255) / 256, 256>>>(global_feats, w_qs, w_kg, w_vg);
    k_knn<<<dim3(NQ / 128, B), 128>>>(xyz_q, anchors_xyz);

    // KS / VS projections: [4096,512] = anchors_feats @ w
    k_sgemm<false,false,false><<<dim3(4, 32), 256>>>(anchors_feats, w_ks, nullptr, nullptr, pKS, B*NA, DIM, DIM);
    k_sgemm<false,false,false><<<dim3(4, 32), 256>>>(anchors_feats, w_vs, nullptr, nullptr, pVS, B*NA, DIM, DIM);

    // fc_delta: H1 (bufA) then PE = H1 @ d2_w + d2_b (bufB)
    k_h1<<<(unsigned)(((size_t)ROWS8 * DIM) / 256), 256>>>(xyz_q, anchors_xyz, d1_w, d1_b);
    k_sgemm<false,true,false><<<dim3(4, ROWS8 / 128), 256>>>(pA, d2_w, d2_b, nullptr, pB, ROWS8, DIM, DIM);

    // attention input X (bufC); T_pre = X@g1+b (bufA); G = relu(T_pre)@g2+b (bufC)
    k_buildx<<<(unsigned)(((size_t)ROWS9 * DIM) / 256), 256>>>();
    k_sgemm<false,true,false><<<dim3(4, ROWS9 / 128), 256>>>(pC, g1_w, g1_b, nullptr, pA, ROWS9, DIM, DIM);
    k_sgemm<true, true,false><<<dim3(4, ROWS9 / 128), 256>>>(pA, g2_w, g2_b, nullptr, pC, ROWS9, DIM, DIM);

    // softmax over 9 tokens + weighted sum -> lat
    k_attn_lat<<<BQ, 512>>>();

    // decoder: net0 = PE(xyz) @ fc_p + b  (into d_out)
    k_pe_fcp<<<BQ, 128>>>(xyz_q, fc_p_w, fc_p_b, out);

    for (int i = 0; i < NBLK; i++) {
        const float* cw = fc_c_w + (size_t)i * DIM * HID;
        const float* cb = fc_c_b + (size_t)i * HID;
        const float* b0w = blk0_w + (size_t)i * HID * HID;
        const float* b0b = blk0_b + (size_t)i * HID;
        const float* b1w = blk1_w + (size_t)i * HID * HID;
        const float* b1b = blk1_b + (size_t)i * HID;
        // tmp = net + lat @ fc_c + b
        k_sgemm<false,true,true ><<<dim3(4, BQ / 128), 256>>>(pLat, cw, cb, out, pTmp, BQ, HID, DIM);
        // h = relu(tmp) @ blk0 + b
        k_sgemm<true, true,false><<<dim3(4, BQ / 128), 256>>>(pTmp, b0w, b0b, nullptr, pH, BQ, HID, HID);
        // net = tmp + relu(h) @ blk1 + b
        k_sgemm<true, true,true ><<<dim3(4, BQ / 128), 256>>>(pH, b1w, b1b, pTmp, out, BQ, HID, HID);
    }
}

// round 7
// speedup vs baseline: 2.1164x; 2.1164x over previous
#include <cuda_runtime.h>
#include <cstdint>
#include <math.h>

#define B 2
#define NQ 4096
#define NA 2048
#define DIM 512
#define HID 512
#define NBLK 5
#define KNN 8

#define BQ    (B*NQ)        // 8192
#define ROWS8 (BQ*KNN)      // 65536
#define ROWS9 (BQ*9)        // 73728

// ---------------- static scratch (no allocations allowed) ----------------
__device__ float g_KS[B*NA*DIM];
__device__ float g_VS[B*NA*DIM];
__device__ int   g_idx[BQ*KNN];
__device__ float g_bufA[(size_t)ROWS9*DIM];
__device__ float g_bufB[(size_t)ROWS9*DIM];
__device__ float g_bufC[(size_t)ROWS9*DIM];
__device__ float g_lat[BQ*DIM];
__device__ float g_tmp[BQ*HID];
__device__ float g_h[BQ*HID];
__device__ float g_qattn[B*DIM];
__device__ float g_kgv[B*DIM];
__device__ float g_vgv[B*DIM];
__device__ float g_wt[(size_t)20*512*512];   // 20 transposed weight mats [N,K]

#define T_KS  0
#define T_VS  1
#define T_D2  2
#define T_G1  3
#define T_G2  4
#define T_FCC 5
#define T_B0  10
#define T_B1  15

// ---------------- tf32 helpers ----------------
__device__ __forceinline__ uint32_t to_tf32(float x) {
    uint32_t u;
    asm("cvt.rna.tf32.f32 %0, %1;" : "=r"(u) : "f"(x));
    return u;
}

__device__ __forceinline__ void mma_m16n8k8(float* d, const uint32_t* a, const uint32_t* b) {
    asm volatile(
        "mma.sync.aligned.m16n8k8.row.col.f32.tf32.tf32.f32 "
        "{%0,%1,%2,%3}, {%4,%5,%6,%7}, {%8,%9}, {%0,%1,%2,%3};"
        : "+f"(d[0]), "+f"(d[1]), "+f"(d[2]), "+f"(d[3])
        : "r"(a[0]), "r"(a[1]), "r"(a[2]), "r"(a[3]),
          "r"(b[0]), "r"(b[1]));
}

// ---------------- weight transpose: [K,N] -> [N,K] ----------------
__global__ void k_transpose(const float* __restrict__ wks, const float* __restrict__ wvs,
                            const float* __restrict__ d2w, const float* __restrict__ g1w,
                            const float* __restrict__ g2w, const float* __restrict__ fcc,
                            const float* __restrict__ b0w, const float* __restrict__ b1w) {
    __shared__ float t[32][33];
    int z = blockIdx.z;
    const float* src;
    if      (z == 0) src = wks;
    else if (z == 1) src = wvs;
    else if (z == 2) src = d2w;
    else if (z == 3) src = g1w;
    else if (z == 4) src = g2w;
    else if (z < 10) src = fcc + (size_t)(z - 5)  * 262144;
    else if (z < 15) src = b0w + (size_t)(z - 10) * 262144;
    else             src = b1w + (size_t)(z - 15) * 262144;
    float* dst = g_wt + (size_t)z * 262144;
    int x  = blockIdx.x * 32 + threadIdx.x;
    int y0 = blockIdx.y * 32;
#pragma unroll
    for (int i = threadIdx.y; i < 32; i += 8)
        t[i][threadIdx.x] = src[(size_t)(y0 + i) * 512 + x];
    __syncthreads();
    int xo  = blockIdx.y * 32 + threadIdx.x;
    int yo0 = blockIdx.x * 32;
#pragma unroll
    for (int i = threadIdx.y; i < 32; i += 8)
        dst[(size_t)(yo0 + i) * 512 + xo] = t[threadIdx.x][i];
}

// ---------------- tf32 mma.sync GEMM: C[M,512] = f(A[M,512]) @ WtT (+bias)(+res) ----
// Wt is [N,K] row-major (pre-transposed == B col-major for mma row.col).
// 128x128x16 CTA tile, 8 warps (2m x 4n), warp tile 64x32 = 4x4 m16n8k8.
template<bool RELU_A, bool HAS_BIAS, bool HAS_RES>
__global__ __launch_bounds__(256, 2)
void k_mma(const float* __restrict__ A, const float* __restrict__ Wt,
           const float* __restrict__ bias, const float* __restrict__ R,
           float* __restrict__ C, int M) {
    __shared__ float As[128][20];
    __shared__ float Bs[128][20];
    const int tid  = threadIdx.x;
    const int lane = tid & 31;
    const int warp = tid >> 5;
    const int wm   = warp >> 2;      // 0..1
    const int wn   = warp & 3;       // 0..3
    const int gid  = lane >> 2;      // 0..7
    const int tig  = lane & 3;       // 0..3
    const int bn = blockIdx.x * 128;
    const int bm = blockIdx.y * 128;

    // global->shared mapping: two float4 per thread per matrix
    const int r0 = tid >> 2;         // 0..63
    const int c4 = (tid & 3) * 4;    // 0,4,8,12

    float acc[4][4][4];
#pragma unroll
    for (int i = 0; i < 4; i++)
#pragma unroll
        for (int j = 0; j < 4; j++)
#pragma unroll
            for (int l = 0; l < 4; l++) acc[i][j][l] = 0.f;

    for (int k0 = 0; k0 < 512; k0 += 16) {
#pragma unroll
        for (int h = 0; h < 2; h++) {
            const int row = r0 + h * 64;
            float4 a4 = *(const float4*)(A  + (size_t)(bm + row) * 512 + k0 + c4);
            float4 b4 = *(const float4*)(Wt + (size_t)(bn + row) * 512 + k0 + c4);
            if (RELU_A) {
                a4.x = fmaxf(a4.x, 0.f); a4.y = fmaxf(a4.y, 0.f);
                a4.z = fmaxf(a4.z, 0.f); a4.w = fmaxf(a4.w, 0.f);
            }
            As[row][c4 + 0] = __uint_as_float(to_tf32(a4.x));
            As[row][c4 + 1] = __uint_as_float(to_tf32(a4.y));
            As[row][c4 + 2] = __uint_as_float(to_tf32(a4.z));
            As[row][c4 + 3] = __uint_as_float(to_tf32(a4.w));
            Bs[row][c4 + 0] = __uint_as_float(to_tf32(b4.x));
            Bs[row][c4 + 1] = __uint_as_float(to_tf32(b4.y));
            Bs[row][c4 + 2] = __uint_as_float(to_tf32(b4.z));
            Bs[row][c4 + 3] = __uint_as_float(to_tf32(b4.w));
        }
        __syncthreads();

#pragma unroll
        for (int k8 = 0; k8 < 16; k8 += 8) {
            uint32_t af[4][4], bf[4][2];
#pragma unroll
            for (int mi = 0; mi < 4; mi++) {
                const int m = wm * 64 + mi * 16 + gid;
                af[mi][0] = __float_as_uint(As[m    ][k8 + tig    ]);
                af[mi][1] = __float_as_uint(As[m + 8][k8 + tig    ]);
                af[mi][2] = __float_as_uint(As[m    ][k8 + tig + 4]);
                af[mi][3] = __float_as_uint(As[m + 8][k8 + tig + 4]);
            }
#pragma unroll
            for (int ni = 0; ni < 4; ni++) {
                const int n = wn * 32 + ni * 8 + gid;
                bf[ni][0] = __float_as_uint(Bs[n][k8 + tig    ]);
                bf[ni][1] = __float_as_uint(Bs[n][k8 + tig + 4]);
            }
#pragma unroll
            for (int mi = 0; mi < 4; mi++)
#pragma unroll
                for (int ni = 0; ni < 4; ni++)
                    mma_m16n8k8(acc[mi][ni], af[mi], bf[ni]);
        }
        __syncthreads();
    }

    // epilogue: c0,c1 -> row gid, cols 2tig,2tig+1; c2,c3 -> row gid+8
#pragma unroll
    for (int mi = 0; mi < 4; mi++) {
#pragma unroll
        for (int h = 0; h < 2; h++) {
            const int row = bm + wm * 64 + mi * 16 + gid + h * 8;
            float* Crow = C + (size_t)row * 512;
            const float* Rrow = R + (size_t)row * 512;
#pragma unroll
            for (int ni = 0; ni < 4; ni++) {
                const int col = bn + wn * 32 + ni * 8 + tig * 2;
                float2 v;
                v.x = acc[mi][ni][h * 2 + 0];
                v.y = acc[mi][ni][h * 2 + 1];
                if (HAS_BIAS) { v.x += bias[col]; v.y += bias[col + 1]; }
                if (HAS_RES) {
                    float2 rr = *(const float2*)(Rrow + col);
                    v.x += rr.x; v.y += rr.y;
                }
                *(float2*)(Crow + col) = v;
            }
        }
    }
}

// ---------------- tiny projection of global feats ----------------
__global__ void k_global_proj(const float* __restrict__ gf,
                              const float* __restrict__ wqs,
                              const float* __restrict__ wkg,
                              const float* __restrict__ wvg) {
    int t = blockIdx.x * blockDim.x + threadIdx.x;
    if (t >= 3 * B * DIM) return;
    int which = t / (B * DIM);
    int r = t % (B * DIM);
    int b = r / DIM, n = r % DIM;
    const float* W = (which == 0) ? wqs : (which == 1) ? wkg : wvg;
    float acc = 0.f;
    for (int k = 0; k < DIM; k++)
        acc = fmaf(gf[b * DIM + k], W[(size_t)k * DIM + n], acc);
    float* out = (which == 0) ? g_qattn : (which == 1) ? g_kgv : g_vgv;
    out[b * DIM + n] = acc;
}

// ---------------- brute-force KNN (top-8 smallest d2) ----------------
__global__ void k_knn(const float* __restrict__ xyz_q,
                      const float* __restrict__ axyz) {
    __shared__ float sx[512], sy[512], sz[512], s2[512];
    int b = blockIdx.y;
    int q = blockIdx.x * 128 + threadIdx.x;
    int bq = b * NQ + q;
    float qx = xyz_q[bq * 3 + 0];
    float qy = xyz_q[bq * 3 + 1];
    float qz = xyz_q[bq * 3 + 2];
    float q2 = qx * qx + qy * qy + qz * qz;
    float bd[KNN]; int bi[KNN];
#pragma unroll
    for (int i = 0; i < KNN; i++) { bd[i] = INFINITY; bi[i] = 0; }
    for (int t0 = 0; t0 < NA; t0 += 512) {
        __syncthreads();
        for (int j = threadIdx.x; j < 512; j += 128) {
            float ax = axyz[(b * NA + t0 + j) * 3 + 0];
            float ay = axyz[(b * NA + t0 + j) * 3 + 1];
            float az = axyz[(b * NA + t0 + j) * 3 + 2];
            sx[j] = ax; sy[j] = ay; sz[j] = az;
            s2[j] = ax * ax + ay * ay + az * az;
        }
        __syncthreads();
        for (int j = 0; j < 512; j++) {
            float d2 = q2 + s2[j] - 2.f * (qx * sx[j] + qy * sy[j] + qz * sz[j]);
            if (d2 < bd[KNN - 1]) {
                bd[KNN - 1] = d2; bi[KNN - 1] = t0 + j;
#pragma unroll
                for (int s = KNN - 1; s > 0; --s) {
                    if (bd[s] < bd[s - 1]) {
                        float td = bd[s]; bd[s] = bd[s - 1]; bd[s - 1] = td;
                        int ti = bi[s]; bi[s] = bi[s - 1]; bi[s - 1] = ti;
                    }
                }
            }
        }
    }
#pragma unroll
    for (int i = 0; i < KNN; i++) g_idx[bq * KNN + i] = bi[i];
}

// ---------------- H1 = relu(d @ d1_w + d1_b) ----------------
__global__ void k_h1(const float* __restrict__ xyz_q,
                     const float* __restrict__ axyz,
                     const float* __restrict__ d1w,
                     const float* __restrict__ d1b) {
    size_t o = (size_t)blockIdx.x * blockDim.x + threadIdx.x;
    if (o >= (size_t)ROWS8 * DIM) return;
    int f = (int)(o & 511);
    size_t r = o >> 9;
    int kk = (int)(r & 7);
    int bq = (int)(r >> 3);
    int b = bq >> 12;
    int aidx = g_idx[bq * KNN + kk];
    const float* qp = xyz_q + (size_t)bq * 3;
    const float* ap = axyz + ((size_t)b * NA + aidx) * 3;
    float dx = qp[0] - ap[0], dy = qp[1] - ap[1], dz = qp[2] - ap[2];
    float h = fmaf(dx, d1w[f], fmaf(dy, d1w[512 + f], fmaf(dz, d1w[1024 + f], d1b[f])));
    g_bufA[o] = fmaxf(h, 0.f);
}

// ---------------- build attention input X = q - k + pos ----------------
__global__ void k_buildx() {
    size_t o = (size_t)blockIdx.x * blockDim.x + threadIdx.x;
    if (o >= (size_t)ROWS9 * DIM) return;
    int f = (int)(o & 511);
    size_t r = o >> 9;
    int n = (int)(r % 9);
    int bq = (int)(r / 9);
    int b = bq >> 12;
    float v = g_qattn[b * DIM + f];
    if (n < KNN) {
        int aidx = g_idx[bq * KNN + n];
        v = v - g_KS[((size_t)b * NA + aidx) * DIM + f]
              + g_bufB[((size_t)bq * KNN + n) * DIM + f];
    } else {
        v = v - g_kgv[b * DIM + f];
    }
    g_bufC[o] = v;
}

// ---------------- per-feature softmax over 9 tokens + weighted sum ----------------
__global__ void k_attn_lat() {
    int bq = blockIdx.x;
    int f = threadIdx.x;
    int b = bq >> 12;
    __shared__ int sidx[KNN];
    if (threadIdx.x < KNN) sidx[threadIdx.x] = g_idx[bq * KNN + threadIdx.x];
    __syncthreads();
    float v[9];
#pragma unroll
    for (int n = 0; n < 9; n++)
        v[n] = g_bufC[((size_t)bq * 9 + n) * DIM + f];
    float m = v[0];
#pragma unroll
    for (int n = 1; n < 9; n++) m = fmaxf(m, v[n]);
    float s = 0.f;
#pragma unroll
    for (int n = 0; n < 9; n++) { v[n] = expf(v[n] - m); s += v[n]; }
    float inv = 1.f / s;
    float acc = 0.f;
#pragma unroll
    for (int n = 0; n < KNN; n++) {
        float val = g_VS[((size_t)b * NA + sidx[n]) * DIM + f]
                  + g_bufB[((size_t)bq * KNN + n) * DIM + f];
        acc = fmaf(v[n], val, acc);
    }
    acc = fmaf(v[8], g_vgv[b * DIM + f], acc);
    g_lat[(size_t)bq * DIM + f] = acc * inv;
}

// ---------------- NeRF positional encoding + fc_p ----------------
__global__ void k_pe_fcp(const float* __restrict__ xyz_q,
                         const float* __restrict__ fcpw,
                         const float* __restrict__ fcpb,
                         float* __restrict__ out) {
    __shared__ float pe[60];
    int bq = blockIdx.x;
    if (threadIdx.x < 60) {
        int i = threadIdx.x;
        int fr = i / 6, rem = i % 6, sc = rem / 3, c = rem % 3;
        float p = xyz_q[(size_t)bq * 3 + c];
        float a = p * ((float)(1 << fr) * 3.14159265358979f);
        pe[i] = (sc == 0) ? sinf(a) : cosf(a);
    }
    __syncthreads();
#pragma unroll
    for (int j = 0; j < 4; j++) {
        int n = j * 128 + threadIdx.x;
        float acc = fcpb[n];
#pragma unroll
        for (int i = 0; i < 60; i++)
            acc = fmaf(pe[i], fcpw[(size_t)i * 512 + n], acc);
        out[(size_t)bq * 512 + n] = acc;
    }
}

// ---------------- launch ----------------
extern "C" void kernel_launch(void* const* d_in, const int* in_sizes, int n_in,
                              void* d_out, int out_size) {
    const float* xyz_q        = (const float*)d_in[0];
    const float* global_feats = (const float*)d_in[1];
    const float* anchors_xyz  = (const float*)d_in[2];
    const float* anchors_feats= (const float*)d_in[3];
    const float* w_qs = (const float*)d_in[4];
    const float* w_ks = (const float*)d_in[5];
    const float* w_vs = (const float*)d_in[6];
    const float* w_kg = (const float*)d_in[7];
    const float* w_vg = (const float*)d_in[8];
    const float* d1_w = (const float*)d_in[9];
    const float* d1_b = (const float*)d_in[10];
    const float* d2_w = (const float*)d_in[11];
    const float* d2_b = (const float*)d_in[12];
    const float* g1_w = (const float*)d_in[13];
    const float* g1_b = (const float*)d_in[14];
    const float* g2_w = (const float*)d_in[15];
    const float* g2_b = (const float*)d_in[16];
    const float* fc_p_w = (const float*)d_in[17];
    const float* fc_p_b = (const float*)d_in[18];
    const float* fc_c_w = (const float*)d_in[19];
    const float* fc_c_b = (const float*)d_in[20];
    const float* blk0_w = (const float*)d_in[21];
    const float* blk0_b = (const float*)d_in[22];
    const float* blk1_w = (const float*)d_in[23];
    const float* blk1_b = (const float*)d_in[24];
    float* out = (float*)d_out;

    float *pKS, *pVS, *pA, *pB, *pC, *pLat, *pTmp, *pH, *pWT;
    cudaGetSymbolAddress((void**)&pKS,  g_KS);
    cudaGetSymbolAddress((void**)&pVS,  g_VS);
    cudaGetSymbolAddress((void**)&pA,   g_bufA);
    cudaGetSymbolAddress((void**)&pB,   g_bufB);
    cudaGetSymbolAddress((void**)&pC,   g_bufC);
    cudaGetSymbolAddress((void**)&pLat, g_lat);
    cudaGetSymbolAddress((void**)&pTmp, g_tmp);
    cudaGetSymbolAddress((void**)&pH,   g_h);
    cudaGetSymbolAddress((void**)&pWT,  g_wt);

    // weight transposes + global projections + KNN
    k_transpose<<<dim3(16, 16, 20), dim3(32, 8)>>>(w_ks, w_vs, d2_w, g1_w, g2_w,
                                                   fc_c_w, blk0_w, blk1_w);
    k_global_proj<<<(3 * B * DIM + 255) / 256, 256>>>(global_feats, w_qs, w_kg, w_vg);
    k_knn<<<dim3(NQ / 128, B), 128>>>(xyz_q, anchors_xyz);

    // KS / VS projections
    k_mma<false,false,false><<<dim3(4, (B*NA)/128), 256>>>(
        anchors_feats, pWT + (size_t)T_KS*262144, nullptr, nullptr, pKS, B*NA);
    k_mma<false,false,false><<<dim3(4, (B*NA)/128), 256>>>(
        anchors_feats, pWT + (size_t)T_VS*262144, nullptr, nullptr, pVS, B*NA);

    // fc_delta
    k_h1<<<(unsigned)(((size_t)ROWS8 * DIM) / 256), 256>>>(xyz_q, anchors_xyz, d1_w, d1_b);
    k_mma<false,true,false><<<dim3(4, ROWS8/128), 256>>>(
        pA, pWT + (size_t)T_D2*262144, d2_b, nullptr, pB, ROWS8);

    // attention MLPs
    k_buildx<<<(unsigned)(((size_t)ROWS9 * DIM) / 256), 256>>>();
    k_mma<false,true,false><<<dim3(4, ROWS9/128), 256>>>(
        pC, pWT + (size_t)T_G1*262144, g1_b, nullptr, pA, ROWS9);
    k_mma<true, true,false><<<dim3(4, ROWS9/128), 256>>>(
        pA, pWT + (size_t)T_G2*262144, g2_b, nullptr, pC, ROWS9);

    // softmax + weighted sum
    k_attn_lat<<<BQ, 512>>>();

    // decoder
    k_pe_fcp<<<BQ, 128>>>(xyz_q, fc_p_w, fc_p_b, out);

    for (int i = 0; i < NBLK; i++) {
        const float* cb  = fc_c_b + (size_t)i * HID;
        const float* b0b = blk0_b + (size_t)i * HID;
        const float* b1b = blk1_b + (size_t)i * HID;
        float* cwT  = pWT + (size_t)(T_FCC + i) * 262144;
        float* b0wT = pWT + (size_t)(T_B0  + i) * 262144;
        float* b1wT = pWT + (size_t)(T_B1  + i) * 262144;
        // tmp = net + lat @ fc_c + b
        k_mma<false,true,true ><<<dim3(4, BQ/128), 256>>>(
            pLat, cwT, cb, out, pTmp, BQ);
        // h = relu(tmp) @ blk0 + b
        k_mma<true, true,false><<<dim3(4, BQ/128), 256>>>(
            pTmp, b0wT, b0b, nullptr, pH, BQ);
        // net = tmp + relu(h) @ blk1 + b
        k_mma<true, true,true ><<<dim3(4, BQ/128), 256>>>(
            pH, b1wT, b1b, pTmp, out, BQ);
    }
}

// round 10
// speedup vs baseline: 2.3020x; 1.0877x over previous
#include <cuda_runtime.h>
#include <cstdint>
#include <math.h>

#define B 2
#define NQ 4096
#define NA 2048
#define DIM 512
#define HID 512
#define NBLK 5
#define KNN 8

#define BQ    (B*NQ)        // 8192
#define ROWS8 (BQ*KNN)      // 65536
#define ROWS9 (BQ*9)        // 73728

// ---------------- static scratch (no allocations allowed) ----------------
__device__ float g_KS[B*NA*DIM];
__device__ float g_VS[B*NA*DIM];
__device__ int   g_idx[BQ*KNN];
__device__ float g_bufA[(size_t)ROWS9*DIM];
__device__ float g_bufB[(size_t)ROWS9*DIM];
__device__ float g_bufC[(size_t)ROWS9*DIM];
__device__ float g_lat[BQ*DIM];
__device__ float g_tmp[BQ*HID];
__device__ float g_h[BQ*HID];
__device__ float g_qattn[B*DIM];
__device__ float g_kgv[B*DIM];
__device__ float g_vgv[B*DIM];
__device__ float g_wt[(size_t)20*512*512];   // 20 transposed weight mats [N,K]

#define T_KS  0
#define T_VS  1
#define T_D2  2
#define T_G1  3
#define T_G2  4
#define T_FCC 5
#define T_B0  10
#define T_B1  15

// ---------------- tf32 / cp.async helpers ----------------
__device__ __forceinline__ uint32_t to_tf32(float x) {
    uint32_t u;
    asm("cvt.rna.tf32.f32 %0, %1;" : "=r"(u) : "f"(x));
    return u;
}

__device__ __forceinline__ void cp16(void* smem_dst, const void* gsrc) {
    uint32_t s = (uint32_t)__cvta_generic_to_shared(smem_dst);
    asm volatile("cp.async.ca.shared.global [%0], [%1], 16;" :: "r"(s), "l"(gsrc) : "memory");
}
#define CP_COMMIT() asm volatile("cp.async.commit_group;" ::: "memory")
#define CP_WAIT1()  asm volatile("cp.async.wait_group 1;" ::: "memory")
#define CP_WAIT0()  asm volatile("cp.async.wait_group 0;" ::: "memory")

__device__ __forceinline__ void mma_m16n8k8(float* d, const uint32_t* a, const uint32_t* b) {
    asm volatile(
        "mma.sync.aligned.m16n8k8.row.col.f32.tf32.tf32.f32 "
        "{%0,%1,%2,%3}, {%4,%5,%6,%7}, {%8,%9}, {%0,%1,%2,%3};"
        : "+f"(d[0]), "+f"(d[1]), "+f"(d[2]), "+f"(d[3])
        : "r"(a[0]), "r"(a[1]), "r"(a[2]), "r"(a[3]),
          "r"(b[0]), "r"(b[1]));
}

// ---------------- weight transpose: [K,N] -> [N,K] ----------------
__global__ void k_transpose(const float* __restrict__ wks, const float* __restrict__ wvs,
                            const float* __restrict__ d2w, const float* __restrict__ g1w,
                            const float* __restrict__ g2w, const float* __restrict__ fcc,
                            const float* __restrict__ b0w, const float* __restrict__ b1w) {
    __shared__ float t[32][33];
    int z = blockIdx.z;
    const float* src;
    if      (z == 0) src = wks;
    else if (z == 1) src = wvs;
    else if (z == 2) src = d2w;
    else if (z == 3) src = g1w;
    else if (z == 4) src = g2w;
    else if (z < 10) src = fcc + (size_t)(z - 5)  * 262144;
    else if (z < 15) src = b0w + (size_t)(z - 10) * 262144;
    else             src = b1w + (size_t)(z - 15) * 262144;
    float* dst = g_wt + (size_t)z * 262144;
    int x  = blockIdx.x * 32 + threadIdx.x;
    int y0 = blockIdx.y * 32;
#pragma unroll
    for (int i = threadIdx.y; i < 32; i += 8)
        t[i][threadIdx.x] = src[(size_t)(y0 + i) * 512 + x];
    __syncthreads();
    int xo  = blockIdx.y * 32 + threadIdx.x;
    int yo0 = blockIdx.x * 32;
#pragma unroll
    for (int i = threadIdx.y; i < 32; i += 8)
        dst[(size_t)(yo0 + i) * 512 + xo] = t[threadIdx.x][i];
}

// ---------------- tf32 mma.sync GEMM with cp.async double buffering ----------------
// C[M,512] = f(A[M,512]) @ WtT (+bias)(+res); Wt is [N,K] row-major.
// 128x128x16 CTA tile, 8 warps (2m x 4n), warp tile 64x32 = 4x4 m16n8k8.
// SMEM holds raw fp32 (cp.async); relu+tf32 conversion at fragment load.
template<bool RELU_A, bool HAS_BIAS, bool HAS_RES>
__global__ __launch_bounds__(256, 2)
void k_mma(const float* __restrict__ A, const float* __restrict__ Wt,
           const float* __restrict__ bias, const float* __restrict__ R,
           float* __restrict__ C, int M) {
    __shared__ float As[2][128][20];
    __shared__ float Bs[2][128][20];
    const int tid  = threadIdx.x;
    const int lane = tid & 31;
    const int warp = tid >> 5;
    const int wm   = warp >> 2;      // 0..1
    const int wn   = warp & 3;       // 0..3
    const int gid  = lane >> 2;      // 0..7
    const int tig  = lane & 3;       // 0..3
    const int bn = blockIdx.x * 128;
    const int bm = blockIdx.y * 128;

    const int r0 = tid >> 2;         // 0..63
    const int c4 = (tid & 3) * 4;    // 0,4,8,12

    float acc[4][4][4];
#pragma unroll
    for (int i = 0; i < 4; i++)
#pragma unroll
        for (int j = 0; j < 4; j++)
#pragma unroll
            for (int l = 0; l < 4; l++) acc[i][j][l] = 0.f;

    // prologue: prefetch stage 0
#pragma unroll
    for (int h = 0; h < 2; h++) {
        const int row = r0 + h * 64;
        cp16(&As[0][row][c4], A  + (size_t)(bm + row) * 512 + c4);
        cp16(&Bs[0][row][c4], Wt + (size_t)(bn + row) * 512 + c4);
    }
    CP_COMMIT();

#pragma unroll 1
    for (int it = 0; it < 32; ++it) {
        const int st = it & 1;
        if (it + 1 < 32) {
            const int k0  = (it + 1) * 16;
            const int st2 = (it + 1) & 1;
#pragma unroll
            for (int h = 0; h < 2; h++) {
                const int row = r0 + h * 64;
                cp16(&As[st2][row][c4], A  + (size_t)(bm + row) * 512 + k0 + c4);
                cp16(&Bs[st2][row][c4], Wt + (size_t)(bn + row) * 512 + k0 + c4);
            }
            CP_COMMIT();
            CP_WAIT1();
        } else {
            CP_WAIT0();
        }
        __syncthreads();

#pragma unroll
        for (int k8 = 0; k8 < 16; k8 += 8) {
            uint32_t af[4][4], bf[4][2];
#pragma unroll
            for (int mi = 0; mi < 4; mi++) {
                const int m = wm * 64 + mi * 16 + gid;
                float a0 = As[st][m    ][k8 + tig    ];
                float a1 = As[st][m + 8][k8 + tig    ];
                float a2 = As[st][m    ][k8 + tig + 4];
                float a3 = As[st][m + 8][k8 + tig + 4];
                if (RELU_A) {
                    a0 = fmaxf(a0, 0.f); a1 = fmaxf(a1, 0.f);
                    a2 = fmaxf(a2, 0.f); a3 = fmaxf(a3, 0.f);
                }
                af[mi][0] = to_tf32(a0); af[mi][1] = to_tf32(a1);
                af[mi][2] = to_tf32(a2); af[mi][3] = to_tf32(a3);
            }
#pragma unroll
            for (int ni = 0; ni < 4; ni++) {
                const int n = wn * 32 + ni * 8 + gid;
                bf[ni][0] = to_tf32(Bs[st][n][k8 + tig    ]);
                bf[ni][1] = to_tf32(Bs[st][n][k8 + tig + 4]);
            }
#pragma unroll
            for (int mi = 0; mi < 4; mi++)
#pragma unroll
                for (int ni = 0; ni < 4; ni++)
                    mma_m16n8k8(acc[mi][ni], af[mi], bf[ni]);
        }
        __syncthreads();
    }

    // epilogue: c0,c1 -> row gid, cols 2tig,2tig+1; c2,c3 -> row gid+8
#pragma unroll
    for (int mi = 0; mi < 4; mi++) {
#pragma unroll
        for (int h = 0; h < 2; h++) {
            const int row = bm + wm * 64 + mi * 16 + gid + h * 8;
            float* Crow = C + (size_t)row * 512;
            const float* Rrow = R + (size_t)row * 512;
#pragma unroll
            for (int ni = 0; ni < 4; ni++) {
                const int col = bn + wn * 32 + ni * 8 + tig * 2;
                float2 v;
                v.x = acc[mi][ni][h * 2 + 0];
                v.y = acc[mi][ni][h * 2 + 1];
                if (HAS_BIAS) { v.x += bias[col]; v.y += bias[col + 1]; }
                if (HAS_RES) {
                    float2 rr = *(const float2*)(Rrow + col);
                    v.x += rr.x; v.y += rr.y;
                }
                *(float2*)(Crow + col) = v;
            }
        }
    }
}

// ---------------- tiny projection of global feats ----------------
__global__ void k_global_proj(const float* __restrict__ gf,
                              const float* __restrict__ wqs,
                              const float* __restrict__ wkg,
                              const float* __restrict__ wvg) {
    int t = blockIdx.x * blockDim.x + threadIdx.x;
    if (t >= 3 * B * DIM) return;
    int which = t / (B * DIM);
    int r = t % (B * DIM);
    int b = r / DIM, n = r % DIM;
    const float* W = (which == 0) ? wqs : (which == 1) ? wkg : wvg;
    float acc = 0.f;
    for (int k = 0; k < DIM; k++)
        acc = fmaf(gf[b * DIM + k], W[(size_t)k * DIM + n], acc);
    float* out = (which == 0) ? g_qattn : (which == 1) ? g_kgv : g_vgv;
    out[b * DIM + n] = acc;
}

// ---------------- brute-force KNN (top-8 smallest d2) ----------------
__global__ void k_knn(const float* __restrict__ xyz_q,
                      const float* __restrict__ axyz) {
    __shared__ float sx[512], sy[512], sz[512], s2[512];
    int b = blockIdx.y;
    int q = blockIdx.x * 128 + threadIdx.x;
    int bq = b * NQ + q;
    float qx = xyz_q[bq * 3 + 0];
    float qy = xyz_q[bq * 3 + 1];
    float qz = xyz_q[bq * 3 + 2];
    float q2 = qx * qx + qy * qy + qz * qz;
    float bd[KNN]; int bi[KNN];
#pragma unroll
    for (int i = 0; i < KNN; i++) { bd[i] = INFINITY; bi[i] = 0; }
    for (int t0 = 0; t0 < NA; t0 += 512) {
        __syncthreads();
        for (int j = threadIdx.x; j < 512; j += 128) {
            float ax = axyz[(b * NA + t0 + j) * 3 + 0];
            float ay = axyz[(b * NA + t0 + j) * 3 + 1];
            float az = axyz[(b * NA + t0 + j) * 3 + 2];
            sx[j] = ax; sy[j] = ay; sz[j] = az;
            s2[j] = ax * ax + ay * ay + az * az;
        }
        __syncthreads();
        for (int j = 0; j < 512; j++) {
            float d2 = q2 + s2[j] - 2.f * (qx * sx[j] + qy * sy[j] + qz * sz[j]);
            if (d2 < bd[KNN - 1]) {
                bd[KNN - 1] = d2; bi[KNN - 1] = t0 + j;
#pragma unroll
                for (int s = KNN - 1; s > 0; --s) {
                    if (bd[s] < bd[s - 1]) {
                        float td = bd[s]; bd[s] = bd[s - 1]; bd[s - 1] = td;
                        int ti = bi[s]; bi[s] = bi[s - 1]; bi[s - 1] = ti;
                    }
                }
            }
        }
    }
#pragma unroll
    for (int i = 0; i < KNN; i++) g_idx[bq * KNN + i] = bi[i];
}

// ---------------- H1 = relu(d @ d1_w + d1_b) ----------------
__global__ void k_h1(const float* __restrict__ xyz_q,
                     const float* __restrict__ axyz,
                     const float* __restrict__ d1w,
                     const float* __restrict__ d1b) {
    size_t o = (size_t)blockIdx.x * blockDim.x + threadIdx.x;
    if (o >= (size_t)ROWS8 * DIM) return;
    int f = (int)(o & 511);
    size_t r = o >> 9;
    int kk = (int)(r & 7);
    int bq = (int)(r >> 3);
    int b = bq >> 12;
    int aidx = g_idx[bq * KNN + kk];
    const float* qp = xyz_q + (size_t)bq * 3;
    const float* ap = axyz + ((size_t)b * NA + aidx) * 3;
    float dx = qp[0] - ap[0], dy = qp[1] - ap[1], dz = qp[2] - ap[2];
    float h = fmaf(dx, d1w[f], fmaf(dy, d1w[512 + f], fmaf(dz, d1w[1024 + f], d1b[f])));
    g_bufA[o] = fmaxf(h, 0.f);
}

// ---------------- build attention input X = q - k + pos ----------------
__global__ void k_buildx() {
    size_t o = (size_t)blockIdx.x * blockDim.x + threadIdx.x;
    if (o >= (size_t)ROWS9 * DIM) return;
    int f = (int)(o & 511);
    size_t r = o >> 9;
    int n = (int)(r % 9);
    int bq = (int)(r / 9);
    int b = bq >> 12;
    float v = g_qattn[b * DIM + f];
    if (n < KNN) {
        int aidx = g_idx[bq * KNN + n];
        v = v - g_KS[((size_t)b * NA + aidx) * DIM + f]
              + g_bufB[((size_t)bq * KNN + n) * DIM + f];
    } else {
        v = v - g_kgv[b * DIM + f];
    }
    g_bufC[o] = v;
}

// ---------------- per-feature softmax over 9 tokens + weighted sum ----------------
__global__ void k_attn_lat() {
    int bq = blockIdx.x;
    int f = threadIdx.x;
    int b = bq >> 12;
    __shared__ int sidx[KNN];
    if (threadIdx.x < KNN) sidx[threadIdx.x] = g_idx[bq * KNN + threadIdx.x];
    __syncthreads();
    float v[9];
#pragma unroll
    for (int n = 0; n < 9; n++)
        v[n] = g_bufC[((size_t)bq * 9 + n) * DIM + f];
    float m = v[0];
#pragma unroll
    for (int n = 1; n < 9; n++) m = fmaxf(m, v[n]);
    float s = 0.f;
#pragma unroll
    for (int n = 0; n < 9; n++) { v[n] = expf(v[n] - m); s += v[n]; }
    float inv = 1.f / s;
    float acc = 0.f;
#pragma unroll
    for (int n = 0; n < KNN; n++) {
        float val = g_VS[((size_t)b * NA + sidx[n]) * DIM + f]
                  + g_bufB[((size_t)bq * KNN + n) * DIM + f];
        acc = fmaf(v[n], val, acc);
    }
    acc = fmaf(v[8], g_vgv[b * DIM + f], acc);
    g_lat[(size_t)bq * DIM + f] = acc * inv;
}

// ---------------- NeRF positional encoding + fc_p ----------------
__global__ void k_pe_fcp(const float* __restrict__ xyz_q,
                         const float* __restrict__ fcpw,
                         const float* __restrict__ fcpb,
                         float* __restrict__ out) {
    __shared__ float pe[60];
    int bq = blockIdx.x;
    if (threadIdx.x < 60) {
        int i = threadIdx.x;
        int fr = i / 6, rem = i % 6, sc = rem / 3, c = rem % 3;
        float p = xyz_q[(size_t)bq * 3 + c];
        float a = p * ((float)(1 << fr) * 3.14159265358979f);
        pe[i] = (sc == 0) ? sinf(a) : cosf(a);
    }
    __syncthreads();
#pragma unroll
    for (int j = 0; j < 4; j++) {
        int n = j * 128 + threadIdx.x;
        float acc = fcpb[n];
#pragma unroll
        for (int i = 0; i < 60; i++)
            acc = fmaf(pe[i], fcpw[(size_t)i * 512 + n], acc);
        out[(size_t)bq * 512 + n] = acc;
    }
}

// ---------------- launch ----------------
extern "C" void kernel_launch(void* const* d_in, const int* in_sizes, int n_in,
                              void* d_out, int out_size) {
    const float* xyz_q        = (const float*)d_in[0];
    const float* global_feats = (const float*)d_in[1];
    const float* anchors_xyz  = (const float*)d_in[2];
    const float* anchors_feats= (const float*)d_in[3];
    const float* w_qs = (const float*)d_in[4];
    const float* w_ks = (const float*)d_in[5];
    const float* w_vs = (const float*)d_in[6];
    const float* w_kg = (const float*)d_in[7];
    const float* w_vg = (const float*)d_in[8];
    const float* d1_w = (const float*)d_in[9];
    const float* d1_b = (const float*)d_in[10];
    const float* d2_w = (const float*)d_in[11];
    const float* d2_b = (const float*)d_in[12];
    const float* g1_w = (const float*)d_in[13];
    const float* g1_b = (const float*)d_in[14];
    const float* g2_w = (const float*)d_in[15];
    const float* g2_b = (const float*)d_in[16];
    const float* fc_p_w = (const float*)d_in[17];
    const float* fc_p_b = (const float*)d_in[18];
    const float* fc_c_w = (const float*)d_in[19];
    const float* fc_c_b = (const float*)d_in[20];
    const float* blk0_w = (const float*)d_in[21];
    const float* blk0_b = (const float*)d_in[22];
    const float* blk1_w = (const float*)d_in[23];
    const float* blk1_b = (const float*)d_in[24];
    float* out = (float*)d_out;

    float *pKS, *pVS, *pA, *pB, *pC, *pLat, *pTmp, *pH, *pWT;
    cudaGetSymbolAddress((void**)&pKS,  g_KS);
    cudaGetSymbolAddress((void**)&pVS,  g_VS);
    cudaGetSymbolAddress((void**)&pA,   g_bufA);
    cudaGetSymbolAddress((void**)&pB,   g_bufB);
    cudaGetSymbolAddress((void**)&pC,   g_bufC);
    cudaGetSymbolAddress((void**)&pLat, g_lat);
    cudaGetSymbolAddress((void**)&pTmp, g_tmp);
    cudaGetSymbolAddress((void**)&pH,   g_h);
    cudaGetSymbolAddress((void**)&pWT,  g_wt);

    // weight transposes + global projections + KNN
    k_transpose<<<dim3(16, 16, 20), dim3(32, 8)>>>(w_ks, w_vs, d2_w, g1_w, g2_w,
                                                   fc_c_w, blk0_w, blk1_w);
    k_global_proj<<<(3 * B * DIM + 255) / 256, 256>>>(global_feats, w_qs, w_kg, w_vg);
    k_knn<<<dim3(NQ / 128, B), 128>>>(xyz_q, anchors_xyz);

    // KS / VS projections
    k_mma<false,false,false><<<dim3(4, (B*NA)/128), 256>>>(
        anchors_feats, pWT + (size_t)T_KS*262144, nullptr, nullptr, pKS, B*NA);
    k_mma<false,false,false><<<dim3(4, (B*NA)/128), 256>>>(
        anchors_feats, pWT + (size_t)T_VS*262144, nullptr, nullptr, pVS, B*NA);

    // fc_delta
    k_h1<<<(unsigned)(((size_t)ROWS8 * DIM) / 256), 256>>>(xyz_q, anchors_xyz, d1_w, d1_b);
    k_mma<false,true,false><<<dim3(4, ROWS8/128), 256>>>(
        pA, pWT + (size_t)T_D2*262144, d2_b, nullptr, pB, ROWS8);

    // attention MLPs
    k_buildx<<<(unsigned)(((size_t)ROWS9 * DIM) / 256), 256>>>();
    k_mma<false,true,false><<<dim3(4, ROWS9/128), 256>>>(
        pC, pWT + (size_t)T_G1*262144, g1_b, nullptr, pA, ROWS9);
    k_mma<true, true,false><<<dim3(4, ROWS9/128), 256>>>(
        pA, pWT + (size_t)T_G2*262144, g2_b, nullptr, pC, ROWS9);

    // softmax + weighted sum
    k_attn_lat<<<BQ, 512>>>();

    // decoder
    k_pe_fcp<<<BQ, 128>>>(xyz_q, fc_p_w, fc_p_b, out);

    for (int i = 0; i < NBLK; i++) {
        const float* cb  = fc_c_b + (size_t)i * HID;
        const float* b0b = blk0_b + (size_t)i * HID;
        const float* b1b = blk1_b + (size_t)i * HID;
        float* cwT  = pWT + (size_t)(T_FCC + i) * 262144;
        float* b0wT = pWT + (size_t)(T_B0  + i) * 262144;
        float* b1wT = pWT + (size_t)(T_B1  + i) * 262144;
        // tmp = net + lat @ fc_c + b
        k_mma<false,true,true ><<<dim3(4, BQ/128), 256>>>(
            pLat, cwT, cb, out, pTmp, BQ);
        // h = relu(tmp) @ blk0 + b
        k_mma<true, true,false><<<dim3(4, BQ/128), 256>>>(
            pTmp, b0wT, b0b, nullptr, pH, BQ);
        // net = tmp + relu(h) @ blk1 + b
        k_mma<true, true,true ><<<dim3(4, BQ/128), 256>>>(
            pH, b1wT, b1b, pTmp, out, BQ);
    }
}

// round 11
// speedup vs baseline: 2.6340x; 1.1442x over previous
#include <cuda_runtime.h>
#include <cstdint>
#include <math.h>

#define B 2
#define NQ 4096
#define NA 2048
#define DIM 512
#define HID 512
#define NBLK 5
#define KNN 8

#define BQ    (B*NQ)        // 8192
#define ROWS8 (BQ*KNN)      // 65536
#define ROWS9 (BQ*9)        // 73728

// ---------------- static scratch (no allocations allowed) ----------------
__device__ float g_KS[B*NA*DIM];
__device__ float g_VS[B*NA*DIM];
__device__ int   g_idx[BQ*KNN];
__device__ float g_bufA[(size_t)ROWS9*DIM];
__device__ float g_bufB[(size_t)ROWS9*DIM];
__device__ float g_bufC[(size_t)ROWS9*DIM];
__device__ float g_lat[BQ*DIM];
__device__ float g_tmp[BQ*HID];
__device__ float g_h[BQ*HID];
__device__ float g_qattn[B*DIM];
__device__ float g_kgv[B*DIM];
__device__ float g_vgv[B*DIM];
__device__ float g_wt[(size_t)20*512*512];   // 20 transposed weights [N,K], tf32-rounded

#define T_KS  0
#define T_VS  1
#define T_D2  2
#define T_G1  3
#define T_G2  4
#define T_FCC 5
#define T_B0  10
#define T_B1  15

// ---------------- tf32 / cp.async helpers ----------------
__device__ __forceinline__ uint32_t to_tf32(float x) {
    uint32_t u;
    asm("cvt.rna.tf32.f32 %0, %1;" : "=r"(u) : "f"(x));
    return u;
}

__device__ __forceinline__ void cp16(float* smem_dst, const float* gsrc) {
    uint32_t s = (uint32_t)__cvta_generic_to_shared(smem_dst);
    asm volatile("cp.async.ca.shared.global [%0], [%1], 16;" :: "r"(s), "l"(gsrc) : "memory");
}
#define CP_COMMIT() asm volatile("cp.async.commit_group;" ::: "memory")
#define CP_WAIT1()  asm volatile("cp.async.wait_group 1;" ::: "memory")
#define CP_WAIT0()  asm volatile("cp.async.wait_group 0;" ::: "memory")

__device__ __forceinline__ void mma_m16n8k8(float* d, const uint32_t* a, const uint32_t* b) {
    asm volatile(
        "mma.sync.aligned.m16n8k8.row.col.f32.tf32.tf32.f32 "
        "{%0,%1,%2,%3}, {%4,%5,%6,%7}, {%8,%9}, {%0,%1,%2,%3};"
        : "+f"(d[0]), "+f"(d[1]), "+f"(d[2]), "+f"(d[3])
        : "r"(a[0]), "r"(a[1]), "r"(a[2]), "r"(a[3]),
          "r"(b[0]), "r"(b[1]));
}

// ---------------- weight transpose: [K,N] -> [N,K], tf32-rounded ----------------
__global__ void k_transpose(const float* __restrict__ wks, const float* __restrict__ wvs,
                            const float* __restrict__ d2w, const float* __restrict__ g1w,
                            const float* __restrict__ g2w, const float* __restrict__ fcc,
                            const float* __restrict__ b0w, const float* __restrict__ b1w) {
    __shared__ float t[32][33];
    int z = blockIdx.z;
    const float* src;
    if      (z == 0) src = wks;
    else if (z == 1) src = wvs;
    else if (z == 2) src = d2w;
    else if (z == 3) src = g1w;
    else if (z == 4) src = g2w;
    else if (z < 10) src = fcc + (size_t)(z - 5)  * 262144;
    else if (z < 15) src = b0w + (size_t)(z - 10) * 262144;
    else             src = b1w + (size_t)(z - 15) * 262144;
    float* dst = g_wt + (size_t)z * 262144;
    int x  = blockIdx.x * 32 + threadIdx.x;
    int y0 = blockIdx.y * 32;
#pragma unroll
    for (int i = threadIdx.y; i < 32; i += 8)
        t[i][threadIdx.x] = src[(size_t)(y0 + i) * 512 + x];
    __syncthreads();
    int xo  = blockIdx.y * 32 + threadIdx.x;
    int yo0 = blockIdx.x * 32;
#pragma unroll
    for (int i = threadIdx.y; i < 32; i += 8)
        dst[(size_t)(yo0 + i) * 512 + xo] = __uint_as_float(to_tf32(t[threadIdx.x][i]));
}

// ---------------- tf32 mma.sync GEMM, cp.async double-buffered, BK=32 ----------------
// C[M,512] = f(A[M,512]) @ WtT (+bias)(+res); Wt [N,K] row-major, already tf32.
// 128x128x32 CTA tile, 8 warps (2m x 4n), warp tile 64x32 = 4x4 m16n8k8.
// SMEM stride 36 floats (144 B): fragment banks (4m+tig) mod 32 all-distinct.
#define SROW 36
#define STAGE_F (128 * SROW)           // floats per matrix per stage
#define GEMM_SMEM (4 * STAGE_F * 4)    // bytes: 2 stages x (A+B)

template<bool RELU_A, bool HAS_BIAS, bool HAS_RES>
__global__ __launch_bounds__(256, 2)
void k_mma(const float* __restrict__ A, const float* __restrict__ Wt,
           const float* __restrict__ bias, const float* __restrict__ R,
           float* __restrict__ C, int M) {
    extern __shared__ float sm[];
    float* Asm = sm;                    // [2][128*SROW]
    float* Bsm = sm + 2 * STAGE_F;      // [2][128*SROW]
    const int tid  = threadIdx.x;
    const int lane = tid & 31;
    const int warp = tid >> 5;
    const int wm   = warp >> 2;
    const int wn   = warp & 3;
    const int gid  = lane >> 2;
    const int tig  = lane & 3;
    const int bn = blockIdx.x * 128;
    const int bm = blockIdx.y * 128;

    // cp.async mapping: 128 rows x 8 chunks of 16B; 256 thr -> 32 rows/pass, 4 passes
    const int crow = tid >> 3;          // 0..31
    const int cchk = (tid & 7) * 4;     // float offset 0..28

    float acc[4][4][4];
#pragma unroll
    for (int i = 0; i < 4; i++)
#pragma unroll
        for (int j = 0; j < 4; j++)
#pragma unroll
            for (int l = 0; l < 4; l++) acc[i][j][l] = 0.f;

    // prologue: prefetch stage 0 (k0 = 0)
#pragma unroll
    for (int p = 0; p < 4; p++) {
        const int row = crow + p * 32;
        cp16(Asm + row * SROW + cchk, A  + (size_t)(bm + row) * 512 + cchk);
        cp16(Bsm + row * SROW + cchk, Wt + (size_t)(bn + row) * 512 + cchk);
    }
    CP_COMMIT();

#pragma unroll 1
    for (int it = 0; it < 16; ++it) {
        const int st = it & 1;
        if (it + 1 < 16) {
            const int k0  = (it + 1) * 32;
            const int st2 = (it + 1) & 1;
#pragma unroll
            for (int p = 0; p < 4; p++) {
                const int row = crow + p * 32;
                cp16(Asm + st2 * STAGE_F + row * SROW + cchk,
                     A  + (size_t)(bm + row) * 512 + k0 + cchk);
                cp16(Bsm + st2 * STAGE_F + row * SROW + cchk,
                     Wt + (size_t)(bn + row) * 512 + k0 + cchk);
            }
            CP_COMMIT();
            CP_WAIT1();
        } else {
            CP_WAIT0();
        }
        __syncthreads();

        const float* As = Asm + st * STAGE_F;
        const float* Bs = Bsm + st * STAGE_F;
#pragma unroll
        for (int k8 = 0; k8 < 32; k8 += 8) {
            uint32_t af[4][4], bf[4][2];
#pragma unroll
            for (int mi = 0; mi < 4; mi++) {
                const int m = wm * 64 + mi * 16 + gid;
                float a0 = As[(m    ) * SROW + k8 + tig    ];
                float a1 = As[(m + 8) * SROW + k8 + tig    ];
                float a2 = As[(m    ) * SROW + k8 + tig + 4];
                float a3 = As[(m + 8) * SROW + k8 + tig + 4];
                if (RELU_A) {
                    a0 = fmaxf(a0, 0.f); a1 = fmaxf(a1, 0.f);
                    a2 = fmaxf(a2, 0.f); a3 = fmaxf(a3, 0.f);
                }
                af[mi][0] = to_tf32(a0); af[mi][1] = to_tf32(a1);
                af[mi][2] = to_tf32(a2); af[mi][3] = to_tf32(a3);
            }
#pragma unroll
            for (int ni = 0; ni < 4; ni++) {
                const int n = wn * 32 + ni * 8 + gid;
                bf[ni][0] = __float_as_uint(Bs[n * SROW + k8 + tig    ]);
                bf[ni][1] = __float_as_uint(Bs[n * SROW + k8 + tig + 4]);
            }
#pragma unroll
            for (int mi = 0; mi < 4; mi++)
#pragma unroll
                for (int ni = 0; ni < 4; ni++)
                    mma_m16n8k8(acc[mi][ni], af[mi], bf[ni]);
        }
        __syncthreads();
    }

    // epilogue
#pragma unroll
    for (int mi = 0; mi < 4; mi++) {
#pragma unroll
        for (int h = 0; h < 2; h++) {
            const int row = bm + wm * 64 + mi * 16 + gid + h * 8;
            float* Crow = C + (size_t)row * 512;
            const float* Rrow = R + (size_t)row * 512;
#pragma unroll
            for (int ni = 0; ni < 4; ni++) {
                const int col = bn + wn * 32 + ni * 8 + tig * 2;
                float2 v;
                v.x = acc[mi][ni][h * 2 + 0];
                v.y = acc[mi][ni][h * 2 + 1];
                if (HAS_BIAS) { v.x += bias[col]; v.y += bias[col + 1]; }
                if (HAS_RES) {
                    float2 rr = *(const float2*)(Rrow + col);
                    v.x += rr.x; v.y += rr.y;
                }
                *(float2*)(Crow + col) = v;
            }
        }
    }
}

// ---------------- tiny projection of global feats ----------------
__global__ void k_global_proj(const float* __restrict__ gf,
                              const float* __restrict__ wqs,
                              const float* __restrict__ wkg,
                              const float* __restrict__ wvg) {
    int t = blockIdx.x * blockDim.x + threadIdx.x;
    if (t >= 3 * B * DIM) return;
    int which = t / (B * DIM);
    int r = t % (B * DIM);
    int b = r / DIM, n = r % DIM;
    const float* W = (which == 0) ? wqs : (which == 1) ? wkg : wvg;
    float acc = 0.f;
    for (int k = 0; k < DIM; k++)
        acc = fmaf(gf[b * DIM + k], W[(size_t)k * DIM + n], acc);
    float* out = (which == 0) ? g_qattn : (which == 1) ? g_kgv : g_vgv;
    out[b * DIM + n] = acc;
}

// ---------------- brute-force KNN (top-8 smallest d2) ----------------
__global__ void k_knn(const float* __restrict__ xyz_q,
                      const float* __restrict__ axyz) {
    __shared__ float sx[512], sy[512], sz[512], s2[512];
    int b = blockIdx.y;
    int q = blockIdx.x * 128 + threadIdx.x;
    int bq = b * NQ + q;
    float qx = xyz_q[bq * 3 + 0];
    float qy = xyz_q[bq * 3 + 1];
    float qz = xyz_q[bq * 3 + 2];
    float q2 = qx * qx + qy * qy + qz * qz;
    float bd[KNN]; int bi[KNN];
#pragma unroll
    for (int i = 0; i < KNN; i++) { bd[i] = INFINITY; bi[i] = 0; }
    for (int t0 = 0; t0 < NA; t0 += 512) {
        __syncthreads();
        for (int j = threadIdx.x; j < 512; j += 128) {
            float ax = axyz[(b * NA + t0 + j) * 3 + 0];
            float ay = axyz[(b * NA + t0 + j) * 3 + 1];
            float az = axyz[(b * NA + t0 + j) * 3 + 2];
            sx[j] = ax; sy[j] = ay; sz[j] = az;
            s2[j] = ax * ax + ay * ay + az * az;
        }
        __syncthreads();
        for (int j = 0; j < 512; j++) {
            float d2 = q2 + s2[j] - 2.f * (qx * sx[j] + qy * sy[j] + qz * sz[j]);
            if (d2 < bd[KNN - 1]) {
                bd[KNN - 1] = d2; bi[KNN - 1] = t0 + j;
#pragma unroll
                for (int s = KNN - 1; s > 0; --s) {
                    if (bd[s] < bd[s - 1]) {
                        float td = bd[s]; bd[s] = bd[s - 1]; bd[s - 1] = td;
                        int ti = bi[s]; bi[s] = bi[s - 1]; bi[s - 1] = ti;
                    }
                }
            }
        }
    }
#pragma unroll
    for (int i = 0; i < KNN; i++) g_idx[bq * KNN + i] = bi[i];
}

// ---------------- H1 = relu(d @ d1_w + d1_b) ----------------
__global__ void k_h1(const float* __restrict__ xyz_q,
                     const float* __restrict__ axyz,
                     const float* __restrict__ d1w,
                     const float* __restrict__ d1b) {
    size_t o = (size_t)blockIdx.x * blockDim.x + threadIdx.x;
    if (o >= (size_t)ROWS8 * DIM) return;
    int f = (int)(o & 511);
    size_t r = o >> 9;
    int kk = (int)(r & 7);
    int bq = (int)(r >> 3);
    int b = bq >> 12;
    int aidx = g_idx[bq * KNN + kk];
    const float* qp = xyz_q + (size_t)bq * 3;
    const float* ap = axyz + ((size_t)b * NA + aidx) * 3;
    float dx = qp[0] - ap[0], dy = qp[1] - ap[1], dz = qp[2] - ap[2];
    float h = fmaf(dx, d1w[f], fmaf(dy, d1w[512 + f], fmaf(dz, d1w[1024 + f], d1b[f])));
    g_bufA[o] = fmaxf(h, 0.f);
}

// ---------------- build attention input X = q - k + pos ----------------
__global__ void k_buildx() {
    size_t o = (size_t)blockIdx.x * blockDim.x + threadIdx.x;
    if (o >= (size_t)ROWS9 * DIM) return;
    int f = (int)(o & 511);
    size_t r = o >> 9;
    int n = (int)(r % 9);
    int bq = (int)(r / 9);
    int b = bq >> 12;
    float v = g_qattn[b * DIM + f];
    if (n < KNN) {
        int aidx = g_idx[bq * KNN + n];
        v = v - g_KS[((size_t)b * NA + aidx) * DIM + f]
              + g_bufB[((size_t)bq * KNN + n) * DIM + f];
    } else {
        v = v - g_kgv[b * DIM + f];
    }
    g_bufC[o] = v;
}

// ---------------- per-feature softmax over 9 tokens + weighted sum ----------------
__global__ void k_attn_lat() {
    int bq = blockIdx.x;
    int f = threadIdx.x;
    int b = bq >> 12;
    __shared__ int sidx[KNN];
    if (threadIdx.x < KNN) sidx[threadIdx.x] = g_idx[bq * KNN + threadIdx.x];
    __syncthreads();
    float v[9];
#pragma unroll
    for (int n = 0; n < 9; n++)
        v[n] = g_bufC[((size_t)bq * 9 + n) * DIM + f];
    float m = v[0];
#pragma unroll
    for (int n = 1; n < 9; n++) m = fmaxf(m, v[n]);
    float s = 0.f;
#pragma unroll
    for (int n = 0; n < 9; n++) { v[n] = expf(v[n] - m); s += v[n]; }
    float inv = 1.f / s;
    float acc = 0.f;
#pragma unroll
    for (int n = 0; n < KNN; n++) {
        float val = g_VS[((size_t)b * NA + sidx[n]) * DIM + f]
                  + g_bufB[((size_t)bq * KNN + n) * DIM + f];
        acc = fmaf(v[n], val, acc);
    }
    acc = fmaf(v[8], g_vgv[b * DIM + f], acc);
    g_lat[(size_t)bq * DIM + f] = acc * inv;
}

// ---------------- NeRF positional encoding + fc_p ----------------
__global__ void k_pe_fcp(const float* __restrict__ xyz_q,
                         const float* __restrict__ fcpw,
                         const float* __restrict__ fcpb,
                         float* __restrict__ out) {
    __shared__ float pe[60];
    int bq = blockIdx.x;
    if (threadIdx.x < 60) {
        int i = threadIdx.x;
        int fr = i / 6, rem = i % 6, sc = rem / 3, c = rem % 3;
        float p = xyz_q[(size_t)bq * 3 + c];
        float a = p * ((float)(1 << fr) * 3.14159265358979f);
        pe[i] = (sc == 0) ? sinf(a) : cosf(a);
    }
    __syncthreads();
#pragma unroll
    for (int j = 0; j < 4; j++) {
        int n = j * 128 + threadIdx.x;
        float acc = fcpb[n];
#pragma unroll
        for (int i = 0; i < 60; i++)
            acc = fmaf(pe[i], fcpw[(size_t)i * 512 + n], acc);
        out[(size_t)bq * 512 + n] = acc;
    }
}

// ---------------- launch ----------------
extern "C" void kernel_launch(void* const* d_in, const int* in_sizes, int n_in,
                              void* d_out, int out_size) {
    const float* xyz_q        = (const float*)d_in[0];
    const float* global_feats = (const float*)d_in[1];
    const float* anchors_xyz  = (const float*)d_in[2];
    const float* anchors_feats= (const float*)d_in[3];
    const float* w_qs = (const float*)d_in[4];
    const float* w_ks = (const float*)d_in[5];
    const float* w_vs = (const float*)d_in[6];
    const float* w_kg = (const float*)d_in[7];
    const float* w_vg = (const float*)d_in[8];
    const float* d1_w = (const float*)d_in[9];
    const float* d1_b = (const float*)d_in[10];
    const float* d2_w = (const float*)d_in[11];
    const float* d2_b = (const float*)d_in[12];
    const float* g1_w = (const float*)d_in[13];
    const float* g1_b = (const float*)d_in[14];
    const float* g2_w = (const float*)d_in[15];
    const float* g2_b = (const float*)d_in[16];
    const float* fc_p_w = (const float*)d_in[17];
    const float* fc_p_b = (const float*)d_in[18];
    const float* fc_c_w = (const float*)d_in[19];
    const float* fc_c_b = (const float*)d_in[20];
    const float* blk0_w = (const float*)d_in[21];
    const float* blk0_b = (const float*)d_in[22];
    const float* blk1_w = (const float*)d_in[23];
    const float* blk1_b = (const float*)d_in[24];
    float* out = (float*)d_out;

    float *pKS, *pVS, *pA, *pB, *pC, *pLat, *pTmp, *pH, *pWT;
    cudaGetSymbolAddress((void**)&pKS,  g_KS);
    cudaGetSymbolAddress((void**)&pVS,  g_VS);
    cudaGetSymbolAddress((void**)&pA,   g_bufA);
    cudaGetSymbolAddress((void**)&pB,   g_bufB);
    cudaGetSymbolAddress((void**)&pC,   g_bufC);
    cudaGetSymbolAddress((void**)&pLat, g_lat);
    cudaGetSymbolAddress((void**)&pTmp, g_tmp);
    cudaGetSymbolAddress((void**)&pH,   g_h);
    cudaGetSymbolAddress((void**)&pWT,  g_wt);

    cudaFuncSetAttribute(k_mma<false,false,false>, cudaFuncAttributeMaxDynamicSharedMemorySize, GEMM_SMEM);
    cudaFuncSetAttribute(k_mma<false,true, false>, cudaFuncAttributeMaxDynamicSharedMemorySize, GEMM_SMEM);
    cudaFuncSetAttribute(k_mma<true, true, false>, cudaFuncAttributeMaxDynamicSharedMemorySize, GEMM_SMEM);
    cudaFuncSetAttribute(k_mma<false,true, true >, cudaFuncAttributeMaxDynamicSharedMemorySize, GEMM_SMEM);
    cudaFuncSetAttribute(k_mma<true, true, true >, cudaFuncAttributeMaxDynamicSharedMemorySize, GEMM_SMEM);

    // weight transposes (tf32-rounded) + global projections + KNN
    k_transpose<<<dim3(16, 16, 20), dim3(32, 8)>>>(w_ks, w_vs, d2_w, g1_w, g2_w,
                                                   fc_c_w, blk0_w, blk1_w);
    k_global_proj<<<(3 * B * DIM + 255) / 256, 256>>>(global_feats, w_qs, w_kg, w_vg);
    k_knn<<<dim3(NQ / 128, B), 128>>>(xyz_q, anchors_xyz);

    // KS / VS projections
    k_mma<false,false,false><<<dim3(4, (B*NA)/128), 256, GEMM_SMEM>>>(
        anchors_feats, pWT + (size_t)T_KS*262144, nullptr, nullptr, pKS, B*NA);
    k_mma<false,false,false><<<dim3(4, (B*NA)/128), 256, GEMM_SMEM>>>(
        anchors_feats, pWT + (size_t)T_VS*262144, nullptr, nullptr, pVS, B*NA);

    // fc_delta
    k_h1<<<(unsigned)(((size_t)ROWS8 * DIM) / 256), 256>>>(xyz_q, anchors_xyz, d1_w, d1_b);
    k_mma<false,true,false><<<dim3(4, ROWS8/128), 256, GEMM_SMEM>>>(
        pA, pWT + (size_t)T_D2*262144, d2_b, nullptr, pB, ROWS8);

    // attention MLPs
    k_buildx<<<(unsigned)(((size_t)ROWS9 * DIM) / 256), 256>>>();
    k_mma<false,true,false><<<dim3(4, ROWS9/128), 256, GEMM_SMEM>>>(
        pC, pWT + (size_t)T_G1*262144, g1_b, nullptr, pA, ROWS9);
    k_mma<true, true,false><<<dim3(4, ROWS9/128), 256, GEMM_SMEM>>>(
        pA, pWT + (size_t)T_G2*262144, g2_b, nullptr, pC, ROWS9);

    // softmax + weighted sum
    k_attn_lat<<<BQ, 512>>>();

    // decoder
    k_pe_fcp<<<BQ, 128>>>(xyz_q, fc_p_w, fc_p_b, out);

    for (int i = 0; i < NBLK; i++) {
        const float* cb  = fc_c_b + (size_t)i * HID;
        const float* b0b = blk0_b + (size_t)i * HID;
        const float* b1b = blk1_b + (size_t)i * HID;
        float* cwT  = pWT + (size_t)(T_FCC + i) * 262144;
        float* b0wT = pWT + (size_t)(T_B0  + i) * 262144;
        float* b1wT = pWT + (size_t)(T_B1  + i) * 262144;
        // tmp = net + lat @ fc_c + b
        k_mma<false,true,true ><<<dim3(4, BQ/128), 256, GEMM_SMEM>>>(
            pLat, cwT, cb, out, pTmp, BQ);
        // h = relu(tmp) @ blk0 + b
        k_mma<true, true,false><<<dim3(4, BQ/128), 256, GEMM_SMEM>>>(
            pTmp, b0wT, b0b, nullptr, pH, BQ);
        // net = tmp + relu(h) @ blk1 + b
        k_mma<true, true,true ><<<dim3(4, BQ/128), 256, GEMM_SMEM>>>(
            pH, b1wT, b1b, pTmp, out, BQ);
    }
}

// round 12
// speedup vs baseline: 2.7426x; 1.0412x over previous
#include <cuda_runtime.h>
#include <cstdint>
#include <math.h>

#define B 2
#define NQ 4096
#define NA 2048
#define DIM 512
#define HID 512
#define NBLK 5
#define KNN 8

#define BQ    (B*NQ)        // 8192
#define ROWS8 (BQ*KNN)      // 65536
#define ROWS9 (BQ*9)        // 73728
#define KVSZ  (B*NA*DIM)    // one K/V projection buffer

// ---------------- static scratch (no allocations allowed) ----------------
__device__ float g_KV[2*KVSZ];               // [0]=KS, [1]=VS (contiguous for dual GEMM)
__device__ int   g_idx[BQ*KNN];
__device__ float g_af32[KVSZ];               // anchors_feats tf32-rounded
__device__ float g_bufA[(size_t)ROWS9*DIM];
__device__ float g_bufB[(size_t)ROWS9*DIM];
__device__ float g_bufC[(size_t)ROWS9*DIM];
__device__ float g_lat[BQ*DIM];              // tf32-rounded
__device__ float g_tmp[BQ*HID];              // exact (residual)
__device__ float g_tmpR[BQ*HID];             // tf32(relu(tmp))
__device__ float g_h[BQ*HID];                // tf32(relu(h))
__device__ float g_qattn[B*DIM];
__device__ float g_kgv[B*DIM];
__device__ float g_vgv[B*DIM];
__device__ float g_wt[(size_t)20*512*512];   // 20 transposed weights [N,K], tf32-rounded

#define T_KS  0
#define T_VS  1
#define T_D2  2
#define T_G1  3
#define T_G2  4
#define T_FCC 5
#define T_B0  10
#define T_B1  15

// ---------------- tf32 / cp.async helpers ----------------
__device__ __forceinline__ uint32_t to_tf32(float x) {
    uint32_t u;
    asm("cvt.rna.tf32.f32 %0, %1;" : "=r"(u) : "f"(x));
    return u;
}
__device__ __forceinline__ float tf32f(float x) { return __uint_as_float(to_tf32(x)); }

__device__ __forceinline__ void cp16(float* smem_dst, const float* gsrc) {
    uint32_t s = (uint32_t)__cvta_generic_to_shared(smem_dst);
    asm volatile("cp.async.ca.shared.global [%0], [%1], 16;" :: "r"(s), "l"(gsrc) : "memory");
}
#define CP_COMMIT() asm volatile("cp.async.commit_group;" ::: "memory")
#define CP_WAIT1()  asm volatile("cp.async.wait_group 1;" ::: "memory")
#define CP_WAIT0()  asm volatile("cp.async.wait_group 0;" ::: "memory")

__device__ __forceinline__ void mma_m16n8k8(float* d, const uint32_t* a, const uint32_t* b) {
    asm volatile(
        "mma.sync.aligned.m16n8k8.row.col.f32.tf32.tf32.f32 "
        "{%0,%1,%2,%3}, {%4,%5,%6,%7}, {%8,%9}, {%0,%1,%2,%3};"
        : "+f"(d[0]), "+f"(d[1]), "+f"(d[2]), "+f"(d[3])
        : "r"(a[0]), "r"(a[1]), "r"(a[2]), "r"(a[3]),
          "r"(b[0]), "r"(b[1]));
}

// ---------------- weight transpose: [K,N] -> [N,K], tf32-rounded ----------------
__global__ void k_transpose(const float* __restrict__ wks, const float* __restrict__ wvs,
                            const float* __restrict__ d2w, const float* __restrict__ g1w,
                            const float* __restrict__ g2w, const float* __restrict__ fcc,
                            const float* __restrict__ b0w, const float* __restrict__ b1w) {
    __shared__ float t[32][33];
    int z = blockIdx.z;
    const float* src;
    if      (z == 0) src = wks;
    else if (z == 1) src = wvs;
    else if (z == 2) src = d2w;
    else if (z == 3) src = g1w;
    else if (z == 4) src = g2w;
    else if (z < 10) src = fcc + (size_t)(z - 5)  * 262144;
    else if (z < 15) src = b0w + (size_t)(z - 10) * 262144;
    else             src = b1w + (size_t)(z - 15) * 262144;
    float* dst = g_wt + (size_t)z * 262144;
    int x  = blockIdx.x * 32 + threadIdx.x;
    int y0 = blockIdx.y * 32;
#pragma unroll
    for (int i = threadIdx.y; i < 32; i += 8)
        t[i][threadIdx.x] = src[(size_t)(y0 + i) * 512 + x];
    __syncthreads();
    int xo  = blockIdx.y * 32 + threadIdx.x;
    int yo0 = blockIdx.x * 32;
#pragma unroll
    for (int i = threadIdx.y; i < 32; i += 8)
        dst[(size_t)(yo0 + i) * 512 + xo] = tf32f(t[threadIdx.x][i]);
}

// ---------------- round anchors_feats to tf32 ----------------
__global__ void k_round_af(const float* __restrict__ af) {
    int o = blockIdx.x * 256 + threadIdx.x;
    g_af32[o] = tf32f(af[o]);
}

// ---------------- tf32 mma.sync GEMM, cp.async double-buffered, BK=32 ----------------
// All operands in memory are pre-rounded tf32; mainloop is pure LDS+MMA.
// OUTMODE: 0 = C exact; 1 = C exact + C2 = tf32(relu(C)); 2 = C = tf32(relu(C)) only.
#define SROW 36
#define STAGE_F (128 * SROW)
#define GEMM_SMEM (4 * STAGE_F * 4)

template<bool HAS_BIAS, bool HAS_RES, int OUTMODE>
__global__ __launch_bounds__(256, 2)
void k_mma(const float* __restrict__ A, const float* __restrict__ Wt,
           const float* __restrict__ bias, const float* __restrict__ R,
           float* __restrict__ C, float* __restrict__ C2, int M,
           size_t zsW, size_t zsC) {
    extern __shared__ float sm[];
    float* Asm = sm;
    float* Bsm = sm + 2 * STAGE_F;
    Wt += (size_t)blockIdx.z * zsW;
    C  += (size_t)blockIdx.z * zsC;
    const int tid  = threadIdx.x;
    const int lane = tid & 31;
    const int warp = tid >> 5;
    const int wm   = warp >> 2;
    const int wn   = warp & 3;
    const int gid  = lane >> 2;
    const int tig  = lane & 3;
    const int bn = blockIdx.x * 128;
    const int bm = blockIdx.y * 128;

    const int crow = tid >> 3;
    const int cchk = (tid & 7) * 4;

    float acc[4][4][4];
#pragma unroll
    for (int i = 0; i < 4; i++)
#pragma unroll
        for (int j = 0; j < 4; j++)
#pragma unroll
            for (int l = 0; l < 4; l++) acc[i][j][l] = 0.f;

#pragma unroll
    for (int p = 0; p < 4; p++) {
        const int row = crow + p * 32;
        cp16(Asm + row * SROW + cchk, A  + (size_t)(bm + row) * 512 + cchk);
        cp16(Bsm + row * SROW + cchk, Wt + (size_t)(bn + row) * 512 + cchk);
    }
    CP_COMMIT();

#pragma unroll 1
    for (int it = 0; it < 16; ++it) {
        const int st = it & 1;
        if (it + 1 < 16) {
            const int k0  = (it + 1) * 32;
            const int st2 = (it + 1) & 1;
#pragma unroll
            for (int p = 0; p < 4; p++) {
                const int row = crow + p * 32;
                cp16(Asm + st2 * STAGE_F + row * SROW + cchk,
                     A  + (size_t)(bm + row) * 512 + k0 + cchk);
                cp16(Bsm + st2 * STAGE_F + row * SROW + cchk,
                     Wt + (size_t)(bn + row) * 512 + k0 + cchk);
            }
            CP_COMMIT();
            CP_WAIT1();
        } else {
            CP_WAIT0();
        }
        __syncthreads();

        const float* As = Asm + st * STAGE_F;
        const float* Bs = Bsm + st * STAGE_F;
#pragma unroll
        for (int k8 = 0; k8 < 32; k8 += 8) {
            uint32_t af[4][4], bf[4][2];
#pragma unroll
            for (int mi = 0; mi < 4; mi++) {
                const int m = wm * 64 + mi * 16 + gid;
                af[mi][0] = __float_as_uint(As[(m    ) * SROW + k8 + tig    ]);
                af[mi][1] = __float_as_uint(As[(m + 8) * SROW + k8 + tig    ]);
                af[mi][2] = __float_as_uint(As[(m    ) * SROW + k8 + tig + 4]);
                af[mi][3] = __float_as_uint(As[(m + 8) * SROW + k8 + tig + 4]);
            }
#pragma unroll
            for (int ni = 0; ni < 4; ni++) {
                const int n = wn * 32 + ni * 8 + gid;
                bf[ni][0] = __float_as_uint(Bs[n * SROW + k8 + tig    ]);
                bf[ni][1] = __float_as_uint(Bs[n * SROW + k8 + tig + 4]);
            }
#pragma unroll
            for (int mi = 0; mi < 4; mi++)
#pragma unroll
                for (int ni = 0; ni < 4; ni++)
                    mma_m16n8k8(acc[mi][ni], af[mi], bf[ni]);
        }
        __syncthreads();
    }

    // epilogue
#pragma unroll
    for (int mi = 0; mi < 4; mi++) {
#pragma unroll
        for (int h = 0; h < 2; h++) {
            const int row = bm + wm * 64 + mi * 16 + gid + h * 8;
            float* Crow = C + (size_t)row * 512;
            float* C2row = (OUTMODE == 1) ? (C2 + (size_t)row * 512) : nullptr;
            const float* Rrow = R + (size_t)row * 512;
#pragma unroll
            for (int ni = 0; ni < 4; ni++) {
                const int col = bn + wn * 32 + ni * 8 + tig * 2;
                float2 v;
                v.x = acc[mi][ni][h * 2 + 0];
                v.y = acc[mi][ni][h * 2 + 1];
                if (HAS_BIAS) { v.x += bias[col]; v.y += bias[col + 1]; }
                if (HAS_RES) {
                    float2 rr = *(const float2*)(Rrow + col);
                    v.x += rr.x; v.y += rr.y;
                }
                if (OUTMODE == 2) {
                    float2 w;
                    w.x = tf32f(fmaxf(v.x, 0.f));
                    w.y = tf32f(fmaxf(v.y, 0.f));
                    *(float2*)(Crow + col) = w;
                } else {
                    *(float2*)(Crow + col) = v;
                    if (OUTMODE == 1) {
                        float2 w;
                        w.x = tf32f(fmaxf(v.x, 0.f));
                        w.y = tf32f(fmaxf(v.y, 0.f));
                        *(float2*)(C2row + col) = w;
                    }
                }
            }
        }
    }
}

// ---------------- tiny projection of global feats ----------------
__global__ void k_global_proj(const float* __restrict__ gf,
                              const float* __restrict__ wqs,
                              const float* __restrict__ wkg,
                              const float* __restrict__ wvg) {
    int t = blockIdx.x * blockDim.x + threadIdx.x;
    if (t >= 3 * B * DIM) return;
    int which = t / (B * DIM);
    int r = t % (B * DIM);
    int b = r / DIM, n = r % DIM;
    const float* W = (which == 0) ? wqs : (which == 1) ? wkg : wvg;
    float acc = 0.f;
    for (int k = 0; k < DIM; k++)
        acc = fmaf(gf[b * DIM + k], W[(size_t)k * DIM + n], acc);
    float* out = (which == 0) ? g_qattn : (which == 1) ? g_kgv : g_vgv;
    out[b * DIM + n] = acc;
}

// ---------------- brute-force KNN (top-8 smallest d2) ----------------
__global__ void k_knn(const float* __restrict__ xyz_q,
                      const float* __restrict__ axyz) {
    __shared__ float sx[512], sy[512], sz[512], s2[512];
    int b = blockIdx.y;
    int q = blockIdx.x * 128 + threadIdx.x;
    int bq = b * NQ + q;
    float qx = xyz_q[bq * 3 + 0];
    float qy = xyz_q[bq * 3 + 1];
    float qz = xyz_q[bq * 3 + 2];
    float q2 = qx * qx + qy * qy + qz * qz;
    float bd[KNN]; int bi[KNN];
#pragma unroll
    for (int i = 0; i < KNN; i++) { bd[i] = INFINITY; bi[i] = 0; }
    for (int t0 = 0; t0 < NA; t0 += 512) {
        __syncthreads();
        for (int j = threadIdx.x; j < 512; j += 128) {
            float ax = axyz[(b * NA + t0 + j) * 3 + 0];
            float ay = axyz[(b * NA + t0 + j) * 3 + 1];
            float az = axyz[(b * NA + t0 + j) * 3 + 2];
            sx[j] = ax; sy[j] = ay; sz[j] = az;
            s2[j] = ax * ax + ay * ay + az * az;
        }
        __syncthreads();
        for (int j = 0; j < 512; j++) {
            float d2 = q2 + s2[j] - 2.f * (qx * sx[j] + qy * sy[j] + qz * sz[j]);
            if (d2 < bd[KNN - 1]) {
                bd[KNN - 1] = d2; bi[KNN - 1] = t0 + j;
#pragma unroll
                for (int s = KNN - 1; s > 0; --s) {
                    if (bd[s] < bd[s - 1]) {
                        float td = bd[s]; bd[s] = bd[s - 1]; bd[s - 1] = td;
                        int ti = bi[s]; bi[s] = bi[s - 1]; bi[s - 1] = ti;
                    }
                }
            }
        }
    }
#pragma unroll
    for (int i = 0; i < KNN; i++) g_idx[bq * KNN + i] = bi[i];
}

// ---------------- H1 = tf32(relu(d @ d1_w + d1_b)) ----------------
__global__ void k_h1(const float* __restrict__ xyz_q,
                     const float* __restrict__ axyz,
                     const float* __restrict__ d1w,
                     const float* __restrict__ d1b) {
    size_t o = (size_t)blockIdx.x * blockDim.x + threadIdx.x;
    if (o >= (size_t)ROWS8 * DIM) return;
    int f = (int)(o & 511);
    size_t r = o >> 9;
    int kk = (int)(r & 7);
    int bq = (int)(r >> 3);
    int b = bq >> 12;
    int aidx = g_idx[bq * KNN + kk];
    const float* qp = xyz_q + (size_t)bq * 3;
    const float* ap = axyz + ((size_t)b * NA + aidx) * 3;
    float dx = qp[0] - ap[0], dy = qp[1] - ap[1], dz = qp[2] - ap[2];
    float h = fmaf(dx, d1w[f], fmaf(dy, d1w[512 + f], fmaf(dz, d1w[1024 + f], d1b[f])));
    g_bufA[o] = tf32f(fmaxf(h, 0.f));
}

// ---------------- build attention input X = tf32(q - k + pos) ----------------
__global__ void k_buildx() {
    size_t o = (size_t)blockIdx.x * blockDim.x + threadIdx.x;
    if (o >= (size_t)ROWS9 * DIM) return;
    int f = (int)(o & 511);
    size_t r = o >> 9;
    int n = (int)(r % 9);
    int bq = (int)(r / 9);
    int b = bq >> 12;
    float v = g_qattn[b * DIM + f];
    if (n < KNN) {
        int aidx = g_idx[bq * KNN + n];
        v = v - g_KV[((size_t)b * NA + aidx) * DIM + f]
              + g_bufB[((size_t)bq * KNN + n) * DIM + f];
    } else {
        v = v - g_kgv[b * DIM + f];
    }
    g_bufC[o] = tf32f(v);
}

// ---------------- per-feature softmax over 9 tokens + weighted sum ----------------
__global__ void k_attn_lat() {
    int bq = blockIdx.x;
    int f = threadIdx.x;
    int b = bq >> 12;
    __shared__ int sidx[KNN];
    if (threadIdx.x < KNN) sidx[threadIdx.x] = g_idx[bq * KNN + threadIdx.x];
    __syncthreads();
    float v[9];
#pragma unroll
    for (int n = 0; n < 9; n++)
        v[n] = g_bufC[((size_t)bq * 9 + n) * DIM + f];
    float m = v[0];
#pragma unroll
    for (int n = 1; n < 9; n++) m = fmaxf(m, v[n]);
    float s = 0.f;
#pragma unroll
    for (int n = 0; n < 9; n++) { v[n] = expf(v[n] - m); s += v[n]; }
    float inv = 1.f / s;
    float acc = 0.f;
#pragma unroll
    for (int n = 0; n < KNN; n++) {
        float val = g_KV[KVSZ + ((size_t)b * NA + sidx[n]) * DIM + f]
                  + g_bufB[((size_t)bq * KNN + n) * DIM + f];
        acc = fmaf(v[n], val, acc);
    }
    acc = fmaf(v[8], g_vgv[b * DIM + f], acc);
    g_lat[(size_t)bq * DIM + f] = tf32f(acc * inv);
}

// ---------------- NeRF positional encoding + fc_p ----------------
__global__ void k_pe_fcp(const float* __restrict__ xyz_q,
                         const float* __restrict__ fcpw,
                         const float* __restrict__ fcpb,
                         float* __restrict__ out) {
    __shared__ float pe[60];
    int bq = blockIdx.x;
    if (threadIdx.x < 60) {
        int i = threadIdx.x;
        int fr = i / 6, rem = i % 6, sc = rem / 3, c = rem % 3;
        float p = xyz_q[(size_t)bq * 3 + c];
        float a = p * ((float)(1 << fr) * 3.14159265358979f);
        pe[i] = (sc == 0) ? sinf(a) : cosf(a);
    }
    __syncthreads();
#pragma unroll
    for (int j = 0; j < 4; j++) {
        int n = j * 128 + threadIdx.x;
        float acc = fcpb[n];
#pragma unroll
        for (int i = 0; i < 60; i++)
            acc = fmaf(pe[i], fcpw[(size_t)i * 512 + n], acc);
        out[(size_t)bq * 512 + n] = acc;
    }
}

// ---------------- launch ----------------
extern "C" void kernel_launch(void* const* d_in, const int* in_sizes, int n_in,
                              void* d_out, int out_size) {
    const float* xyz_q        = (const float*)d_in[0];
    const float* global_feats = (const float*)d_in[1];
    const float* anchors_xyz  = (const float*)d_in[2];
    const float* anchors_feats= (const float*)d_in[3];
    const float* w_qs = (const float*)d_in[4];
    const float* w_ks = (const float*)d_in[5];
    const float* w_vs = (const float*)d_in[6];
    const float* w_kg = (const float*)d_in[7];
    const float* w_vg = (const float*)d_in[8];
    const float* d1_w = (const float*)d_in[9];
    const float* d1_b = (const float*)d_in[10];
    const float* d2_w = (const float*)d_in[11];
    const float* d2_b = (const float*)d_in[12];
    const float* g1_w = (const float*)d_in[13];
    const float* g1_b = (const float*)d_in[14];
    const float* g2_w = (const float*)d_in[15];
    const float* g2_b = (const float*)d_in[16];
    const float* fc_p_w = (const float*)d_in[17];
    const float* fc_p_b = (const float*)d_in[18];
    const float* fc_c_w = (const float*)d_in[19];
    const float* fc_c_b = (const float*)d_in[20];
    const float* blk0_w = (const float*)d_in[21];
    const float* blk0_b = (const float*)d_in[22];
    const float* blk1_w = (const float*)d_in[23];
    const float* blk1_b = (const float*)d_in[24];
    float* out = (float*)d_out;

    float *pKV, *pAF, *pA, *pB, *pC, *pLat, *pTmp, *pTmpR, *pH, *pWT;
    cudaGetSymbolAddress((void**)&pKV,   g_KV);
    cudaGetSymbolAddress((void**)&pAF,   g_af32);
    cudaGetSymbolAddress((void**)&pA,    g_bufA);
    cudaGetSymbolAddress((void**)&pB,    g_bufB);
    cudaGetSymbolAddress((void**)&pC,    g_bufC);
    cudaGetSymbolAddress((void**)&pLat,  g_lat);
    cudaGetSymbolAddress((void**)&pTmp,  g_tmp);
    cudaGetSymbolAddress((void**)&pTmpR, g_tmpR);
    cudaGetSymbolAddress((void**)&pH,    g_h);
    cudaGetSymbolAddress((void**)&pWT,   g_wt);

    cudaFuncSetAttribute(k_mma<false,false,0>, cudaFuncAttributeMaxDynamicSharedMemorySize, GEMM_SMEM);
    cudaFuncSetAttribute(k_mma<true, false,0>, cudaFuncAttributeMaxDynamicSharedMemorySize, GEMM_SMEM);
    cudaFuncSetAttribute(k_mma<true, false,2>, cudaFuncAttributeMaxDynamicSharedMemorySize, GEMM_SMEM);
    cudaFuncSetAttribute(k_mma<true, true, 1>, cudaFuncAttributeMaxDynamicSharedMemorySize, GEMM_SMEM);
    cudaFuncSetAttribute(k_mma<true, true, 0>, cudaFuncAttributeMaxDynamicSharedMemorySize, GEMM_SMEM);

    // prep: transposed tf32 weights, rounded anchors_feats, projections, KNN
    k_transpose<<<dim3(16, 16, 20), dim3(32, 8)>>>(w_ks, w_vs, d2_w, g1_w, g2_w,
                                                   fc_c_w, blk0_w, blk1_w);
    k_round_af<<<KVSZ / 256, 256>>>(anchors_feats);
    k_global_proj<<<(3 * B * DIM + 255) / 256, 256>>>(global_feats, w_qs, w_kg, w_vg);
    k_knn<<<dim3(NQ / 128, B), 128>>>(xyz_q, anchors_xyz);

    // KS + VS projections in ONE launch (z picks weight/output)
    k_mma<false,false,0><<<dim3(4, (B*NA)/128, 2), 256, GEMM_SMEM>>>(
        pAF, pWT + (size_t)T_KS*262144, nullptr, nullptr, pKV, nullptr, B*NA,
        262144, (size_t)KVSZ);

    // fc_delta
    k_h1<<<(unsigned)(((size_t)ROWS8 * DIM) / 256), 256>>>(xyz_q, anchors_xyz, d1_w, d1_b);
    k_mma<true,false,0><<<dim3(4, ROWS8/128), 256, GEMM_SMEM>>>(
        pA, pWT + (size_t)T_D2*262144, d2_b, nullptr, pB, nullptr, ROWS8, 0, 0);

    // attention MLPs: g1 writes tf32(relu(T_pre)); g2 writes G exact
    k_buildx<<<(unsigned)(((size_t)ROWS9 * DIM) / 256), 256>>>();
    k_mma<true,false,2><<<dim3(4, ROWS9/128), 256, GEMM_SMEM>>>(
        pC, pWT + (size_t)T_G1*262144, g1_b, nullptr, pA, nullptr, ROWS9, 0, 0);
    k_mma<true,false,0><<<dim3(4, ROWS9/128), 256, GEMM_SMEM>>>(
        pA, pWT + (size_t)T_G2*262144, g2_b, nullptr, pC, nullptr, ROWS9, 0, 0);

    // softmax + weighted sum -> lat (tf32)
    k_attn_lat<<<BQ, 512>>>();

    // decoder
    k_pe_fcp<<<BQ, 128>>>(xyz_q, fc_p_w, fc_p_b, out);

    for (int i = 0; i < NBLK; i++) {
        const float* cb  = fc_c_b + (size_t)i * HID;
        const float* b0b = blk0_b + (size_t)i * HID;
        const float* b1b = blk1_b + (size_t)i * HID;
        float* cwT  = pWT + (size_t)(T_FCC + i) * 262144;
        float* b0wT = pWT + (size_t)(T_B0  + i) * 262144;
        float* b1wT = pWT + (size_t)(T_B1  + i) * 262144;
        // tmp = net + lat @ fc_c + b   (exact) ; tmpR = tf32(relu(tmp))
        k_mma<true,true,1><<<dim3(4, BQ/128), 256, GEMM_SMEM>>>(
            pLat, cwT, cb, out, pTmp, pTmpR, BQ, 0, 0);
        // h = tf32(relu(relu(tmp) @ blk0 + b))
        k_mma<true,false,2><<<dim3(4, BQ/128), 256, GEMM_SMEM>>>(
            pTmpR, b0wT, b0b, nullptr, pH, nullptr, BQ, 0, 0);
        // net = tmp + relu(h) @ blk1 + b   (exact)
        k_mma<true,true,0><<<dim3(4, BQ/128), 256, GEMM_SMEM>>>(
            pH, b1wT, b1b, pTmp, out, nullptr, BQ, 0, 0);
    }
}

// round 13
// speedup vs baseline: 3.1124x; 1.1349x over previous
#include <cuda_runtime.h>
#include <cstdint>
#include <math.h>

#define B 2
#define NQ 4096
#define NA 2048
#define DIM 512
#define HID 512
#define NBLK 5
#define KNN 8
#define NCHUNK 8
#define CHUNK (NA/NCHUNK)   // 256

#define BQ    (B*NQ)        // 8192
#define ROWS8 (BQ*KNN)      // 65536
#define ROWS9 (BQ*9)        // 73728
#define KVSZ  (B*NA*DIM)

// ---------------- static scratch (no allocations allowed) ----------------
__device__ float g_KV[2*KVSZ];               // [0]=KS, [1]=VS
__device__ int   g_idx[BQ*KNN];
__device__ float g_knn_d[BQ*NCHUNK*KNN];
__device__ int   g_knn_i[BQ*NCHUNK*KNN];
__device__ float g_af32[KVSZ];
__device__ float g_bufA[(size_t)ROWS9*DIM];
__device__ float g_bufB[(size_t)ROWS9*DIM];
__device__ float g_bufC[(size_t)ROWS9*DIM];
__device__ float g_lat[BQ*DIM];
__device__ float g_tmp[BQ*HID];
__device__ float g_tmpR[BQ*HID];
__device__ float g_h[BQ*HID];
__device__ float g_qattn[B*DIM];
__device__ float g_kgv[B*DIM];
__device__ float g_vgv[B*DIM];
__device__ float g_wt[(size_t)20*512*512];

#define T_KS  0
#define T_VS  1
#define T_D2  2
#define T_G1  3
#define T_G2  4
#define T_FCC 5
#define T_B0  10
#define T_B1  15

// ---------------- tf32 / cp.async helpers ----------------
__device__ __forceinline__ uint32_t to_tf32(float x) {
    uint32_t u;
    asm("cvt.rna.tf32.f32 %0, %1;" : "=r"(u) : "f"(x));
    return u;
}
__device__ __forceinline__ float tf32f(float x) { return __uint_as_float(to_tf32(x)); }

__device__ __forceinline__ void cp16(float* smem_dst, const float* gsrc) {
    uint32_t s = (uint32_t)__cvta_generic_to_shared(smem_dst);
    asm volatile("cp.async.ca.shared.global [%0], [%1], 16;" :: "r"(s), "l"(gsrc) : "memory");
}
#define CP_COMMIT() asm volatile("cp.async.commit_group;" ::: "memory")
#define CP_WAIT1()  asm volatile("cp.async.wait_group 1;" ::: "memory")
#define CP_WAIT0()  asm volatile("cp.async.wait_group 0;" ::: "memory")

__device__ __forceinline__ void mma_m16n8k8(float* d, const uint32_t* a, const uint32_t* b) {
    asm volatile(
        "mma.sync.aligned.m16n8k8.row.col.f32.tf32.tf32.f32 "
        "{%0,%1,%2,%3}, {%4,%5,%6,%7}, {%8,%9}, {%0,%1,%2,%3};"
        : "+f"(d[0]), "+f"(d[1]), "+f"(d[2]), "+f"(d[3])
        : "r"(a[0]), "r"(a[1]), "r"(a[2]), "r"(a[3]),
          "r"(b[0]), "r"(b[1]));
}

// ---------------- weight transpose: [K,N] -> [N,K], tf32-rounded ----------------
__global__ void k_transpose(const float* __restrict__ wks, const float* __restrict__ wvs,
                            const float* __restrict__ d2w, const float* __restrict__ g1w,
                            const float* __restrict__ g2w, const float* __restrict__ fcc,
                            const float* __restrict__ b0w, const float* __restrict__ b1w) {
    __shared__ float t[32][33];
    int z = blockIdx.z;
    const float* src;
    if      (z == 0) src = wks;
    else if (z == 1) src = wvs;
    else if (z == 2) src = d2w;
    else if (z == 3) src = g1w;
    else if (z == 4) src = g2w;
    else if (z < 10) src = fcc + (size_t)(z - 5)  * 262144;
    else if (z < 15) src = b0w + (size_t)(z - 10) * 262144;
    else             src = b1w + (size_t)(z - 15) * 262144;
    float* dst = g_wt + (size_t)z * 262144;
    int x  = blockIdx.x * 32 + threadIdx.x;
    int y0 = blockIdx.y * 32;
#pragma unroll
    for (int i = threadIdx.y; i < 32; i += 8)
        t[i][threadIdx.x] = src[(size_t)(y0 + i) * 512 + x];
    __syncthreads();
    int xo  = blockIdx.y * 32 + threadIdx.x;
    int yo0 = blockIdx.x * 32;
#pragma unroll
    for (int i = threadIdx.y; i < 32; i += 8)
        dst[(size_t)(yo0 + i) * 512 + xo] = tf32f(t[threadIdx.x][i]);
}

// ---------------- round anchors_feats to tf32 (float4) ----------------
__global__ void k_round_af(const float* __restrict__ af) {
    int o = blockIdx.x * 256 + threadIdx.x;
    float4 v = *(const float4*)(af + o * 4);
    float4 w;
    w.x = tf32f(v.x); w.y = tf32f(v.y); w.z = tf32f(v.z); w.w = tf32f(v.w);
    *(float4*)(g_af32 + o * 4) = w;
}

// ---------------- tf32 mma.sync GEMM, cp.async double-buffered, BK=32 ----------------
#define SROW 36
#define STAGE_F (128 * SROW)
#define GEMM_SMEM (4 * STAGE_F * 4)

template<bool HAS_BIAS, bool HAS_RES, int OUTMODE>
__global__ __launch_bounds__(256, 2)
void k_mma(const float* __restrict__ A, const float* __restrict__ Wt,
           const float* __restrict__ bias, const float* __restrict__ R,
           float* __restrict__ C, float* __restrict__ C2, int M,
           size_t zsW, size_t zsC) {
    extern __shared__ float sm[];
    float* Asm = sm;
    float* Bsm = sm + 2 * STAGE_F;
    Wt += (size_t)blockIdx.z * zsW;
    C  += (size_t)blockIdx.z * zsC;
    const int tid  = threadIdx.x;
    const int lane = tid & 31;
    const int warp = tid >> 5;
    const int wm   = warp >> 2;
    const int wn   = warp & 3;
    const int gid  = lane >> 2;
    const int tig  = lane & 3;
    const int bn = blockIdx.x * 128;
    const int bm = blockIdx.y * 128;

    const int crow = tid >> 3;
    const int cchk = (tid & 7) * 4;

    float acc[4][4][4];
#pragma unroll
    for (int i = 0; i < 4; i++)
#pragma unroll
        for (int j = 0; j < 4; j++)
#pragma unroll
            for (int l = 0; l < 4; l++) acc[i][j][l] = 0.f;

#pragma unroll
    for (int p = 0; p < 4; p++) {
        const int row = crow + p * 32;
        cp16(Asm + row * SROW + cchk, A  + (size_t)(bm + row) * 512 + cchk);
        cp16(Bsm + row * SROW + cchk, Wt + (size_t)(bn + row) * 512 + cchk);
    }
    CP_COMMIT();

#pragma unroll 1
    for (int it = 0; it < 16; ++it) {
        const int st = it & 1;
        if (it + 1 < 16) {
            const int k0  = (it + 1) * 32;
            const int st2 = (it + 1) & 1;
#pragma unroll
            for (int p = 0; p < 4; p++) {
                const int row = crow + p * 32;
                cp16(Asm + st2 * STAGE_F + row * SROW + cchk,
                     A  + (size_t)(bm + row) * 512 + k0 + cchk);
                cp16(Bsm + st2 * STAGE_F + row * SROW + cchk,
                     Wt + (size_t)(bn + row) * 512 + k0 + cchk);
            }
            CP_COMMIT();
            CP_WAIT1();
        } else {
            CP_WAIT0();
        }
        __syncthreads();

        const float* As = Asm + st * STAGE_F;
        const float* Bs = Bsm + st * STAGE_F;
#pragma unroll
        for (int k8 = 0; k8 < 32; k8 += 8) {
            uint32_t af[4][4], bf[4][2];
#pragma unroll
            for (int mi = 0; mi < 4; mi++) {
                const int m = wm * 64 + mi * 16 + gid;
                af[mi][0] = __float_as_uint(As[(m    ) * SROW + k8 + tig    ]);
                af[mi][1] = __float_as_uint(As[(m + 8) * SROW + k8 + tig    ]);
                af[mi][2] = __float_as_uint(As[(m    ) * SROW + k8 + tig + 4]);
                af[mi][3] = __float_as_uint(As[(m + 8) * SROW + k8 + tig + 4]);
            }
#pragma unroll
            for (int ni = 0; ni < 4; ni++) {
                const int n = wn * 32 + ni * 8 + gid;
                bf[ni][0] = __float_as_uint(Bs[n * SROW + k8 + tig    ]);
                bf[ni][1] = __float_as_uint(Bs[n * SROW + k8 + tig + 4]);
            }
#pragma unroll
            for (int mi = 0; mi < 4; mi++)
#pragma unroll
                for (int ni = 0; ni < 4; ni++)
                    mma_m16n8k8(acc[mi][ni], af[mi], bf[ni]);
        }
        __syncthreads();
    }

    // epilogue
#pragma unroll
    for (int mi = 0; mi < 4; mi++) {
#pragma unroll
        for (int h = 0; h < 2; h++) {
            const int row = bm + wm * 64 + mi * 16 + gid + h * 8;
            float* Crow = C + (size_t)row * 512;
            float* C2row = (OUTMODE == 1) ? (C2 + (size_t)row * 512) : nullptr;
            const float* Rrow = R + (size_t)row * 512;
#pragma unroll
            for (int ni = 0; ni < 4; ni++) {
                const int col = bn + wn * 32 + ni * 8 + tig * 2;
                float2 v;
                v.x = acc[mi][ni][h * 2 + 0];
                v.y = acc[mi][ni][h * 2 + 1];
                if (HAS_BIAS) { v.x += bias[col]; v.y += bias[col + 1]; }
                if (HAS_RES) {
                    float2 rr = *(const float2*)(Rrow + col);
                    v.x += rr.x; v.y += rr.y;
                }
                if (OUTMODE == 2) {
                    float2 w;
                    w.x = tf32f(fmaxf(v.x, 0.f));
                    w.y = tf32f(fmaxf(v.y, 0.f));
                    *(float2*)(Crow + col) = w;
                } else {
                    *(float2*)(Crow + col) = v;
                    if (OUTMODE == 1) {
                        float2 w;
                        w.x = tf32f(fmaxf(v.x, 0.f));
                        w.y = tf32f(fmaxf(v.y, 0.f));
                        *(float2*)(C2row + col) = w;
                    }
                }
            }
        }
    }
}

// ---------------- tiny projection of global feats ----------------
__global__ void k_global_proj(const float* __restrict__ gf,
                              const float* __restrict__ wqs,
                              const float* __restrict__ wkg,
                              const float* __restrict__ wvg) {
    int t = blockIdx.x * blockDim.x + threadIdx.x;
    if (t >= 3 * B * DIM) return;
    int which = t / (B * DIM);
    int r = t % (B * DIM);
    int b = r / DIM, n = r % DIM;
    const float* W = (which == 0) ? wqs : (which == 1) ? wkg : wvg;
    float acc = 0.f;
    for (int k = 0; k < DIM; k++)
        acc = fmaf(gf[b * DIM + k], W[(size_t)k * DIM + n], acc);
    float* out = (which == 0) ? g_qattn : (which == 1) ? g_kgv : g_vgv;
    out[b * DIM + n] = acc;
}

// ---------------- KNN phase 1: per-chunk top-8 (grid 32 x B x NCHUNK) ----------------
__global__ void k_knn_part(const float* __restrict__ xyz_q,
                           const float* __restrict__ axyz) {
    __shared__ float sx[CHUNK], sy[CHUNK], sz[CHUNK], s2[CHUNK];
    int b = blockIdx.y, z = blockIdx.z;
    int q = blockIdx.x * 128 + threadIdx.x;
    int bq = b * NQ + q;
    float qx = xyz_q[bq * 3 + 0];
    float qy = xyz_q[bq * 3 + 1];
    float qz = xyz_q[bq * 3 + 2];
    float q2 = qx * qx + qy * qy + qz * qz;
    for (int j = threadIdx.x; j < CHUNK; j += 128) {
        const float* ap = axyz + ((size_t)(b * NA + z * CHUNK + j)) * 3;
        float ax = ap[0], ay = ap[1], az = ap[2];
        sx[j] = ax; sy[j] = ay; sz[j] = az;
        s2[j] = ax * ax + ay * ay + az * az;
    }
    __syncthreads();
    float bd[KNN]; int bi[KNN];
#pragma unroll
    for (int i = 0; i < KNN; i++) { bd[i] = INFINITY; bi[i] = 0; }
    for (int j = 0; j < CHUNK; j++) {
        float d2 = q2 + s2[j] - 2.f * (qx * sx[j] + qy * sy[j] + qz * sz[j]);
        if (d2 < bd[KNN - 1]) {
            bd[KNN - 1] = d2; bi[KNN - 1] = z * CHUNK + j;
#pragma unroll
            for (int s = KNN - 1; s > 0; --s) {
                if (bd[s] < bd[s - 1]) {
                    float td = bd[s]; bd[s] = bd[s - 1]; bd[s - 1] = td;
                    int ti = bi[s]; bi[s] = bi[s - 1]; bi[s - 1] = ti;
                }
            }
        }
    }
    size_t base = ((size_t)bq * NCHUNK + z) * KNN;
#pragma unroll
    for (int i = 0; i < KNN; i++) { g_knn_d[base + i] = bd[i]; g_knn_i[base + i] = bi[i]; }
}

// ---------------- KNN phase 2: merge 8 sorted chunk-lists (ascending z => stable) ----
__global__ void k_knn_merge() {
    int bq = blockIdx.x * 256 + threadIdx.x;
    float bd[KNN]; int bi[KNN];
#pragma unroll
    for (int i = 0; i < KNN; i++) { bd[i] = INFINITY; bi[i] = 0; }
    for (int z = 0; z < NCHUNK; z++) {
        size_t base = ((size_t)bq * NCHUNK + z) * KNN;
#pragma unroll
        for (int c = 0; c < KNN; c++) {
            float d = g_knn_d[base + c];
            if (!(d < bd[KNN - 1])) break;   // chunk list sorted ascending
            int idx = g_knn_i[base + c];
            bd[KNN - 1] = d; bi[KNN - 1] = idx;
#pragma unroll
            for (int s = KNN - 1; s > 0; --s) {
                if (bd[s] < bd[s - 1]) {
                    float td = bd[s]; bd[s] = bd[s - 1]; bd[s - 1] = td;
                    int ti = bi[s]; bi[s] = bi[s - 1]; bi[s - 1] = ti;
                }
            }
        }
    }
#pragma unroll
    for (int i = 0; i < KNN; i++) g_idx[bq * KNN + i] = bi[i];
}

// ---------------- H1 = tf32(relu(d @ d1_w + d1_b)), float4 ----------------
__global__ void k_h1(const float* __restrict__ xyz_q,
                     const float* __restrict__ axyz,
                     const float* __restrict__ d1w,
                     const float* __restrict__ d1b) {
    size_t t = (size_t)blockIdx.x * 256 + threadIdx.x;   // ROWS8*128 threads
    int f = (int)(t & 127) * 4;
    size_t r = t >> 7;
    int kk = (int)(r & 7);
    int bq = (int)(r >> 3);
    int b = bq >> 12;
    int aidx = g_idx[bq * KNN + kk];
    const float* qp = xyz_q + (size_t)bq * 3;
    const float* ap = axyz + ((size_t)b * NA + aidx) * 3;
    float dx = qp[0] - ap[0], dy = qp[1] - ap[1], dz = qp[2] - ap[2];
    float4 w0 = *(const float4*)(d1w + f);
    float4 w1 = *(const float4*)(d1w + 512 + f);
    float4 w2 = *(const float4*)(d1w + 1024 + f);
    float4 bb = *(const float4*)(d1b + f);
    float4 o;
    o.x = tf32f(fmaxf(fmaf(dx, w0.x, fmaf(dy, w1.x, fmaf(dz, w2.x, bb.x))), 0.f));
    o.y = tf32f(fmaxf(fmaf(dx, w0.y, fmaf(dy, w1.y, fmaf(dz, w2.y, bb.y))), 0.f));
    o.z = tf32f(fmaxf(fmaf(dx, w0.z, fmaf(dy, w1.z, fmaf(dz, w2.z, bb.z))), 0.f));
    o.w = tf32f(fmaxf(fmaf(dx, w0.w, fmaf(dy, w1.w, fmaf(dz, w2.w, bb.w))), 0.f));
    *(float4*)(g_bufA + r * 512 + f) = o;
}

// ---------------- build attention input X = tf32(q - k + pos), float4 ----------------
__global__ void k_buildx() {
    size_t t = (size_t)blockIdx.x * 256 + threadIdx.x;   // ROWS9*128 threads
    int f = (int)(t & 127) * 4;
    size_t r = t >> 7;
    int n = (int)(r % 9);
    int bq = (int)(r / 9);
    int b = bq >> 12;
    float4 qv = *(const float4*)(g_qattn + b * DIM + f);
    float4 o;
    if (n < KNN) {
        int aidx = g_idx[bq * KNN + n];
        float4 kv = *(const float4*)(g_KV + ((size_t)b * NA + aidx) * DIM + f);
        float4 pe = *(const float4*)(g_bufB + ((size_t)bq * KNN + n) * DIM + f);
        o.x = tf32f(qv.x - kv.x + pe.x);
        o.y = tf32f(qv.y - kv.y + pe.y);
        o.z = tf32f(qv.z - kv.z + pe.z);
        o.w = tf32f(qv.w - kv.w + pe.w);
    } else {
        float4 kg = *(const float4*)(g_kgv + b * DIM + f);
        o.x = tf32f(qv.x - kg.x);
        o.y = tf32f(qv.y - kg.y);
        o.z = tf32f(qv.z - kg.z);
        o.w = tf32f(qv.w - kg.w);
    }
    *(float4*)(g_bufC + r * 512 + f) = o;
}

// ---------------- per-feature softmax over 9 tokens + weighted sum ----------------
__global__ void k_attn_lat() {
    int bq = blockIdx.x;
    int f = threadIdx.x;
    int b = bq >> 12;
    __shared__ int sidx[KNN];
    if (threadIdx.x < KNN) sidx[threadIdx.x] = g_idx[bq * KNN + threadIdx.x];
    __syncthreads();
    float v[9];
#pragma unroll
    for (int n = 0; n < 9; n++)
        v[n] = g_bufC[((size_t)bq * 9 + n) * DIM + f];
    float m = v[0];
#pragma unroll
    for (int n = 1; n < 9; n++) m = fmaxf(m, v[n]);
    float s = 0.f;
#pragma unroll
    for (int n = 0; n < 9; n++) { v[n] = expf(v[n] - m); s += v[n]; }
    float inv = 1.f / s;
    float acc = 0.f;
#pragma unroll
    for (int n = 0; n < KNN; n++) {
        float val = g_KV[KVSZ + ((size_t)b * NA + sidx[n]) * DIM + f]
                  + g_bufB[((size_t)bq * KNN + n) * DIM + f];
        acc = fmaf(v[n], val, acc);
    }
    acc = fmaf(v[8], g_vgv[b * DIM + f], acc);
    g_lat[(size_t)bq * DIM + f] = tf32f(acc * inv);
}

// ---------------- NeRF positional encoding + fc_p ----------------
__global__ void k_pe_fcp(const float* __restrict__ xyz_q,
                         const float* __restrict__ fcpw,
                         const float* __restrict__ fcpb,
                         float* __restrict__ out) {
    __shared__ float pe[60];
    int bq = blockIdx.x;
    if (threadIdx.x < 60) {
        int i = threadIdx.x;
        int fr = i / 6, rem = i % 6, sc = rem / 3, c = rem % 3;
        float p = xyz_q[(size_t)bq * 3 + c];
        float a = p * ((float)(1 << fr) * 3.14159265358979f);
        pe[i] = (sc == 0) ? sinf(a) : cosf(a);
    }
    __syncthreads();
#pragma unroll
    for (int j = 0; j < 4; j++) {
        int n = j * 128 + threadIdx.x;
        float acc = fcpb[n];
#pragma unroll
        for (int i = 0; i < 60; i++)
            acc = fmaf(pe[i], fcpw[(size_t)i * 512 + n], acc);
        out[(size_t)bq * 512 + n] = acc;
    }
}

// ---------------- launch ----------------
extern "C" void kernel_launch(void* const* d_in, const int* in_sizes, int n_in,
                              void* d_out, int out_size) {
    const float* xyz_q        = (const float*)d_in[0];
    const float* global_feats = (const float*)d_in[1];
    const float* anchors_xyz  = (const float*)d_in[2];
    const float* anchors_feats= (const float*)d_in[3];
    const float* w_qs = (const float*)d_in[4];
    const float* w_ks = (const float*)d_in[5];
    const float* w_vs = (const float*)d_in[6];
    const float* w_kg = (const float*)d_in[7];
    const float* w_vg = (const float*)d_in[8];
    const float* d1_w = (const float*)d_in[9];
    const float* d1_b = (const float*)d_in[10];
    const float* d2_w = (const float*)d_in[11];
    const float* d2_b = (const float*)d_in[12];
    const float* g1_w = (const float*)d_in[13];
    const float* g1_b = (const float*)d_in[14];
    const float* g2_w = (const float*)d_in[15];
    const float* g2_b = (const float*)d_in[16];
    const float* fc_p_w = (const float*)d_in[17];
    const float* fc_p_b = (const float*)d_in[18];
    const float* fc_c_w = (const float*)d_in[19];
    const float* fc_c_b = (const float*)d_in[20];
    const float* blk0_w = (const float*)d_in[21];
    const float* blk0_b = (const float*)d_in[22];
    const float* blk1_w = (const float*)d_in[23];
    const float* blk1_b = (const float*)d_in[24];
    float* out = (float*)d_out;

    float *pKV, *pAF, *pA, *pB, *pC, *pLat, *pTmp, *pTmpR, *pH, *pWT;
    cudaGetSymbolAddress((void**)&pKV,   g_KV);
    cudaGetSymbolAddress((void**)&pAF,   g_af32);
    cudaGetSymbolAddress((void**)&pA,    g_bufA);
    cudaGetSymbolAddress((void**)&pB,    g_bufB);
    cudaGetSymbolAddress((void**)&pC,    g_bufC);
    cudaGetSymbolAddress((void**)&pLat,  g_lat);
    cudaGetSymbolAddress((void**)&pTmp,  g_tmp);
    cudaGetSymbolAddress((void**)&pTmpR, g_tmpR);
    cudaGetSymbolAddress((void**)&pH,    g_h);
    cudaGetSymbolAddress((void**)&pWT,   g_wt);

    cudaFuncSetAttribute(k_mma<false,false,0>, cudaFuncAttributeMaxDynamicSharedMemorySize, GEMM_SMEM);
    cudaFuncSetAttribute(k_mma<true, false,0>, cudaFuncAttributeMaxDynamicSharedMemorySize, GEMM_SMEM);
    cudaFuncSetAttribute(k_mma<true, false,2>, cudaFuncAttributeMaxDynamicSharedMemorySize, GEMM_SMEM);
    cudaFuncSetAttribute(k_mma<true, true, 1>, cudaFuncAttributeMaxDynamicSharedMemorySize, GEMM_SMEM);
    cudaFuncSetAttribute(k_mma<true, true, 0>, cudaFuncAttributeMaxDynamicSharedMemorySize, GEMM_SMEM);

    // prep
    k_transpose<<<dim3(16, 16, 20), dim3(32, 8)>>>(w_ks, w_vs, d2_w, g1_w, g2_w,
                                                   fc_c_w, blk0_w, blk1_w);
    k_round_af<<<KVSZ / 1024, 256>>>(anchors_feats);
    k_global_proj<<<(3 * B * DIM + 255) / 256, 256>>>(global_feats, w_qs, w_kg, w_vg);
    k_knn_part<<<dim3(NQ / 128, B, NCHUNK), 128>>>(xyz_q, anchors_xyz);
    k_knn_merge<<<BQ / 256, 256>>>();

    // KS + VS projections (one launch, z picks weight/output)
    k_mma<false,false,0><<<dim3(4, (B*NA)/128, 2), 256, GEMM_SMEM>>>(
        pAF, pWT + (size_t)T_KS*262144, nullptr, nullptr, pKV, nullptr, B*NA,
        262144, (size_t)KVSZ);

    // fc_delta
    k_h1<<<(unsigned)(((size_t)ROWS8 * 128) / 256), 256>>>(xyz_q, anchors_xyz, d1_w, d1_b);
    k_mma<true,false,0><<<dim3(4, ROWS8/128), 256, GEMM_SMEM>>>(
        pA, pWT + (size_t)T_D2*262144, d2_b, nullptr, pB, nullptr, ROWS8, 0, 0);

    // attention MLPs
    k_buildx<<<(unsigned)(((size_t)ROWS9 * 128) / 256), 256>>>();
    k_mma<true,false,2><<<dim3(4, ROWS9/128), 256, GEMM_SMEM>>>(
        pC, pWT + (size_t)T_G1*262144, g1_b, nullptr, pA, nullptr, ROWS9, 0, 0);
    k_mma<true,false,0><<<dim3(4, ROWS9/128), 256, GEMM_SMEM>>>(
        pA, pWT + (size_t)T_G2*262144, g2_b, nullptr, pC, nullptr, ROWS9, 0, 0);

    // softmax + weighted sum
    k_attn_lat<<<BQ, 512>>>();

    // decoder
    k_pe_fcp<<<BQ, 128>>>(xyz_q, fc_p_w, fc_p_b, out);

    for (int i = 0; i < NBLK; i++) {
        const float* cb  = fc_c_b + (size_t)i * HID;
        const float* b0b = blk0_b + (size_t)i * HID;
        const float* b1b = blk1_b + (size_t)i * HID;
        float* cwT  = pWT + (size_t)(T_FCC + i) * 262144;
        float* b0wT = pWT + (size_t)(T_B0  + i) * 262144;
        float* b1wT = pWT + (size_t)(T_B1  + i) * 262144;
        k_mma<true,true,1><<<dim3(4, BQ/128), 256, GEMM_SMEM>>>(
            pLat, cwT, cb, out, pTmp, pTmpR, BQ, 0, 0);
        k_mma<true,false,2><<<dim3(4, BQ/128), 256, GEMM_SMEM>>>(
            pTmpR, b0wT, b0b, nullptr, pH, nullptr, BQ, 0, 0);
        k_mma<true,true,0><<<dim3(4, BQ/128), 256, GEMM_SMEM>>>(
            pH, b1wT, b1b, pTmp, out, nullptr, BQ, 0, 0);
    }
}

// round 14
// speedup vs baseline: 3.2965x; 1.0591x over previous
#include <cuda_runtime.h>
#include <cstdint>
#include <math.h>

#define B 2
#define NQ 4096
#define NA 2048
#define DIM 512
#define HID 512
#define NBLK 5
#define KNN 8
#define NCHUNK 16
#define CHUNK (NA/NCHUNK)   // 128

#define BQ    (B*NQ)        // 8192
#define ROWS8 (BQ*KNN)      // 65536
#define ROWS9 (BQ*9)        // 73728
#define KVSZ  (B*NA*DIM)

// ---------------- static scratch (no allocations allowed) ----------------
__device__ float g_KV[2*KVSZ];               // [0]=KS, [1]=VS
__device__ int   g_idx[BQ*KNN];
__device__ float g_knn_d[BQ*NCHUNK*KNN];
__device__ int   g_knn_i[BQ*NCHUNK*KNN];
__device__ float g_af32[KVSZ];
__device__ float g_bufA[(size_t)ROWS9*DIM];
__device__ float g_bufB[(size_t)ROWS9*DIM];
__device__ float g_bufC[(size_t)ROWS9*DIM];
__device__ float g_lat[BQ*DIM];
__device__ float g_tmp[BQ*HID];
__device__ float g_tmpR[BQ*HID];
__device__ float g_h[BQ*HID];
__device__ float g_qattn[B*DIM];
__device__ float g_kgv[B*DIM];
__device__ float g_vgv[B*DIM];
__device__ float g_wt[(size_t)20*512*512];

#define T_KS  0
#define T_VS  1
#define T_D2  2
#define T_G1  3
#define T_G2  4
#define T_FCC 5
#define T_B0  10
#define T_B1  15

// ---------------- tf32 / cp.async helpers ----------------
__device__ __forceinline__ uint32_t to_tf32(float x) {
    uint32_t u;
    asm("cvt.rna.tf32.f32 %0, %1;" : "=r"(u) : "f"(x));
    return u;
}
__device__ __forceinline__ float tf32f(float x) { return __uint_as_float(to_tf32(x)); }

__device__ __forceinline__ void cp16(float* smem_dst, const float* gsrc) {
    uint32_t s = (uint32_t)__cvta_generic_to_shared(smem_dst);
    asm volatile("cp.async.ca.shared.global [%0], [%1], 16;" :: "r"(s), "l"(gsrc) : "memory");
}
#define CP_COMMIT() asm volatile("cp.async.commit_group;" ::: "memory")
#define CP_WAIT1()  asm volatile("cp.async.wait_group 1;" ::: "memory")
#define CP_WAIT0()  asm volatile("cp.async.wait_group 0;" ::: "memory")

__device__ __forceinline__ void mma_m16n8k8(float* d, const uint32_t* a, const uint32_t* b) {
    asm volatile(
        "mma.sync.aligned.m16n8k8.row.col.f32.tf32.tf32.f32 "
        "{%0,%1,%2,%3}, {%4,%5,%6,%7}, {%8,%9}, {%0,%1,%2,%3};"
        : "+f"(d[0]), "+f"(d[1]), "+f"(d[2]), "+f"(d[3])
        : "r"(a[0]), "r"(a[1]), "r"(a[2]), "r"(a[3]),
          "r"(b[0]), "r"(b[1]));
}

// ---------------- weight transpose: [K,N] -> [N,K], tf32-rounded ----------------
__global__ void k_transpose(const float* __restrict__ wks, const float* __restrict__ wvs,
                            const float* __restrict__ d2w, const float* __restrict__ g1w,
                            const float* __restrict__ g2w, const float* __restrict__ fcc,
                            const float* __restrict__ b0w, const float* __restrict__ b1w) {
    __shared__ float t[32][33];
    int z = blockIdx.z;
    const float* src;
    if      (z == 0) src = wks;
    else if (z == 1) src = wvs;
    else if (z == 2) src = d2w;
    else if (z == 3) src = g1w;
    else if (z == 4) src = g2w;
    else if (z < 10) src = fcc + (size_t)(z - 5)  * 262144;
    else if (z < 15) src = b0w + (size_t)(z - 10) * 262144;
    else             src = b1w + (size_t)(z - 15) * 262144;
    float* dst = g_wt + (size_t)z * 262144;
    int x  = blockIdx.x * 32 + threadIdx.x;
    int y0 = blockIdx.y * 32;
#pragma unroll
    for (int i = threadIdx.y; i < 32; i += 8)
        t[i][threadIdx.x] = src[(size_t)(y0 + i) * 512 + x];
    __syncthreads();
    int xo  = blockIdx.y * 32 + threadIdx.x;
    int yo0 = blockIdx.x * 32;
#pragma unroll
    for (int i = threadIdx.y; i < 32; i += 8)
        dst[(size_t)(yo0 + i) * 512 + xo] = tf32f(t[threadIdx.x][i]);
}

// ---------------- round anchors_feats to tf32 (float4) ----------------
__global__ void k_round_af(const float* __restrict__ af) {
    int o = blockIdx.x * 256 + threadIdx.x;
    float4 v = *(const float4*)(af + o * 4);
    float4 w;
    w.x = tf32f(v.x); w.y = tf32f(v.y); w.z = tf32f(v.z); w.w = tf32f(v.w);
    *(float4*)(g_af32 + o * 4) = w;
}

// ---------------- tf32 mma.sync GEMM, cp.async double-buffered, BK=32 ----------------
// 128x128 CTA tile, 4 warps (2m x 2n), warp tile 64x64 = 4x8 m16n8k8.
// Per-slab smem traffic 64KB/CTA (was 96KB with 8 thin warps) -> 1.5x less LDS.
#define SROW 36
#define STAGE_F (128 * SROW)
#define GEMM_SMEM (4 * STAGE_F * 4)

template<bool HAS_BIAS, bool HAS_RES, int OUTMODE>
__global__ __launch_bounds__(128, 2)
void k_mma(const float* __restrict__ A, const float* __restrict__ Wt,
           const float* __restrict__ bias, const float* __restrict__ R,
           float* __restrict__ C, float* __restrict__ C2, int M,
           size_t zsW, size_t zsC) {
    extern __shared__ float sm[];
    float* Asm = sm;
    float* Bsm = sm + 2 * STAGE_F;
    Wt += (size_t)blockIdx.z * zsW;
    C  += (size_t)blockIdx.z * zsC;
    const int tid  = threadIdx.x;
    const int lane = tid & 31;
    const int warp = tid >> 5;
    const int wm   = warp >> 1;      // 0..1
    const int wn   = warp & 1;       // 0..1
    const int gid  = lane >> 2;      // 0..7
    const int tig  = lane & 3;       // 0..3
    const int bn = blockIdx.x * 128;
    const int bm = blockIdx.y * 128;

    // cp.async: 128 rows x 8 chunks of 16B; 128 thr -> 16 rows/pass, 8 passes
    const int crow = tid >> 3;       // 0..15
    const int cchk = (tid & 7) * 4;

    float acc[4][8][4];
#pragma unroll
    for (int i = 0; i < 4; i++)
#pragma unroll
        for (int j = 0; j < 8; j++)
#pragma unroll
            for (int l = 0; l < 4; l++) acc[i][j][l] = 0.f;

#pragma unroll
    for (int p = 0; p < 8; p++) {
        const int row = crow + p * 16;
        cp16(Asm + row * SROW + cchk, A  + (size_t)(bm + row) * 512 + cchk);
        cp16(Bsm + row * SROW + cchk, Wt + (size_t)(bn + row) * 512 + cchk);
    }
    CP_COMMIT();

#pragma unroll 1
    for (int it = 0; it < 16; ++it) {
        const int st = it & 1;
        if (it + 1 < 16) {
            const int k0  = (it + 1) * 32;
            const int st2 = (it + 1) & 1;
#pragma unroll
            for (int p = 0; p < 8; p++) {
                const int row = crow + p * 16;
                cp16(Asm + st2 * STAGE_F + row * SROW + cchk,
                     A  + (size_t)(bm + row) * 512 + k0 + cchk);
                cp16(Bsm + st2 * STAGE_F + row * SROW + cchk,
                     Wt + (size_t)(bn + row) * 512 + k0 + cchk);
            }
            CP_COMMIT();
            CP_WAIT1();
        } else {
            CP_WAIT0();
        }
        __syncthreads();

        const float* As = Asm + st * STAGE_F;
        const float* Bs = Bsm + st * STAGE_F;
#pragma unroll
        for (int k8 = 0; k8 < 32; k8 += 8) {
            uint32_t af[4][4], bf[8][2];
#pragma unroll
            for (int mi = 0; mi < 4; mi++) {
                const int m = wm * 64 + mi * 16 + gid;
                af[mi][0] = __float_as_uint(As[(m    ) * SROW + k8 + tig    ]);
                af[mi][1] = __float_as_uint(As[(m + 8) * SROW + k8 + tig    ]);
                af[mi][2] = __float_as_uint(As[(m    ) * SROW + k8 + tig + 4]);
                af[mi][3] = __float_as_uint(As[(m + 8) * SROW + k8 + tig + 4]);
            }
#pragma unroll
            for (int ni = 0; ni < 8; ni++) {
                const int n = wn * 64 + ni * 8 + gid;
                bf[ni][0] = __float_as_uint(Bs[n * SROW + k8 + tig    ]);
                bf[ni][1] = __float_as_uint(Bs[n * SROW + k8 + tig + 4]);
            }
#pragma unroll
            for (int mi = 0; mi < 4; mi++)
#pragma unroll
                for (int ni = 0; ni < 8; ni++)
                    mma_m16n8k8(acc[mi][ni], af[mi], bf[ni]);
        }
        __syncthreads();
    }

    // epilogue
#pragma unroll
    for (int mi = 0; mi < 4; mi++) {
#pragma unroll
        for (int h = 0; h < 2; h++) {
            const int row = bm + wm * 64 + mi * 16 + gid + h * 8;
            float* Crow = C + (size_t)row * 512;
            float* C2row = (OUTMODE == 1) ? (C2 + (size_t)row * 512) : nullptr;
            const float* Rrow = R + (size_t)row * 512;
#pragma unroll
            for (int ni = 0; ni < 8; ni++) {
                const int col = bn + wn * 64 + ni * 8 + tig * 2;
                float2 v;
                v.x = acc[mi][ni][h * 2 + 0];
                v.y = acc[mi][ni][h * 2 + 1];
                if (HAS_BIAS) { v.x += bias[col]; v.y += bias[col + 1]; }
                if (HAS_RES) {
                    float2 rr = *(const float2*)(Rrow + col);
                    v.x += rr.x; v.y += rr.y;
                }
                if (OUTMODE == 2) {
                    float2 w;
                    w.x = tf32f(fmaxf(v.x, 0.f));
                    w.y = tf32f(fmaxf(v.y, 0.f));
                    *(float2*)(Crow + col) = w;
                } else {
                    *(float2*)(Crow + col) = v;
                    if (OUTMODE == 1) {
                        float2 w;
                        w.x = tf32f(fmaxf(v.x, 0.f));
                        w.y = tf32f(fmaxf(v.y, 0.f));
                        *(float2*)(C2row + col) = w;
                    }
                }
            }
        }
    }
}

// ---------------- tiny projection of global feats ----------------
__global__ void k_global_proj(const float* __restrict__ gf,
                              const float* __restrict__ wqs,
                              const float* __restrict__ wkg,
                              const float* __restrict__ wvg) {
    int t = blockIdx.x * blockDim.x + threadIdx.x;
    if (t >= 3 * B * DIM) return;
    int which = t / (B * DIM);
    int r = t % (B * DIM);
    int b = r / DIM, n = r % DIM;
    const float* W = (which == 0) ? wqs : (which == 1) ? wkg : wvg;
    float acc = 0.f;
    for (int k = 0; k < DIM; k++)
        acc = fmaf(gf[b * DIM + k], W[(size_t)k * DIM + n], acc);
    float* out = (which == 0) ? g_qattn : (which == 1) ? g_kgv : g_vgv;
    out[b * DIM + n] = acc;
}

// ---------------- KNN phase 1: per-chunk top-8 (grid 32 x B x NCHUNK) ----------------
__global__ void k_knn_part(const float* __restrict__ xyz_q,
                           const float* __restrict__ axyz) {
    __shared__ float sx[CHUNK], sy[CHUNK], sz[CHUNK], s2[CHUNK];
    int b = blockIdx.y, z = blockIdx.z;
    int q = blockIdx.x * 128 + threadIdx.x;
    int bq = b * NQ + q;
    float qx = xyz_q[bq * 3 + 0];
    float qy = xyz_q[bq * 3 + 1];
    float qz = xyz_q[bq * 3 + 2];
    float q2 = qx * qx + qy * qy + qz * qz;
    if (threadIdx.x < CHUNK) {
        int j = threadIdx.x;
        const float* ap = axyz + ((size_t)(b * NA + z * CHUNK + j)) * 3;
        float ax = ap[0], ay = ap[1], az = ap[2];
        sx[j] = ax; sy[j] = ay; sz[j] = az;
        s2[j] = ax * ax + ay * ay + az * az;
    }
    __syncthreads();
    float bd[KNN]; int bi[KNN];
#pragma unroll
    for (int i = 0; i < KNN; i++) { bd[i] = INFINITY; bi[i] = 0; }
    for (int j = 0; j < CHUNK; j++) {
        float d2 = q2 + s2[j] - 2.f * (qx * sx[j] + qy * sy[j] + qz * sz[j]);
        if (d2 < bd[KNN - 1]) {
            bd[KNN - 1] = d2; bi[KNN - 1] = z * CHUNK + j;
#pragma unroll
            for (int s = KNN - 1; s > 0; --s) {
                if (bd[s] < bd[s - 1]) {
                    float td = bd[s]; bd[s] = bd[s - 1]; bd[s - 1] = td;
                    int ti = bi[s]; bi[s] = bi[s - 1]; bi[s - 1] = ti;
                }
            }
        }
    }
    size_t base = ((size_t)bq * NCHUNK + z) * KNN;
#pragma unroll
    for (int i = 0; i < KNN; i++) { g_knn_d[base + i] = bd[i]; g_knn_i[base + i] = bi[i]; }
}

// ---------------- KNN phase 2: merge sorted chunk-lists (ascending z => stable) ----
__global__ void k_knn_merge() {
    int bq = blockIdx.x * 256 + threadIdx.x;
    float bd[KNN]; int bi[KNN];
#pragma unroll
    for (int i = 0; i < KNN; i++) { bd[i] = INFINITY; bi[i] = 0; }
    for (int z = 0; z < NCHUNK; z++) {
        size_t base = ((size_t)bq * NCHUNK + z) * KNN;
#pragma unroll
        for (int c = 0; c < KNN; c++) {
            float d = g_knn_d[base + c];
            if (!(d < bd[KNN - 1])) break;   // chunk list sorted ascending
            int idx = g_knn_i[base + c];
            bd[KNN - 1] = d; bi[KNN - 1] = idx;
#pragma unroll
            for (int s = KNN - 1; s > 0; --s) {
                if (bd[s] < bd[s - 1]) {
                    float td = bd[s]; bd[s] = bd[s - 1]; bd[s - 1] = td;
                    int ti = bi[s]; bi[s] = bi[s - 1]; bi[s - 1] = ti;
                }
            }
        }
    }
#pragma unroll
    for (int i = 0; i < KNN; i++) g_idx[bq * KNN + i] = bi[i];
}

// ---------------- H1 = tf32(relu(d @ d1_w + d1_b)), float4 ----------------
__global__ void k_h1(const float* __restrict__ xyz_q,
                     const float* __restrict__ axyz,
                     const float* __restrict__ d1w,
                     const float* __restrict__ d1b) {
    size_t t = (size_t)blockIdx.x * 256 + threadIdx.x;
    int f = (int)(t & 127) * 4;
    size_t r = t >> 7;
    int kk = (int)(r & 7);
    int bq = (int)(r >> 3);
    int b = bq >> 12;
    int aidx = g_idx[bq * KNN + kk];
    const float* qp = xyz_q + (size_t)bq * 3;
    const float* ap = axyz + ((size_t)b * NA + aidx) * 3;
    float dx = qp[0] - ap[0], dy = qp[1] - ap[1], dz = qp[2] - ap[2];
    float4 w0 = *(const float4*)(d1w + f);
    float4 w1 = *(const float4*)(d1w + 512 + f);
    float4 w2 = *(const float4*)(d1w + 1024 + f);
    float4 bb = *(const float4*)(d1b + f);
    float4 o;
    o.x = tf32f(fmaxf(fmaf(dx, w0.x, fmaf(dy, w1.x, fmaf(dz, w2.x, bb.x))), 0.f));
    o.y = tf32f(fmaxf(fmaf(dx, w0.y, fmaf(dy, w1.y, fmaf(dz, w2.y, bb.y))), 0.f));
    o.z = tf32f(fmaxf(fmaf(dx, w0.z, fmaf(dy, w1.z, fmaf(dz, w2.z, bb.z))), 0.f));
    o.w = tf32f(fmaxf(fmaf(dx, w0.w, fmaf(dy, w1.w, fmaf(dz, w2.w, bb.w))), 0.f));
    *(float4*)(g_bufA + r * 512 + f) = o;
}

// ---------------- build attention input X = tf32(q - k + pos), float4 ----------------
__global__ void k_buildx() {
    size_t t = (size_t)blockIdx.x * 256 + threadIdx.x;
    int f = (int)(t & 127) * 4;
    size_t r = t >> 7;
    int n = (int)(r % 9);
    int bq = (int)(r / 9);
    int b = bq >> 12;
    float4 qv = *(const float4*)(g_qattn + b * DIM + f);
    float4 o;
    if (n < KNN) {
        int aidx = g_idx[bq * KNN + n];
        float4 kv = *(const float4*)(g_KV + ((size_t)b * NA + aidx) * DIM + f);
        float4 pe = *(const float4*)(g_bufB + ((size_t)bq * KNN + n) * DIM + f);
        o.x = tf32f(qv.x - kv.x + pe.x);
        o.y = tf32f(qv.y - kv.y + pe.y);
        o.z = tf32f(qv.z - kv.z + pe.z);
        o.w = tf32f(qv.w - kv.w + pe.w);
    } else {
        float4 kg = *(const float4*)(g_kgv + b * DIM + f);
        o.x = tf32f(qv.x - kg.x);
        o.y = tf32f(qv.y - kg.y);
        o.z = tf32f(qv.z - kg.z);
        o.w = tf32f(qv.w - kg.w);
    }
    *(float4*)(g_bufC + r * 512 + f) = o;
}

// ---------------- per-feature softmax over 9 tokens + weighted sum ----------------
__global__ void k_attn_lat() {
    int bq = blockIdx.x;
    int f = threadIdx.x;
    int b = bq >> 12;
    __shared__ int sidx[KNN];
    if (threadIdx.x < KNN) sidx[threadIdx.x] = g_idx[bq * KNN + threadIdx.x];
    __syncthreads();
    float v[9];
#pragma unroll
    for (int n = 0; n < 9; n++)
        v[n] = g_bufC[((size_t)bq * 9 + n) * DIM + f];
    float m = v[0];
#pragma unroll
    for (int n = 1; n < 9; n++) m = fmaxf(m, v[n]);
    float s = 0.f;
#pragma unroll
    for (int n = 0; n < 9; n++) { v[n] = expf(v[n] - m); s += v[n]; }
    float inv = 1.f / s;
    float acc = 0.f;
#pragma unroll
    for (int n = 0; n < KNN; n++) {
        float val = g_KV[KVSZ + ((size_t)b * NA + sidx[n]) * DIM + f]
                  + g_bufB[((size_t)bq * KNN + n) * DIM + f];
        acc = fmaf(v[n], val, acc);
    }
    acc = fmaf(v[8], g_vgv[b * DIM + f], acc);
    g_lat[(size_t)bq * DIM + f] = tf32f(acc * inv);
}

// ---------------- NeRF positional encoding + fc_p ----------------
__global__ void k_pe_fcp(const float* __restrict__ xyz_q,
                         const float* __restrict__ fcpw,
                         const float* __restrict__ fcpb,
                         float* __restrict__ out) {
    __shared__ float pe[60];
    int bq = blockIdx.x;
    if (threadIdx.x < 60) {
        int i = threadIdx.x;
        int fr = i / 6, rem = i % 6, sc = rem / 3, c = rem % 3;
        float p = xyz_q[(size_t)bq * 3 + c];
        float a = p * ((float)(1 << fr) * 3.14159265358979f);
        pe[i] = (sc == 0) ? sinf(a) : cosf(a);
    }
    __syncthreads();
#pragma unroll
    for (int j = 0; j < 4; j++) {
        int n = j * 128 + threadIdx.x;
        float acc = fcpb[n];
#pragma unroll
        for (int i = 0; i < 60; i++)
            acc = fmaf(pe[i], fcpw[(size_t)i * 512 + n], acc);
        out[(size_t)bq * 512 + n] = acc;
    }
}

// ---------------- launch ----------------
extern "C" void kernel_launch(void* const* d_in, const int* in_sizes, int n_in,
                              void* d_out, int out_size) {
    const float* xyz_q        = (const float*)d_in[0];
    const float* global_feats = (const float*)d_in[1];
    const float* anchors_xyz  = (const float*)d_in[2];
    const float* anchors_feats= (const float*)d_in[3];
    const float* w_qs = (const float*)d_in[4];
    const float* w_ks = (const float*)d_in[5];
    const float* w_vs = (const float*)d_in[6];
    const float* w_kg = (const float*)d_in[7];
    const float* w_vg = (const float*)d_in[8];
    const float* d1_w = (const float*)d_in[9];
    const float* d1_b = (const float*)d_in[10];
    const float* d2_w = (const float*)d_in[11];
    const float* d2_b = (const float*)d_in[12];
    const float* g1_w = (const float*)d_in[13];
    const float* g1_b = (const float*)d_in[14];
    const float* g2_w = (const float*)d_in[15];
    const float* g2_b = (const float*)d_in[16];
    const float* fc_p_w = (const float*)d_in[17];
    const float* fc_p_b = (const float*)d_in[18];
    const float* fc_c_w = (const float*)d_in[19];
    const float* fc_c_b = (const float*)d_in[20];
    const float* blk0_w = (const float*)d_in[21];
    const float* blk0_b = (const float*)d_in[22];
    const float* blk1_w = (const float*)d_in[23];
    const float* blk1_b = (const float*)d_in[24];
    float* out = (float*)d_out;

    float *pKV, *pAF, *pA, *pB, *pC, *pLat, *pTmp, *pTmpR, *pH, *pWT;
    cudaGetSymbolAddress((void**)&pKV,   g_KV);
    cudaGetSymbolAddress((void**)&pAF,   g_af32);
    cudaGetSymbolAddress((void**)&pA,    g_bufA);
    cudaGetSymbolAddress((void**)&pB,    g_bufB);
    cudaGetSymbolAddress((void**)&pC,    g_bufC);
    cudaGetSymbolAddress((void**)&pLat,  g_lat);
    cudaGetSymbolAddress((void**)&pTmp,  g_tmp);
    cudaGetSymbolAddress((void**)&pTmpR, g_tmpR);
    cudaGetSymbolAddress((void**)&pH,    g_h);
    cudaGetSymbolAddress((void**)&pWT,   g_wt);

    cudaFuncSetAttribute(k_mma<false,false,0>, cudaFuncAttributeMaxDynamicSharedMemorySize, GEMM_SMEM);
    cudaFuncSetAttribute(k_mma<true, false,0>, cudaFuncAttributeMaxDynamicSharedMemorySize, GEMM_SMEM);
    cudaFuncSetAttribute(k_mma<true, false,2>, cudaFuncAttributeMaxDynamicSharedMemorySize, GEMM_SMEM);
    cudaFuncSetAttribute(k_mma<true, true, 1>, cudaFuncAttributeMaxDynamicSharedMemorySize, GEMM_SMEM);
    cudaFuncSetAttribute(k_mma<true, true, 0>, cudaFuncAttributeMaxDynamicSharedMemorySize, GEMM_SMEM);

    // prep
    k_transpose<<<dim3(16, 16, 20), dim3(32, 8)>>>(w_ks, w_vs, d2_w, g1_w, g2_w,
                                                   fc_c_w, blk0_w, blk1_w);
    k_round_af<<<KVSZ / 1024, 256>>>(anchors_feats);
    k_global_proj<<<(3 * B * DIM + 255) / 256, 256>>>(global_feats, w_qs, w_kg, w_vg);
    k_knn_part<<<dim3(NQ / 128, B, NCHUNK), 128>>>(xyz_q, anchors_xyz);
    k_knn_merge<<<BQ / 256, 256>>>();

    // KS + VS projections (one launch, z picks weight/output)
    k_mma<false,false,0><<<dim3(4, (B*NA)/128, 2), 128, GEMM_SMEM>>>(
        pAF, pWT + (size_t)T_KS*262144, nullptr, nullptr, pKV, nullptr, B*NA,
        262144, (size_t)KVSZ);

    // fc_delta
    k_h1<<<(unsigned)(((size_t)ROWS8 * 128) / 256), 256>>>(xyz_q, anchors_xyz, d1_w, d1_b);
    k_mma<true,false,0><<<dim3(4, ROWS8/128), 128, GEMM_SMEM>>>(
        pA, pWT + (size_t)T_D2*262144, d2_b, nullptr, pB, nullptr, ROWS8, 0, 0);

    // attention MLPs
    k_buildx<<<(unsigned)(((size_t)ROWS9 * 128) / 256), 256>>>();
    k_mma<true,false,2><<<dim3(4, ROWS9/128), 128, GEMM_SMEM>>>(
        pC, pWT + (size_t)T_G1*262144, g1_b, nullptr, pA, nullptr, ROWS9, 0, 0);
    k_mma<true,false,0><<<dim3(4, ROWS9/128), 128, GEMM_SMEM>>>(
        pA, pWT + (size_t)T_G2*262144, g2_b, nullptr, pC, nullptr, ROWS9, 0, 0);

    // softmax + weighted sum
    k_attn_lat<<<BQ, 512>>>();

    // decoder
    k_pe_fcp<<<BQ, 128>>>(xyz_q, fc_p_w, fc_p_b, out);

    for (int i = 0; i < NBLK; i++) {
        const float* cb  = fc_c_b + (size_t)i * HID;
        const float* b0b = blk0_b + (size_t)i * HID;
        const float* b1b = blk1_b + (size_t)i * HID;
        float* cwT  = pWT + (size_t)(T_FCC + i) * 262144;
        float* b0wT = pWT + (size_t)(T_B0  + i) * 262144;
        float* b1wT = pWT + (size_t)(T_B1  + i) * 262144;
        k_mma<true,true,1><<<dim3(4, BQ/128), 128, GEMM_SMEM>>>(
            pLat, cwT, cb, out, pTmp, pTmpR, BQ, 0, 0);
        k_mma<true,false,2><<<dim3(4, BQ/128), 128, GEMM_SMEM>>>(
            pTmpR, b0wT, b0b, nullptr, pH, nullptr, BQ, 0, 0);
        k_mma<true,true,0><<<dim3(4, BQ/128), 128, GEMM_SMEM>>>(
            pH, b1wT, b1b, pTmp, out, nullptr, BQ, 0, 0);
    }
}

// round 15
// speedup vs baseline: 3.4520x; 1.0472x over previous
#include <cuda_runtime.h>
#include <cstdint>
#include <math.h>

#define B 2
#define NQ 4096
#define NA 2048
#define DIM 512
#define HID 512
#define NBLK 5
#define KNN 8
#define NCHUNK 16
#define CHUNK (NA/NCHUNK)   // 128

#define BQ    (B*NQ)        // 8192
#define ROWS8 (BQ*KNN)      // 65536
#define ROWS9 (BQ*9)        // 73728
#define KVSZ  (B*NA*DIM)

// ---------------- static scratch (no allocations allowed) ----------------
__device__ float g_KV[2*KVSZ];               // [0]=KS, [1]=VS
__device__ int   g_idx[BQ*KNN];
__device__ float g_knn_d[BQ*NCHUNK*KNN];
__device__ int   g_knn_i[BQ*NCHUNK*KNN];
__device__ float g_af32[KVSZ];
__device__ float g_bufA[(size_t)ROWS9*DIM];
__device__ float g_bufB[(size_t)ROWS9*DIM];
__device__ float g_bufC[(size_t)ROWS9*DIM];
__device__ float g_lat[BQ*DIM];
__device__ float g_tmp[BQ*HID];
__device__ float g_tmpR[BQ*HID];
__device__ float g_h[BQ*HID];
__device__ float g_qattn[B*DIM];
__device__ float g_kgv[B*DIM];
__device__ float g_vgv[B*DIM];
__device__ float g_wt[(size_t)20*512*512];

#define T_KS  0
#define T_VS  1
#define T_D2  2
#define T_G1  3
#define T_G2  4
#define T_FCC 5
#define T_B0  10
#define T_B1  15

// ---------------- tf32 / cp.async / ldmatrix helpers ----------------
__device__ __forceinline__ uint32_t to_tf32(float x) {
    uint32_t u;
    asm("cvt.rna.tf32.f32 %0, %1;" : "=r"(u) : "f"(x));
    return u;
}
__device__ __forceinline__ float tf32f(float x) { return __uint_as_float(to_tf32(x)); }

__device__ __forceinline__ void cp16(float* smem_dst, const float* gsrc) {
    uint32_t s = (uint32_t)__cvta_generic_to_shared(smem_dst);
    asm volatile("cp.async.ca.shared.global [%0], [%1], 16;" :: "r"(s), "l"(gsrc) : "memory");
}
#define CP_COMMIT() asm volatile("cp.async.commit_group;" ::: "memory")
#define CP_WAIT1()  asm volatile("cp.async.wait_group 1;" ::: "memory")
#define CP_WAIT0()  asm volatile("cp.async.wait_group 0;" ::: "memory")

__device__ __forceinline__ void ldsm_x4(uint32_t& r0, uint32_t& r1, uint32_t& r2,
                                        uint32_t& r3, uint32_t addr) {
    asm volatile("ldmatrix.sync.aligned.m8n8.x4.shared.b16 {%0,%1,%2,%3}, [%4];"
                 : "=r"(r0), "=r"(r1), "=r"(r2), "=r"(r3) : "r"(addr));
}

__device__ __forceinline__ void mma_m16n8k8(float* d, const uint32_t* a, const uint32_t* b) {
    asm volatile(
        "mma.sync.aligned.m16n8k8.row.col.f32.tf32.tf32.f32 "
        "{%0,%1,%2,%3}, {%4,%5,%6,%7}, {%8,%9}, {%0,%1,%2,%3};"
        : "+f"(d[0]), "+f"(d[1]), "+f"(d[2]), "+f"(d[3])
        : "r"(a[0]), "r"(a[1]), "r"(a[2]), "r"(a[3]),
          "r"(b[0]), "r"(b[1]));
}

// ---------------- weight transpose: [K,N] -> [N,K], tf32-rounded ----------------
__global__ void k_transpose(const float* __restrict__ wks, const float* __restrict__ wvs,
                            const float* __restrict__ d2w, const float* __restrict__ g1w,
                            const float* __restrict__ g2w, const float* __restrict__ fcc,
                            const float* __restrict__ b0w, const float* __restrict__ b1w) {
    __shared__ float t[32][33];
    int z = blockIdx.z;
    const float* src;
    if      (z == 0) src = wks;
    else if (z == 1) src = wvs;
    else if (z == 2) src = d2w;
    else if (z == 3) src = g1w;
    else if (z == 4) src = g2w;
    else if (z < 10) src = fcc + (size_t)(z - 5)  * 262144;
    else if (z < 15) src = b0w + (size_t)(z - 10) * 262144;
    else             src = b1w + (size_t)(z - 15) * 262144;
    float* dst = g_wt + (size_t)z * 262144;
    int x  = blockIdx.x * 32 + threadIdx.x;
    int y0 = blockIdx.y * 32;
#pragma unroll
    for (int i = threadIdx.y; i < 32; i += 8)
        t[i][threadIdx.x] = src[(size_t)(y0 + i) * 512 + x];
    __syncthreads();
    int xo  = blockIdx.y * 32 + threadIdx.x;
    int yo0 = blockIdx.x * 32;
#pragma unroll
    for (int i = threadIdx.y; i < 32; i += 8)
        dst[(size_t)(yo0 + i) * 512 + xo] = tf32f(t[threadIdx.x][i]);
}

// ---------------- round anchors_feats to tf32 (float4) ----------------
__global__ void k_round_af(const float* __restrict__ af) {
    int o = blockIdx.x * 256 + threadIdx.x;
    float4 v = *(const float4*)(af + o * 4);
    float4 w;
    w.x = tf32f(v.x); w.y = tf32f(v.y); w.z = tf32f(v.z); w.w = tf32f(v.w);
    *(float4*)(g_af32 + o * 4) = w;
}

// ---------------- tf32 mma.sync GEMM, cp.async double-buffered, BK=32 ----------------
// 128x128 CTA tile, 4 warps (2m x 2n), warp tile 64x64 = 4x8 m16n8k8.
// Fragments loaded via ldmatrix.x4 (b16 view of tf32): 8 LDSM per k8 (was 32 LDS).
#define SROW 36
#define STAGE_F (128 * SROW)
#define STAGE_B (STAGE_F * 4)
#define TILE16_B (16 * SROW * 4)
#define GEMM_SMEM (4 * STAGE_F * 4)

template<bool HAS_BIAS, bool HAS_RES, int OUTMODE>
__global__ __launch_bounds__(128, 2)
void k_mma(const float* __restrict__ A, const float* __restrict__ Wt,
           const float* __restrict__ bias, const float* __restrict__ R,
           float* __restrict__ C, float* __restrict__ C2, int M,
           size_t zsW, size_t zsC) {
    extern __shared__ float sm[];
    float* Asm = sm;
    float* Bsm = sm + 2 * STAGE_F;
    Wt += (size_t)blockIdx.z * zsW;
    C  += (size_t)blockIdx.z * zsC;
    const int tid  = threadIdx.x;
    const int lane = tid & 31;
    const int warp = tid >> 5;
    const int wm   = warp >> 1;      // 0..1
    const int wn   = warp & 1;       // 0..1
    const int gid  = lane >> 2;      // 0..7
    const int tig  = lane & 3;       // 0..3
    const int bn = blockIdx.x * 128;
    const int bm = blockIdx.y * 128;

    // cp.async: 128 rows x 8 chunks of 16B; 128 thr -> 16 rows/pass, 8 passes
    const int crow = tid >> 3;       // 0..15
    const int cchk = (tid & 7) * 4;

    // ldmatrix lane addressing (b16 view of tf32; tile = 8 rows x 4 tf32)
    const int lrow = lane & 7;
    const int lt   = lane >> 3;      // 0..3
    const uint32_t smem_u32 = (uint32_t)__cvta_generic_to_shared(sm);
    // A: r0..r3 <- (rows+0,k+0) (rows+8,k+0) (rows+0,k+4) (rows+8,k+4)
    const uint32_t aOff = (uint32_t)(((wm * 64 + ((lt & 1) << 3) + lrow) * SROW
                                      + ((lt >> 1) << 2)) * 4);
    // B: r0..r3 <- (n+0,k+0) (n+0,k+4) (n+8,k+0) (n+8,k+4)
    const uint32_t bOff = (uint32_t)(((wn * 64 + ((lt >> 1) << 3) + lrow) * SROW
                                      + ((lt & 1) << 2)) * 4);
    const uint32_t aBase0 = smem_u32 + aOff;
    const uint32_t bBase0 = smem_u32 + 2 * STAGE_B + bOff;

    float acc[4][8][4];
#pragma unroll
    for (int i = 0; i < 4; i++)
#pragma unroll
        for (int j = 0; j < 8; j++)
#pragma unroll
            for (int l = 0; l < 4; l++) acc[i][j][l] = 0.f;

#pragma unroll
    for (int p = 0; p < 8; p++) {
        const int row = crow + p * 16;
        cp16(Asm + row * SROW + cchk, A  + (size_t)(bm + row) * 512 + cchk);
        cp16(Bsm + row * SROW + cchk, Wt + (size_t)(bn + row) * 512 + cchk);
    }
    CP_COMMIT();

#pragma unroll 1
    for (int it = 0; it < 16; ++it) {
        const int st = it & 1;
        if (it + 1 < 16) {
            const int k0  = (it + 1) * 32;
            const int st2 = (it + 1) & 1;
#pragma unroll
            for (int p = 0; p < 8; p++) {
                const int row = crow + p * 16;
                cp16(Asm + st2 * STAGE_F + row * SROW + cchk,
                     A  + (size_t)(bm + row) * 512 + k0 + cchk);
                cp16(Bsm + st2 * STAGE_F + row * SROW + cchk,
                     Wt + (size_t)(bn + row) * 512 + k0 + cchk);
            }
            CP_COMMIT();
            CP_WAIT1();
        } else {
            CP_WAIT0();
        }
        __syncthreads();

        const uint32_t aB = aBase0 + st * STAGE_B;
        const uint32_t bB = bBase0 + st * STAGE_B;
#pragma unroll
        for (int k8 = 0; k8 < 32; k8 += 8) {
            uint32_t af[4][4], bf[8][2];
#pragma unroll
            for (int mi = 0; mi < 4; mi++)
                ldsm_x4(af[mi][0], af[mi][1], af[mi][2], af[mi][3],
                        aB + k8 * 4 + mi * TILE16_B);
#pragma unroll
            for (int p = 0; p < 4; p++)
                ldsm_x4(bf[2 * p][0], bf[2 * p][1], bf[2 * p + 1][0], bf[2 * p + 1][1],
                        bB + k8 * 4 + p * TILE16_B);
#pragma unroll
            for (int mi = 0; mi < 4; mi++)
#pragma unroll
                for (int ni = 0; ni < 8; ni++)
                    mma_m16n8k8(acc[mi][ni], af[mi], bf[ni]);
        }
        __syncthreads();
    }

    // epilogue
#pragma unroll
    for (int mi = 0; mi < 4; mi++) {
#pragma unroll
        for (int h = 0; h < 2; h++) {
            const int row = bm + wm * 64 + mi * 16 + gid + h * 8;
            float* Crow = C + (size_t)row * 512;
            float* C2row = (OUTMODE == 1) ? (C2 + (size_t)row * 512) : nullptr;
            const float* Rrow = R + (size_t)row * 512;
#pragma unroll
            for (int ni = 0; ni < 8; ni++) {
                const int col = bn + wn * 64 + ni * 8 + tig * 2;
                float2 v;
                v.x = acc[mi][ni][h * 2 + 0];
                v.y = acc[mi][ni][h * 2 + 1];
                if (HAS_BIAS) { v.x += bias[col]; v.y += bias[col + 1]; }
                if (HAS_RES) {
                    float2 rr = *(const float2*)(Rrow + col);
                    v.x += rr.x; v.y += rr.y;
                }
                if (OUTMODE == 2) {
                    float2 w;
                    w.x = tf32f(fmaxf(v.x, 0.f));
                    w.y = tf32f(fmaxf(v.y, 0.f));
                    *(float2*)(Crow + col) = w;
                } else {
                    *(float2*)(Crow + col) = v;
                    if (OUTMODE == 1) {
                        float2 w;
                        w.x = tf32f(fmaxf(v.x, 0.f));
                        w.y = tf32f(fmaxf(v.y, 0.f));
                        *(float2*)(C2row + col) = w;
                    }
                }
            }
        }
    }
}

// ---------------- tiny projection of global feats ----------------
__global__ void k_global_proj(const float* __restrict__ gf,
                              const float* __restrict__ wqs,
                              const float* __restrict__ wkg,
                              const float* __restrict__ wvg) {
    int t = blockIdx.x * blockDim.x + threadIdx.x;
    if (t >= 3 * B * DIM) return;
    int which = t / (B * DIM);
    int r = t % (B * DIM);
    int b = r / DIM, n = r % DIM;
    const float* W = (which == 0) ? wqs : (which == 1) ? wkg : wvg;
    float acc = 0.f;
    for (int k = 0; k < DIM; k++)
        acc = fmaf(gf[b * DIM + k], W[(size_t)k * DIM + n], acc);
    float* out = (which == 0) ? g_qattn : (which == 1) ? g_kgv : g_vgv;
    out[b * DIM + n] = acc;
}

// ---------------- KNN phase 1: per-chunk top-8 ----------------
__global__ void k_knn_part(const float* __restrict__ xyz_q,
                           const float* __restrict__ axyz) {
    __shared__ float sx[CHUNK], sy[CHUNK], sz[CHUNK], s2[CHUNK];
    int b = blockIdx.y, z = blockIdx.z;
    int q = blockIdx.x * 128 + threadIdx.x;
    int bq = b * NQ + q;
    float qx = xyz_q[bq * 3 + 0];
    float qy = xyz_q[bq * 3 + 1];
    float qz = xyz_q[bq * 3 + 2];
    float q2 = qx * qx + qy * qy + qz * qz;
    if (threadIdx.x < CHUNK) {
        int j = threadIdx.x;
        const float* ap = axyz + ((size_t)(b * NA + z * CHUNK + j)) * 3;
        float ax = ap[0], ay = ap[1], az = ap[2];
        sx[j] = ax; sy[j] = ay; sz[j] = az;
        s2[j] = ax * ax + ay * ay + az * az;
    }
    __syncthreads();
    float bd[KNN]; int bi[KNN];
#pragma unroll
    for (int i = 0; i < KNN; i++) { bd[i] = INFINITY; bi[i] = 0; }
    for (int j = 0; j < CHUNK; j++) {
        float d2 = q2 + s2[j] - 2.f * (qx * sx[j] + qy * sy[j] + qz * sz[j]);
        if (d2 < bd[KNN - 1]) {
            bd[KNN - 1] = d2; bi[KNN - 1] = z * CHUNK + j;
#pragma unroll
            for (int s = KNN - 1; s > 0; --s) {
                if (bd[s] < bd[s - 1]) {
                    float td = bd[s]; bd[s] = bd[s - 1]; bd[s - 1] = td;
                    int ti = bi[s]; bi[s] = bi[s - 1]; bi[s - 1] = ti;
                }
            }
        }
    }
    size_t base = ((size_t)bq * NCHUNK + z) * KNN;
#pragma unroll
    for (int i = 0; i < KNN; i++) { g_knn_d[base + i] = bd[i]; g_knn_i[base + i] = bi[i]; }
}

// ---------------- KNN phase 2: merge sorted chunk-lists (ascending z => stable) ----
__global__ void k_knn_merge() {
    int bq = blockIdx.x * 256 + threadIdx.x;
    float bd[KNN]; int bi[KNN];
#pragma unroll
    for (int i = 0; i < KNN; i++) { bd[i] = INFINITY; bi[i] = 0; }
    for (int z = 0; z < NCHUNK; z++) {
        size_t base = ((size_t)bq * NCHUNK + z) * KNN;
#pragma unroll
        for (int c = 0; c < KNN; c++) {
            float d = g_knn_d[base + c];
            if (!(d < bd[KNN - 1])) break;   // chunk list sorted ascending
            int idx = g_knn_i[base + c];
            bd[KNN - 1] = d; bi[KNN - 1] = idx;
#pragma unroll
            for (int s = KNN - 1; s > 0; --s) {
                if (bd[s] < bd[s - 1]) {
                    float td = bd[s]; bd[s] = bd[s - 1]; bd[s - 1] = td;
                    int ti = bi[s]; bi[s] = bi[s - 1]; bi[s - 1] = ti;
                }
            }
        }
    }
#pragma unroll
    for (int i = 0; i < KNN; i++) g_idx[bq * KNN + i] = bi[i];
}

// ---------------- H1 = tf32(relu(d @ d1_w + d1_b)), float4 ----------------
__global__ void k_h1(const float* __restrict__ xyz_q,
                     const float* __restrict__ axyz,
                     const float* __restrict__ d1w,
                     const float* __restrict__ d1b) {
    size_t t = (size_t)blockIdx.x * 256 + threadIdx.x;
    int f = (int)(t & 127) * 4;
    size_t r = t >> 7;
    int kk = (int)(r & 7);
    int bq = (int)(r >> 3);
    int b = bq >> 12;
    int aidx = g_idx[bq * KNN + kk];
    const float* qp = xyz_q + (size_t)bq * 3;
    const float* ap = axyz + ((size_t)b * NA + aidx) * 3;
    float dx = qp[0] - ap[0], dy = qp[1] - ap[1], dz = qp[2] - ap[2];
    float4 w0 = *(const float4*)(d1w + f);
    float4 w1 = *(const float4*)(d1w + 512 + f);
    float4 w2 = *(const float4*)(d1w + 1024 + f);
    float4 bb = *(const float4*)(d1b + f);
    float4 o;
    o.x = tf32f(fmaxf(fmaf(dx, w0.x, fmaf(dy, w1.x, fmaf(dz, w2.x, bb.x))), 0.f));
    o.y = tf32f(fmaxf(fmaf(dx, w0.y, fmaf(dy, w1.y, fmaf(dz, w2.y, bb.y))), 0.f));
    o.z = tf32f(fmaxf(fmaf(dx, w0.z, fmaf(dy, w1.z, fmaf(dz, w2.z, bb.z))), 0.f));
    o.w = tf32f(fmaxf(fmaf(dx, w0.w, fmaf(dy, w1.w, fmaf(dz, w2.w, bb.w))), 0.f));
    *(float4*)(g_bufA + r * 512 + f) = o;
}

// ---------------- build attention input X = tf32(q - k + pos), float4 ----------------
__global__ void k_buildx() {
    size_t t = (size_t)blockIdx.x * 256 + threadIdx.x;
    int f = (int)(t & 127) * 4;
    size_t r = t >> 7;
    int n = (int)(r % 9);
    int bq = (int)(r / 9);
    int b = bq >> 12;
    float4 qv = *(const float4*)(g_qattn + b * DIM + f);
    float4 o;
    if (n < KNN) {
        int aidx = g_idx[bq * KNN + n];
        float4 kv = *(const float4*)(g_KV + ((size_t)b * NA + aidx) * DIM + f);
        float4 pe = *(const float4*)(g_bufB + ((size_t)bq * KNN + n) * DIM + f);
        o.x = tf32f(qv.x - kv.x + pe.x);
        o.y = tf32f(qv.y - kv.y + pe.y);
        o.z = tf32f(qv.z - kv.z + pe.z);
        o.w = tf32f(qv.w - kv.w + pe.w);
    } else {
        float4 kg = *(const float4*)(g_kgv + b * DIM + f);
        o.x = tf32f(qv.x - kg.x);
        o.y = tf32f(qv.y - kg.y);
        o.z = tf32f(qv.z - kg.z);
        o.w = tf32f(qv.w - kg.w);
    }
    *(float4*)(g_bufC + r * 512 + f) = o;
}

// ---------------- per-feature softmax over 9 tokens + weighted sum ----------------
__global__ void k_attn_lat() {
    int bq = blockIdx.x;
    int f = threadIdx.x;
    int b = bq >> 12;
    __shared__ int sidx[KNN];
    if (threadIdx.x < KNN) sidx[threadIdx.x] = g_idx[bq * KNN + threadIdx.x];
    __syncthreads();
    float v[9];
#pragma unroll
    for (int n = 0; n < 9; n++)
        v[n] = g_bufC[((size_t)bq * 9 + n) * DIM + f];
    float m = v[0];
#pragma unroll
    for (int n = 1; n < 9; n++) m = fmaxf(m, v[n]);
    float s = 0.f;
#pragma unroll
    for (int n = 0; n < 9; n++) { v[n] = expf(v[n] - m); s += v[n]; }
    float inv = 1.f / s;
    float acc = 0.f;
#pragma unroll
    for (int n = 0; n < KNN; n++) {
        float val = g_KV[KVSZ + ((size_t)b * NA + sidx[n]) * DIM + f]
                  + g_bufB[((size_t)bq * KNN + n) * DIM + f];
        acc = fmaf(v[n], val, acc);
    }
    acc = fmaf(v[8], g_vgv[b * DIM + f], acc);
    g_lat[(size_t)bq * DIM + f] = tf32f(acc * inv);
}

// ---------------- NeRF positional encoding + fc_p ----------------
__global__ void k_pe_fcp(const float* __restrict__ xyz_q,
                         const float* __restrict__ fcpw,
                         const float* __restrict__ fcpb,
                         float* __restrict__ out) {
    __shared__ float pe[60];
    int bq = blockIdx.x;
    if (threadIdx.x < 60) {
        int i = threadIdx.x;
        int fr = i / 6, rem = i % 6, sc = rem / 3, c = rem % 3;
        float p = xyz_q[(size_t)bq * 3 + c];
        float a = p * ((float)(1 << fr) * 3.14159265358979f);
        pe[i] = (sc == 0) ? sinf(a) : cosf(a);
    }
    __syncthreads();
#pragma unroll
    for (int j = 0; j < 4; j++) {
        int n = j * 128 + threadIdx.x;
        float acc = fcpb[n];
#pragma unroll
        for (int i = 0; i < 60; i++)
            acc = fmaf(pe[i], fcpw[(size_t)i * 512 + n], acc);
        out[(size_t)bq * 512 + n] = acc;
    }
}

// ---------------- launch ----------------
extern "C" void kernel_launch(void* const* d_in, const int* in_sizes, int n_in,
                              void* d_out, int out_size) {
    const float* xyz_q        = (const float*)d_in[0];
    const float* global_feats = (const float*)d_in[1];
    const float* anchors_xyz  = (const float*)d_in[2];
    const float* anchors_feats= (const float*)d_in[3];
    const float* w_qs = (const float*)d_in[4];
    const float* w_ks = (const float*)d_in[5];
    const float* w_vs = (const float*)d_in[6];
    const float* w_kg = (const float*)d_in[7];
    const float* w_vg = (const float*)d_in[8];
    const float* d1_w = (const float*)d_in[9];
    const float* d1_b = (const float*)d_in[10];
    const float* d2_w = (const float*)d_in[11];
    const float* d2_b = (const float*)d_in[12];
    const float* g1_w = (const float*)d_in[13];
    const float* g1_b = (const float*)d_in[14];
    const float* g2_w = (const float*)d_in[15];
    const float* g2_b = (const float*)d_in[16];
    const float* fc_p_w = (const float*)d_in[17];
    const float* fc_p_b = (const float*)d_in[18];
    const float* fc_c_w = (const float*)d_in[19];
    const float* fc_c_b = (const float*)d_in[20];
    const float* blk0_w = (const float*)d_in[21];
    const float* blk0_b = (const float*)d_in[22];
    const float* blk1_w = (const float*)d_in[23];
    const float* blk1_b = (const float*)d_in[24];
    float* out = (float*)d_out;

    float *pKV, *pAF, *pA, *pB, *pC, *pLat, *pTmp, *pTmpR, *pH, *pWT;
    cudaGetSymbolAddress((void**)&pKV,   g_KV);
    cudaGetSymbolAddress((void**)&pAF,   g_af32);
    cudaGetSymbolAddress((void**)&pA,    g_bufA);
    cudaGetSymbolAddress((void**)&pB,    g_bufB);
    cudaGetSymbolAddress((void**)&pC,    g_bufC);
    cudaGetSymbolAddress((void**)&pLat,  g_lat);
    cudaGetSymbolAddress((void**)&pTmp,  g_tmp);
    cudaGetSymbolAddress((void**)&pTmpR, g_tmpR);
    cudaGetSymbolAddress((void**)&pH,    g_h);
    cudaGetSymbolAddress((void**)&pWT,   g_wt);

    cudaFuncSetAttribute(k_mma<false,false,0>, cudaFuncAttributeMaxDynamicSharedMemorySize, GEMM_SMEM);
    cudaFuncSetAttribute(k_mma<true, false,0>, cudaFuncAttributeMaxDynamicSharedMemorySize, GEMM_SMEM);
    cudaFuncSetAttribute(k_mma<true, false,2>, cudaFuncAttributeMaxDynamicSharedMemorySize, GEMM_SMEM);
    cudaFuncSetAttribute(k_mma<true, true, 1>, cudaFuncAttributeMaxDynamicSharedMemorySize, GEMM_SMEM);
    cudaFuncSetAttribute(k_mma<true, true, 0>, cudaFuncAttributeMaxDynamicSharedMemorySize, GEMM_SMEM);

    // prep
    k_transpose<<<dim3(16, 16, 20), dim3(32, 8)>>>(w_ks, w_vs, d2_w, g1_w, g2_w,
                                                   fc_c_w, blk0_w, blk1_w);
    k_round_af<<<KVSZ / 1024, 256>>>(anchors_feats);
    k_global_proj<<<(3 * B * DIM + 255) / 256, 256>>>(global_feats, w_qs, w_kg, w_vg);
    k_knn_part<<<dim3(NQ / 128, B, NCHUNK), 128>>>(xyz_q, anchors_xyz);
    k_knn_merge<<<BQ / 256, 256>>>();

    // KS + VS projections (one launch, z picks weight/output)
    k_mma<false,false,0><<<dim3(4, (B*NA)/128, 2), 128, GEMM_SMEM>>>(
        pAF, pWT + (size_t)T_KS*262144, nullptr, nullptr, pKV, nullptr, B*NA,
        262144, (size_t)KVSZ);

    // fc_delta
    k_h1<<<(unsigned)(((size_t)ROWS8 * 128) / 256), 256>>>(xyz_q, anchors_xyz, d1_w, d1_b);
    k_mma<true,false,0><<<dim3(4, ROWS8/128), 128, GEMM_SMEM>>>(
        pA, pWT + (size_t)T_D2*262144, d2_b, nullptr, pB, nullptr, ROWS8, 0, 0);

    // attention MLPs
    k_buildx<<<(unsigned)(((size_t)ROWS9 * 128) / 256), 256>>>();
    k_mma<true,false,2><<<dim3(4, ROWS9/128), 128, GEMM_SMEM>>>(
        pC, pWT + (size_t)T_G1*262144, g1_b, nullptr, pA, nullptr, ROWS9, 0, 0);
    k_mma<true,false,0><<<dim3(4, ROWS9/128), 128, GEMM_SMEM>>>(
        pA, pWT + (size_t)T_G2*262144, g2_b, nullptr, pC, nullptr, ROWS9, 0, 0);

    // softmax + weighted sum
    k_attn_lat<<<BQ, 512>>>();

    // decoder
    k_pe_fcp<<<BQ, 128>>>(xyz_q, fc_p_w, fc_p_b, out);

    for (int i = 0; i < NBLK; i++) {
        const float* cb  = fc_c_b + (size_t)i * HID;
        const float* b0b = blk0_b + (size_t)i * HID;
        const float* b1b = blk1_b + (size_t)i * HID;
        float* cwT  = pWT + (size_t)(T_FCC + i) * 262144;
        float* b0wT = pWT + (size_t)(T_B0  + i) * 262144;
        float* b1wT = pWT + (size_t)(T_B1  + i) * 262144;
        k_mma<true,true,1><<<dim3(4, BQ/128), 128, GEMM_SMEM>>>(
            pLat, cwT, cb, out, pTmp, pTmpR, BQ, 0, 0);
        k_mma<true,false,2><<<dim3(4, BQ/128), 128, GEMM_SMEM>>>(
            pTmpR, b0wT, b0b, nullptr, pH, nullptr, BQ, 0, 0);
        k_mma<true,true,0><<<dim3(4, BQ/128), 128, GEMM_SMEM>>>(
            pH, b1wT, b1b, pTmp, out, nullptr, BQ, 0, 0);
    }
}

// round 17
// speedup vs baseline: 5.1911x; 1.5038x over previous
#include <cuda_runtime.h>
#include <cuda_fp16.h>
#include <cstdint>
#include <math.h>

#define B 2
#define NQ 4096
#define NA 2048
#define DIM 512
#define HID 512
#define NBLK 5
#define KNN 8
#define NCHUNK 16
#define CHUNK (NA/NCHUNK)   // 128

#define BQ    (B*NQ)        // 8192
#define ROWS8 (BQ*KNN)      // 65536
#define ROWS9 (BQ*9)        // 73728
#define KVSZ  (B*NA*DIM)

// ---------------- static scratch (no allocations allowed) ----------------
__device__ float  g_KV[2*KVSZ];                 // [0]=KS, [1]=VS (fp32)
__device__ int    g_idx[BQ*KNN];
__device__ float  g_knn_d[BQ*NCHUNK*KNN];
__device__ int    g_knn_i[BQ*NCHUNK*KNN];
__device__ __half g_af16[KVSZ];                 // anchors_feats fp16
__device__ __half g_h1h[(size_t)ROWS8*DIM];     // H1 fp16
__device__ float  g_pe[(size_t)ROWS8*DIM];      // PE fp32
__device__ __half g_xh[(size_t)ROWS9*DIM];      // X fp16
__device__ __half g_th[(size_t)ROWS9*DIM];      // relu(T_pre) fp16
__device__ float  g_G[(size_t)ROWS9*DIM];       // attn logits fp32
__device__ __half g_lath[BQ*DIM];               // lat fp16
__device__ float  g_tmp[BQ*HID];                // residual fp32
__device__ __half g_tmpRh[BQ*HID];              // relu(tmp) fp16
__device__ __half g_hh[BQ*HID];                 // relu(h) fp16
__device__ float  g_qattn[B*DIM];
__device__ float  g_kgv[B*DIM];
__device__ float  g_vgv[B*DIM];
__device__ __half g_wt[(size_t)20*512*512];     // 20 transposed weights [N,K] fp16

#define T_KS  0
#define T_VS  1
#define T_D2  2
#define T_G1  3
#define T_G2  4
#define T_FCC 5
#define T_B0  10
#define T_B1  15

// ---------------- helpers ----------------
__device__ __forceinline__ void cp16(void* smem_dst, const void* gsrc) {
    uint32_t s = (uint32_t)__cvta_generic_to_shared(smem_dst);
    asm volatile("cp.async.ca.shared.global [%0], [%1], 16;" :: "r"(s), "l"(gsrc) : "memory");
}
#define CP_COMMIT() asm volatile("cp.async.commit_group;" ::: "memory")
#define CP_WAIT1()  asm volatile("cp.async.wait_group 1;" ::: "memory")
#define CP_WAIT0()  asm volatile("cp.async.wait_group 0;" ::: "memory")

__device__ __forceinline__ void ldsm_x4(uint32_t& r0, uint32_t& r1, uint32_t& r2,
                                        uint32_t& r3, uint32_t addr) {
    asm volatile("ldmatrix.sync.aligned.m8n8.x4.shared.b16 {%0,%1,%2,%3}, [%4];"
                 : "=r"(r0), "=r"(r1), "=r"(r2), "=r"(r3) : "r"(addr));
}

__device__ __forceinline__ void mma_f16(float* d, const uint32_t* a, const uint32_t* b) {
    asm volatile(
        "mma.sync.aligned.m16n8k16.row.col.f32.f16.f16.f32 "
        "{%0,%1,%2,%3}, {%4,%5,%6,%7}, {%8,%9}, {%0,%1,%2,%3};"
        : "+f"(d[0]), "+f"(d[1]), "+f"(d[2]), "+f"(d[3])
        : "r"(a[0]), "r"(a[1]), "r"(a[2]), "r"(a[3]),
          "r"(b[0]), "r"(b[1]));
}

// ---------------- weight transpose: [K,N] -> [N,K], fp16 ----------------
__global__ void k_transpose(const float* __restrict__ wks, const float* __restrict__ wvs,
                            const float* __restrict__ d2w, const float* __restrict__ g1w,
                            const float* __restrict__ g2w, const float* __restrict__ fcc,
                            const float* __restrict__ b0w, const float* __restrict__ b1w) {
    __shared__ float t[32][33];
    int z = blockIdx.z;
    const float* src;
    if      (z == 0) src = wks;
    else if (z == 1) src = wvs;
    else if (z == 2) src = d2w;
    else if (z == 3) src = g1w;
    else if (z == 4) src = g2w;
    else if (z < 10) src = fcc + (size_t)(z - 5)  * 262144;
    else if (z < 15) src = b0w + (size_t)(z - 10) * 262144;
    else             src = b1w + (size_t)(z - 15) * 262144;
    __half* dst = g_wt + (size_t)z * 262144;
    int x  = blockIdx.x * 32 + threadIdx.x;
    int y0 = blockIdx.y * 32;
#pragma unroll
    for (int i = threadIdx.y; i < 32; i += 8)
        t[i][threadIdx.x] = src[(size_t)(y0 + i) * 512 + x];
    __syncthreads();
    int xo  = blockIdx.y * 32 + threadIdx.x;
    int yo0 = blockIdx.x * 32;
#pragma unroll
    for (int i = threadIdx.y; i < 32; i += 8)
        dst[(size_t)(yo0 + i) * 512 + xo] = __float2half_rn(t[threadIdx.x][i]);
}

// ---------------- anchors_feats -> fp16 ----------------
__global__ void k_half_af(const float* __restrict__ af) {
    int o = blockIdx.x * 256 + threadIdx.x;
    float4 v = *(const float4*)(af + o * 4);
    half2* dst = (half2*)(g_af16 + o * 4);
    dst[0] = __floats2half2_rn(v.x, v.y);
    dst[1] = __floats2half2_rn(v.z, v.w);
}

// ---------------- fp16 mma.sync GEMM, cp.async double-buffered, BK=64 ----------------
// 128x128 CTA tile, 4 warps (2m x 2n), warp tile 64x64 = 4x8 m16n8k16.
// OUTMODE: 0 = Cf exact fp32; 1 = Cf exact + Ch = half(relu); 2 = Ch = half(relu) only.
#define SROWH 72
#define STAGE_H (128 * SROWH)            // halves per matrix per stage
#define TILE16B (16 * SROWH * 2)
#define GEMM_SMEM (4 * STAGE_H * 2)      // 73728 bytes

template<bool HAS_BIAS, bool HAS_RES, int OUTMODE>
__global__ __launch_bounds__(128, 2)
void k_mma(const __half* __restrict__ A, const __half* __restrict__ Wt,
           const float* __restrict__ bias, const float* __restrict__ R,
           float* __restrict__ Cf, __half* __restrict__ Ch, int M,
           size_t zsW, size_t zsC) {
    extern __shared__ __half smh[];
    __half* Asm = smh;
    __half* Bsm = smh + 2 * STAGE_H;
    Wt += (size_t)blockIdx.z * zsW;
    Cf += (size_t)blockIdx.z * zsC;
    const int tid  = threadIdx.x;
    const int lane = tid & 31;
    const int warp = tid >> 5;
    const int wm   = warp >> 1;      // 0..1
    const int wn   = warp & 1;       // 0..1
    const int gid  = lane >> 2;      // 0..7
    const int tig  = lane & 3;       // 0..3
    const int bn = blockIdx.x * 128;
    const int bm = blockIdx.y * 128;

    // cp.async: 128 rows x 8 chunks of 16B (64 halves/row); 128 thr -> 16 rows/pass
    const int crow = tid >> 3;       // 0..15
    const int cchk = (tid & 7) * 8;  // half offset 0..56

    // ldmatrix lane addressing (8x8 b16 tiles)
    const int lrow = lane & 7;
    const int lt   = lane >> 3;      // 0..3
    const uint32_t smem_u32 = (uint32_t)__cvta_generic_to_shared(smh);
    // A tiles: (m0-7,k0-7)(m8-15,k0-7)(m0-7,k8-15)(m8-15,k8-15)
    const uint32_t aBase0 = smem_u32 +
        (uint32_t)(((wm * 64 + ((lt & 1) << 3) + lrow) * SROWH + ((lt >> 1) << 3)) * 2);
    // B tiles: (n0-7,k0-7)(n0-7,k8-15)(n8-15,k0-7)(n8-15,k8-15)
    const uint32_t bBase0 = smem_u32 + 2 * STAGE_H * 2 +
        (uint32_t)(((wn * 64 + ((lt >> 1) << 3) + lrow) * SROWH + ((lt & 1) << 3)) * 2);

    float acc[4][8][4];
#pragma unroll
    for (int i = 0; i < 4; i++)
#pragma unroll
        for (int j = 0; j < 8; j++)
#pragma unroll
            for (int l = 0; l < 4; l++) acc[i][j][l] = 0.f;

#pragma unroll
    for (int p = 0; p < 8; p++) {
        const int row = crow + p * 16;
        cp16(Asm + row * SROWH + cchk, A  + (size_t)(bm + row) * 512 + cchk);
        cp16(Bsm + row * SROWH + cchk, Wt + (size_t)(bn + row) * 512 + cchk);
    }
    CP_COMMIT();

#pragma unroll 1
    for (int it = 0; it < 8; ++it) {
        const int st = it & 1;
        if (it + 1 < 8) {
            const int k0  = (it + 1) * 64;
            const int st2 = (it + 1) & 1;
#pragma unroll
            for (int p = 0; p < 8; p++) {
                const int row = crow + p * 16;
                cp16(Asm + st2 * STAGE_H + row * SROWH + cchk,
                     A  + (size_t)(bm + row) * 512 + k0 + cchk);
                cp16(Bsm + st2 * STAGE_H + row * SROWH + cchk,
                     Wt + (size_t)(bn + row) * 512 + k0 + cchk);
            }
            CP_COMMIT();
            CP_WAIT1();
        } else {
            CP_WAIT0();
        }
        __syncthreads();

        const uint32_t aB = aBase0 + st * (STAGE_H * 2);
        const uint32_t bB = bBase0 + st * (STAGE_H * 2);
#pragma unroll
        for (int k16 = 0; k16 < 64; k16 += 16) {
            uint32_t af[4][4], bf[8][2];
#pragma unroll
            for (int mi = 0; mi < 4; mi++)
                ldsm_x4(af[mi][0], af[mi][1], af[mi][2], af[mi][3],
                        aB + k16 * 2 + mi * TILE16B);
#pragma unroll
            for (int p = 0; p < 4; p++)
                ldsm_x4(bf[2 * p][0], bf[2 * p][1], bf[2 * p + 1][0], bf[2 * p + 1][1],
                        bB + k16 * 2 + p * TILE16B);
#pragma unroll
            for (int mi = 0; mi < 4; mi++)
#pragma unroll
                for (int ni = 0; ni < 8; ni++)
                    mma_f16(acc[mi][ni], af[mi], bf[ni]);
        }
        __syncthreads();
    }

    // epilogue (c fragment layout same as k8 variant)
#pragma unroll
    for (int mi = 0; mi < 4; mi++) {
#pragma unroll
        for (int h = 0; h < 2; h++) {
            const int row = bm + wm * 64 + mi * 16 + gid + h * 8;
            const float* Rrow = R + (size_t)row * 512;
#pragma unroll
            for (int ni = 0; ni < 8; ni++) {
                const int col = bn + wn * 64 + ni * 8 + tig * 2;
                float2 v;
                v.x = acc[mi][ni][h * 2 + 0];
                v.y = acc[mi][ni][h * 2 + 1];
                if (HAS_BIAS) { v.x += bias[col]; v.y += bias[col + 1]; }
                if (HAS_RES) {
                    float2 rr = *(const float2*)(Rrow + col);
                    v.x += rr.x; v.y += rr.y;
                }
                if (OUTMODE != 2)
                    *(float2*)(Cf + (size_t)row * 512 + col) = v;
                if (OUTMODE != 0)
                    *(half2*)(Ch + (size_t)row * 512 + col) =
                        __floats2half2_rn(fmaxf(v.x, 0.f), fmaxf(v.y, 0.f));
            }
        }
    }
}

// ---------------- tiny projection of global feats ----------------
__global__ void k_global_proj(const float* __restrict__ gf,
                              const float* __restrict__ wqs,
                              const float* __restrict__ wkg,
                              const float* __restrict__ wvg) {
    int t = blockIdx.x * blockDim.x + threadIdx.x;
    if (t >= 3 * B * DIM) return;
    int which = t / (B * DIM);
    int r = t % (B * DIM);
    int b = r / DIM, n = r % DIM;
    const float* W = (which == 0) ? wqs : (which == 1) ? wkg : wvg;
    float acc = 0.f;
    for (int k = 0; k < DIM; k++)
        acc = fmaf(gf[b * DIM + k], W[(size_t)k * DIM + n], acc);
    float* out = (which == 0) ? g_qattn : (which == 1) ? g_kgv : g_vgv;
    out[b * DIM + n] = acc;
}

// ---------------- KNN phase 1: per-chunk top-8 ----------------
__global__ void k_knn_part(const float* __restrict__ xyz_q,
                           const float* __restrict__ axyz) {
    __shared__ float sx[CHUNK], sy[CHUNK], sz[CHUNK], s2[CHUNK];
    int b = blockIdx.y, z = blockIdx.z;
    int q = blockIdx.x * 128 + threadIdx.x;
    int bq = b * NQ + q;
    float qx = xyz_q[bq * 3 + 0];
    float qy = xyz_q[bq * 3 + 1];
    float qz = xyz_q[bq * 3 + 2];
    float q2 = qx * qx + qy * qy + qz * qz;
    if (threadIdx.x < CHUNK) {
        int j = threadIdx.x;
        const float* ap = axyz + ((size_t)(b * NA + z * CHUNK + j)) * 3;
        float ax = ap[0], ay = ap[1], az = ap[2];
        sx[j] = ax; sy[j] = ay; sz[j] = az;
        s2[j] = ax * ax + ay * ay + az * az;
    }
    __syncthreads();
    float bd[KNN]; int bi[KNN];
#pragma unroll
    for (int i = 0; i < KNN; i++) { bd[i] = INFINITY; bi[i] = 0; }
    for (int j = 0; j < CHUNK; j++) {
        float d2 = q2 + s2[j] - 2.f * (qx * sx[j] + qy * sy[j] + qz * sz[j]);
        if (d2 < bd[KNN - 1]) {
            bd[KNN - 1] = d2; bi[KNN - 1] = z * CHUNK + j;
#pragma unroll
            for (int s = KNN - 1; s > 0; --s) {
                if (bd[s] < bd[s - 1]) {
                    float td = bd[s]; bd[s] = bd[s - 1]; bd[s - 1] = td;
                    int ti = bi[s]; bi[s] = bi[s - 1]; bi[s - 1] = ti;
                }
            }
        }
    }
    size_t base = ((size_t)bq * NCHUNK + z) * KNN;
#pragma unroll
    for (int i = 0; i < KNN; i++) { g_knn_d[base + i] = bd[i]; g_knn_i[base + i] = bi[i]; }
}

// ---------------- KNN phase 2: merge sorted chunk-lists (ascending z => stable) ----
__global__ void k_knn_merge() {
    int bq = blockIdx.x * 256 + threadIdx.x;
    float bd[KNN]; int bi[KNN];
#pragma unroll
    for (int i = 0; i < KNN; i++) { bd[i] = INFINITY; bi[i] = 0; }
    for (int z = 0; z < NCHUNK; z++) {
        size_t base = ((size_t)bq * NCHUNK + z) * KNN;
#pragma unroll
        for (int c = 0; c < KNN; c++) {
            float d = g_knn_d[base + c];
            if (!(d < bd[KNN - 1])) break;
            int idx = g_knn_i[base + c];
            bd[KNN - 1] = d; bi[KNN - 1] = idx;
#pragma unroll
            for (int s = KNN - 1; s > 0; --s) {
                if (bd[s] < bd[s - 1]) {
                    float td = bd[s]; bd[s] = bd[s - 1]; bd[s - 1] = td;
                    int ti = bi[s]; bi[s] = bi[s - 1]; bi[s - 1] = ti;
                }
            }
        }
    }
#pragma unroll
    for (int i = 0; i < KNN; i++) g_idx[bq * KNN + i] = bi[i];
}

// ---------------- H1 = fp16(relu(d @ d1_w + d1_b)) ----------------
__global__ void k_h1(const float* __restrict__ xyz_q,
                     const float* __restrict__ axyz,
                     const float* __restrict__ d1w,
                     const float* __restrict__ d1b) {
    size_t t = (size_t)blockIdx.x * 256 + threadIdx.x;
    int f = (int)(t & 127) * 4;
    size_t r = t >> 7;
    int kk = (int)(r & 7);
    int bq = (int)(r >> 3);
    int b = bq >> 12;
    int aidx = g_idx[bq * KNN + kk];
    const float* qp = xyz_q + (size_t)bq * 3;
    const float* ap = axyz + ((size_t)b * NA + aidx) * 3;
    float dx = qp[0] - ap[0], dy = qp[1] - ap[1], dz = qp[2] - ap[2];
    float4 w0 = *(const float4*)(d1w + f);
    float4 w1 = *(const float4*)(d1w + 512 + f);
    float4 w2 = *(const float4*)(d1w + 1024 + f);
    float4 bb = *(const float4*)(d1b + f);
    float ox = fmaxf(fmaf(dx, w0.x, fmaf(dy, w1.x, fmaf(dz, w2.x, bb.x))), 0.f);
    float oy = fmaxf(fmaf(dx, w0.y, fmaf(dy, w1.y, fmaf(dz, w2.y, bb.y))), 0.f);
    float oz = fmaxf(fmaf(dx, w0.z, fmaf(dy, w1.z, fmaf(dz, w2.z, bb.z))), 0.f);
    float ow = fmaxf(fmaf(dx, w0.w, fmaf(dy, w1.w, fmaf(dz, w2.w, bb.w))), 0.f);
    half2* dst = (half2*)(g_h1h + r * 512 + f);
    dst[0] = __floats2half2_rn(ox, oy);
    dst[1] = __floats2half2_rn(oz, ow);
}

// ---------------- build attention input X = fp16(q - k + pos) ----------------
__global__ void k_buildx() {
    size_t t = (size_t)blockIdx.x * 256 + threadIdx.x;
    int f = (int)(t & 127) * 4;
    size_t r = t >> 7;
    int n = (int)(r % 9);
    int bq = (int)(r / 9);
    int b = bq >> 12;
    float4 qv = *(const float4*)(g_qattn + b * DIM + f);
    float ox, oy, oz, ow;
    if (n < KNN) {
        int aidx = g_idx[bq * KNN + n];
        float4 kv = *(const float4*)(g_KV + ((size_t)b * NA + aidx) * DIM + f);
        float4 pe = *(const float4*)(g_pe + ((size_t)bq * KNN + n) * DIM + f);
        ox = qv.x - kv.x + pe.x;
        oy = qv.y - kv.y + pe.y;
        oz = qv.z - kv.z + pe.z;
        ow = qv.w - kv.w + pe.w;
    } else {
        float4 kg = *(const float4*)(g_kgv + b * DIM + f);
        ox = qv.x - kg.x; oy = qv.y - kg.y; oz = qv.z - kg.z; ow = qv.w - kg.w;
    }
    half2* dst = (half2*)(g_xh + r * 512 + f);
    dst[0] = __floats2half2_rn(ox, oy);
    dst[1] = __floats2half2_rn(oz, ow);
}

// ---------------- per-feature softmax over 9 tokens + weighted sum ----------------
__global__ void k_attn_lat() {
    int bq = blockIdx.x;
    int f = threadIdx.x;
    int b = bq >> 12;
    __shared__ int sidx[KNN];
    if (threadIdx.x < KNN) sidx[threadIdx.x] = g_idx[bq * KNN + threadIdx.x];
    __syncthreads();
    float v[9];
#pragma unroll
    for (int n = 0; n < 9; n++)
        v[n] = g_G[((size_t)bq * 9 + n) * DIM + f];
    float m = v[0];
#pragma unroll
    for (int n = 1; n < 9; n++) m = fmaxf(m, v[n]);
    float s = 0.f;
#pragma unroll
    for (int n = 0; n < 9; n++) { v[n] = expf(v[n] - m); s += v[n]; }
    float inv = 1.f / s;
    float acc = 0.f;
#pragma unroll
    for (int n = 0; n < KNN; n++) {
        float val = g_KV[KVSZ + ((size_t)b * NA + sidx[n]) * DIM + f]
                  + g_pe[((size_t)bq * KNN + n) * DIM + f];
        acc = fmaf(v[n], val, acc);
    }
    acc = fmaf(v[8], g_vgv[b * DIM + f], acc);
    g_lath[(size_t)bq * DIM + f] = __float2half_rn(acc * inv);
}

// ---------------- NeRF positional encoding + fc_p ----------------
__global__ void k_pe_fcp(const float* __restrict__ xyz_q,
                         const float* __restrict__ fcpw,
                         const float* __restrict__ fcpb,
                         float* __restrict__ out) {
    __shared__ float pe[60];
    int bq = blockIdx.x;
    if (threadIdx.x < 60) {
        int i = threadIdx.x;
        int fr = i / 6, rem = i % 6, sc = rem / 3, c = rem % 3;
        float p = xyz_q[(size_t)bq * 3 + c];
        float a = p * ((float)(1 << fr) * 3.14159265358979f);
        pe[i] = (sc == 0) ? sinf(a) : cosf(a);
    }
    __syncthreads();
#pragma unroll
    for (int j = 0; j < 4; j++) {
        int n = j * 128 + threadIdx.x;
        float acc = fcpb[n];
#pragma unroll
        for (int i = 0; i < 60; i++)
            acc = fmaf(pe[i], fcpw[(size_t)i * 512 + n], acc);
        out[(size_t)bq * 512 + n] = acc;
    }
}

// ---------------- launch ----------------
extern "C" void kernel_launch(void* const* d_in, const int* in_sizes, int n_in,
                              void* d_out, int out_size) {
    const float* xyz_q        = (const float*)d_in[0];
    const float* global_feats = (const float*)d_in[1];
    const float* anchors_xyz  = (const float*)d_in[2];
    const float* anchors_feats= (const float*)d_in[3];
    const float* w_qs = (const float*)d_in[4];
    const float* w_ks = (const float*)d_in[5];
    const float* w_vs = (const float*)d_in[6];
    const float* w_kg = (const float*)d_in[7];
    const float* w_vg = (const float*)d_in[8];
    const float* d1_w = (const float*)d_in[9];
    const float* d1_b = (const float*)d_in[10];
    const float* d2_w = (const float*)d_in[11];
    const float* d2_b = (const float*)d_in[12];
    const float* g1_w = (const float*)d_in[13];
    const float* g1_b = (const float*)d_in[14];
    const float* g2_w = (const float*)d_in[15];
    const float* g2_b = (const float*)d_in[16];
    const float* fc_p_w = (const float*)d_in[17];
    const float* fc_p_b = (const float*)d_in[18];
    const float* fc_c_w = (const float*)d_in[19];
    const float* fc_c_b = (const float*)d_in[20];
    const float* blk0_w = (const float*)d_in[21];
    const float* blk0_b = (const float*)d_in[22];
    const float* blk1_w = (const float*)d_in[23];
    const float* blk1_b = (const float*)d_in[24];
    float* out = (float*)d_out;

    float *pKV, *pPE, *pG, *pTmp;
    __half *pAF, *pH1, *pX, *pT, *pLat, *pTmpR, *pHh, *pWT;
    cudaGetSymbolAddress((void**)&pKV,   g_KV);
    cudaGetSymbolAddress((void**)&pPE,   g_pe);
    cudaGetSymbolAddress((void**)&pG,    g_G);
    cudaGetSymbolAddress((void**)&pTmp,  g_tmp);
    cudaGetSymbolAddress((void**)&pAF,   g_af16);
    cudaGetSymbolAddress((void**)&pH1,   g_h1h);
    cudaGetSymbolAddress((void**)&pX,    g_xh);
    cudaGetSymbolAddress((void**)&pT,    g_th);
    cudaGetSymbolAddress((void**)&pLat,  g_lath);
    cudaGetSymbolAddress((void**)&pTmpR, g_tmpRh);
    cudaGetSymbolAddress((void**)&pHh,   g_hh);
    cudaGetSymbolAddress((void**)&pWT,   g_wt);

    cudaFuncSetAttribute(k_mma<false,false,0>, cudaFuncAttributeMaxDynamicSharedMemorySize, GEMM_SMEM);
    cudaFuncSetAttribute(k_mma<true, false,0>, cudaFuncAttributeMaxDynamicSharedMemorySize, GEMM_SMEM);
    cudaFuncSetAttribute(k_mma<true, false,2>, cudaFuncAttributeMaxDynamicSharedMemorySize, GEMM_SMEM);
    cudaFuncSetAttribute(k_mma<true, true, 1>, cudaFuncAttributeMaxDynamicSharedMemorySize, GEMM_SMEM);
    cudaFuncSetAttribute(k_mma<true, true, 0>, cudaFuncAttributeMaxDynamicSharedMemorySize, GEMM_SMEM);

    // prep
    k_transpose<<<dim3(16, 16, 20), dim3(32, 8)>>>(w_ks, w_vs, d2_w, g1_w, g2_w,
                                                   fc_c_w, blk0_w, blk1_w);
    k_half_af<<<KVSZ / 1024, 256>>>(anchors_feats);
    k_global_proj<<<(3 * B * DIM + 255) / 256, 256>>>(global_feats, w_qs, w_kg, w_vg);
    k_knn_part<<<dim3(NQ / 128, B, NCHUNK), 128>>>(xyz_q, anchors_xyz);
    k_knn_merge<<<BQ / 256, 256>>>();

    // KS + VS projections (one launch, z picks weight/output) -> fp32 KV
    k_mma<false,false,0><<<dim3(4, (B*NA)/128, 2), 128, GEMM_SMEM>>>(
        pAF, pWT + (size_t)T_KS*262144, nullptr, nullptr, pKV, nullptr, B*NA,
        262144, (size_t)KVSZ);

    // fc_delta: PE = H1 @ d2 + b (fp32)
    k_h1<<<(unsigned)(((size_t)ROWS8 * 128) / 256), 256>>>(xyz_q, anchors_xyz, d1_w, d1_b);
    k_mma<true,false,0><<<dim3(4, ROWS8/128), 128, GEMM_SMEM>>>(
        pH1, pWT + (size_t)T_D2*262144, d2_b, nullptr, pPE, nullptr, ROWS8, 0, 0);

    // attention MLPs: g1 -> half(relu(T_pre)); g2 -> G fp32
    k_buildx<<<(unsigned)(((size_t)ROWS9 * 128) / 256), 256>>>();
    k_mma<true,false,2><<<dim3(4, ROWS9/128), 128, GEMM_SMEM>>>(
        pX, pWT + (size_t)T_G1*262144, g1_b, nullptr, nullptr, pT, ROWS9, 0, 0);
    k_mma<true,false,0><<<dim3(4, ROWS9/128), 128, GEMM_SMEM>>>(
        pT, pWT + (size_t)T_G2*262144, g2_b, nullptr, pG, nullptr, ROWS9, 0, 0);

    // softmax + weighted sum -> lat (fp16)
    k_attn_lat<<<BQ, 512>>>();

    // decoder
    k_pe_fcp<<<BQ, 128>>>(xyz_q, fc_p_w, fc_p_b, out);

    for (int i = 0; i < NBLK; i++) {
        const float* cb  = fc_c_b + (size_t)i * HID;
        const float* b0b = blk0_b + (size_t)i * HID;
        const float* b1b = blk1_b + (size_t)i * HID;
        __half* cwT  = pWT + (size_t)(T_FCC + i) * 262144;
        __half* b0wT = pWT + (size_t)(T_B0  + i) * 262144;
        __half* b1wT = pWT + (size_t)(T_B1  + i) * 262144;
        // tmp = net + lat @ fc_c + b (fp32) ; tmpR = half(relu(tmp))
        k_mma<true,true,1><<<dim3(4, BQ/128), 128, GEMM_SMEM>>>(
            pLat, cwT, cb, out, pTmp, pTmpR, BQ, 0, 0);
        // h = half(relu(relu(tmp) @ blk0 + b))
        k_mma<true,false,2><<<dim3(4, BQ/128), 128, GEMM_SMEM>>>(
            pTmpR, b0wT, b0b, nullptr, nullptr, pHh, BQ, 0, 0);
        // net = tmp + relu(h) @ blk1 + b (fp32)
        k_mma<true,true,0><<<dim3(4, BQ/128), 128, GEMM_SMEM>>>(
            pHh, b1wT, b1b, pTmp, out, nullptr, BQ, 0, 0);
    }
}